// round 1
// baseline (speedup 1.0000x reference)
#include <cuda_runtime.h>
#include <cuda_bf16.h>
#include <math.h>

// ---------------- problem constants ----------------
#define BATCH 2
#define CH    32
#define DD    96
#define VOL   (96*96*96)          // 884736
#define NRR   100
#define H1N   64
#define RHN   256
#define REN   128
#define INV_V (1.0f/884736.0f)
#define EPSN  1e-5f

// ---------------- scratch (static device globals; no allocation) ----------------
__device__ float g_buf0[BATCH*CH*VOL];
__device__ float g_buf1[BATCH*CH*VOL];
__device__ float g_ssum[4][BATCH*CH][2];   // per layer: sum, sumsq of raw conv output per (b,c)
__device__ float g_roi [BATCH*NRR*CH];     // pooled accumulators
__device__ float g_msum[NRR];              // mask row sums

// ---------------- init: zero all accumulators (runs every graph replay) ----------------
__global__ void init_kernel() {
    int t = threadIdx.x;
    float* ss = &g_ssum[0][0][0];
    for (int i = t; i < 4*BATCH*CH*2; i += 256) ss[i] = 0.f;
    for (int i = t; i < BATCH*NRR*CH; i += 256) g_roi[i] = 0.f;
    for (int i = t; i < NRR; i += 256) g_msum[i] = 0.f;
}

// ---------------- direct 3x3x3 conv, 32 output channels per thread ----------------
// Input is normalized+relu'd on the fly using stats of the *input* buffer (NORM_IN).
// Output is RAW conv (no bias: biases cancel under instance norm).
template<int CIN, bool NORM_IN>
__global__ void __launch_bounds__(256, 2)
conv3d_kernel(const float* __restrict__ in,
              const float* __restrict__ w,     // [32][CIN][27]
              const float* __restrict__ ss,    // [B*CIN][2] stats of input (ignored if !NORM_IN)
              float* __restrict__ out)
{
    constexpr int GC = (CIN < 8) ? CIN : 8;    // cin group staged in smem
    __shared__ float w_s[GC*27*32];            // [cil][tap][co], co contiguous

    const int tid = threadIdx.x;
    const int tx = tid & 31;
    const int ty = (tid >> 5) & 3;
    const int tz = tid >> 7;
    const int x0 = blockIdx.x * 32 + tx;
    const int y0 = blockIdx.y * 4 + ty;
    const int b  = blockIdx.z / 48;
    const int z0 = (blockIdx.z % 48) * 2 + tz;

    float acc[32];
    #pragma unroll
    for (int q = 0; q < 32; q++) acc[q] = 0.f;

    for (int cg = 0; cg < CIN; cg += GC) {
        __syncthreads();
        for (int i = tid; i < GC*27*32; i += 256) {
            int co  = i & 31;
            int rem = i >> 5;
            int tap = rem % 27;
            int cil = rem / 27;
            w_s[i] = w[(co*CIN + cg + cil)*27 + tap];
        }
        __syncthreads();

        #pragma unroll 1
        for (int cil = 0; cil < GC; cil++) {
            const int ci = cg + cil;
            const float* p = in + (size_t)(b*CIN + ci) * VOL;
            float na = 1.f, nb = 0.f;
            if (NORM_IN) {
                float s = ss[(b*CIN + ci)*2 + 0];
                float q = ss[(b*CIN + ci)*2 + 1];
                float m = s * INV_V;
                float var = fmaxf(q * INV_V - m*m, 0.f);
                float rstd = rsqrtf(var + EPSN);
                na = rstd; nb = -m * rstd;
            }
            // gather 3x3x3 neighborhood (zero-padded SAME)
            float xv[27];
            #pragma unroll
            for (int dz = 0; dz < 3; dz++) {
                int z = z0 + dz - 1;
                bool okz = ((unsigned)z < 96u);
                #pragma unroll
                for (int dy = 0; dy < 3; dy++) {
                    int y = y0 + dy - 1;
                    bool oky = okz && ((unsigned)y < 96u);
                    #pragma unroll
                    for (int dx = 0; dx < 3; dx++) {
                        int x = x0 + dx - 1;
                        float v = 0.f;
                        if (oky && ((unsigned)x < 96u)) {
                            v = __ldg(p + ((size_t)z*96 + y)*96 + x);
                            if (NORM_IN) v = fmaxf(fmaf(v, na, nb), 0.f);
                        }
                        xv[(dz*3 + dy)*3 + dx] = v;
                    }
                }
            }
            // accumulate into 32 output channels; weight reads are warp-broadcast LDS.128
            #pragma unroll
            for (int tap = 0; tap < 27; tap++) {
                float v = xv[tap];
                const float4* wp = reinterpret_cast<const float4*>(w_s + ((cil*27 + tap) << 5));
                #pragma unroll
                for (int q = 0; q < 8; q++) {
                    float4 ww = wp[q];
                    acc[q*4+0] = fmaf(v, ww.x, acc[q*4+0]);
                    acc[q*4+1] = fmaf(v, ww.y, acc[q*4+1]);
                    acc[q*4+2] = fmaf(v, ww.z, acc[q*4+2]);
                    acc[q*4+3] = fmaf(v, ww.w, acc[q*4+3]);
                }
            }
        }
    }

    const size_t sp = ((size_t)z0*96 + y0)*96 + x0;
    #pragma unroll
    for (int co = 0; co < 32; co++)
        out[(size_t)(b*CH + co)*VOL + sp] = acc[co];
}

// ---------------- per-(b,c) sum / sumsq of a raw buffer ----------------
__global__ void stats_kernel(const float* __restrict__ buf, float* __restrict__ ssum)
{
    const int bc = blockIdx.y;
    const float* p = buf + (size_t)bc * VOL + (size_t)blockIdx.x * 16384;
    float s = 0.f, q = 0.f;
    for (int i = threadIdx.x; i < 16384; i += 256) {
        float v = p[i];
        s += v;
        q = fmaf(v, v, q);
    }
    #pragma unroll
    for (int o = 16; o; o >>= 1) {
        s += __shfl_xor_sync(0xffffffffu, s, o);
        q += __shfl_xor_sync(0xffffffffu, q, o);
    }
    __shared__ float sh[2][8];
    int wrp = threadIdx.x >> 5, ln = threadIdx.x & 31;
    if (ln == 0) { sh[0][wrp] = s; sh[1][wrp] = q; }
    __syncthreads();
    if (threadIdx.x == 0) {
        float ts = 0.f, tq = 0.f;
        #pragma unroll
        for (int i = 0; i < 8; i++) { ts += sh[0][i]; tq += sh[1][i]; }
        atomicAdd(&ssum[bc*2 + 0], ts);
        atomicAdd(&ssum[bc*2 + 1], tq);
    }
}

// ---------------- mask row sums ----------------
__global__ void masksum_kernel(const float* __restrict__ mask)
{
    const int r = blockIdx.y;
    const float* p = mask + (size_t)r * VOL + (size_t)blockIdx.x * 32768;
    float s = 0.f;
    for (int i = threadIdx.x; i < 32768; i += 256) s += p[i];
    #pragma unroll
    for (int o = 16; o; o >>= 1) s += __shfl_xor_sync(0xffffffffu, s, o);
    __shared__ float sh[8];
    int wrp = threadIdx.x >> 5, ln = threadIdx.x & 31;
    if (ln == 0) sh[wrp] = s;
    __syncthreads();
    if (threadIdx.x == 0) {
        float ts = 0.f;
        #pragma unroll
        for (int i = 0; i < 8; i++) ts += sh[i];
        atomicAdd(&g_msum[r], ts);
    }
}

// ---------------- masked pooling: roi[b,r,c] = sum_v e[b,c,v]*mask[r,v] ----------------
// One block computes the full 64x100 output tile for its v-chunks; register
// accumulation across chunks; one atomicAdd set at the end.
#define PCHUNK 64
__global__ void __launch_bounds__(256, 2)
pool_kernel(const float* __restrict__ buf, const float* __restrict__ ss,
            const float* __restrict__ mask)
{
    __shared__ float e_s[64*PCHUNK];     // [bc][v]
    __shared__ float m_s[PCHUNK*100];    // [v][r]
    __shared__ float na_s[64], nb_s[64];

    const int tid = threadIdx.x;
    if (tid < 64) {
        float s = ss[tid*2], q = ss[tid*2+1];
        float m = s * INV_V;
        float var = fmaxf(q * INV_V - m*m, 0.f);
        float rstd = rsqrtf(var + EPSN);
        na_s[tid] = rstd; nb_s[tid] = -m * rstd;
    }
    __syncthreads();

    const int rg  = tid & 31;   // r = rg + 32*j, j=0..3 (j=3 only if rg<4)
    const int bcg = tid >> 5;   // bc = bcg*8 + k

    float acc[8][4];
    #pragma unroll
    for (int k = 0; k < 8; k++)
        #pragma unroll
        for (int j = 0; j < 4; j++) acc[k][j] = 0.f;

    const int nchunks = VOL / PCHUNK;   // 13824
    for (int ch = blockIdx.x; ch < nchunks; ch += gridDim.x) {
        const int v0 = ch * PCHUNK;
        __syncthreads();
        for (int i = tid; i < 64*PCHUNK; i += 256) {
            int bc = i / PCHUNK, v = i % PCHUNK;
            float raw = buf[(size_t)bc*VOL + v0 + v];
            e_s[i] = fmaxf(fmaf(raw, na_s[bc], nb_s[bc]), 0.f);
        }
        for (int i = tid; i < 100*PCHUNK; i += 256) {
            int r = i / PCHUNK, v = i % PCHUNK;
            m_s[v*100 + r] = mask[(size_t)r*VOL + v0 + v];
        }
        __syncthreads();
        for (int v = 0; v < PCHUNK; v++) {
            float mv[4];
            #pragma unroll
            for (int j = 0; j < 4; j++) {
                int r = rg + 32*j;
                mv[j] = (r < 100) ? m_s[v*100 + r] : 0.f;
            }
            #pragma unroll
            for (int k = 0; k < 8; k++) {
                float e = e_s[(bcg*8 + k)*PCHUNK + v];   // warp-broadcast
                #pragma unroll
                for (int j = 0; j < 4; j++)
                    acc[k][j] = fmaf(e, mv[j], acc[k][j]);
            }
        }
    }
    #pragma unroll
    for (int k = 0; k < 8; k++) {
        int bc = bcg*8 + k;
        int bb = bc >> 5, c = bc & 31;
        #pragma unroll
        for (int j = 0; j < 4; j++) {
            int r = rg + 32*j;
            if (r < 100)
                atomicAdd(&g_roi[(bb*NRR + r)*CH + c], acc[k][j]);
        }
    }
}

// ---------------- per-ROI MLPs + gating + projection ----------------
__global__ void mlp_kernel(const float* __restrict__ sw1, const float* __restrict__ sb1,
                           const float* __restrict__ sw2, const float* __restrict__ sb2,
                           const float* __restrict__ pw1, const float* __restrict__ pb1,
                           const float* __restrict__ pw2, const float* __restrict__ pb2,
                           float* __restrict__ out)
{
    const int b = blockIdx.x / NRR;
    const int r = blockIdx.x % NRR;
    const int tid = threadIdx.x;

    __shared__ float roi_s[32], h_s[64], sf_s[32], h2_s[256];

    if (tid < 32)
        roi_s[tid] = g_roi[(b*NRR + r)*CH + tid] / g_msum[r];
    __syncthreads();

    if (tid < 64) {
        float s = sb1[r*H1N + tid];
        #pragma unroll
        for (int c = 0; c < 32; c++)
            s = fmaf(roi_s[c], sw1[(r*CH + c)*H1N + tid], s);
        h_s[tid] = fmaxf(s, 0.f);
    }
    __syncthreads();

    if (tid < 32) {
        float s = sb2[r*CH + tid];
        #pragma unroll
        for (int j = 0; j < 64; j++)
            s = fmaf(h_s[j], sw2[(r*H1N + j)*CH + tid], s);
        float scale = 1.f / (1.f + expf(-s));
        sf_s[tid] = scale * roi_s[tid];
    }
    __syncthreads();

    {
        float s = pb1[r*RHN + tid];
        #pragma unroll
        for (int c = 0; c < 32; c++)
            s = fmaf(sf_s[c], pw1[(r*CH + c)*RHN + tid], s);
        h2_s[tid] = fmaxf(s, 0.f);
    }
    __syncthreads();

    if (tid < 128) {
        float s = pb2[r*REN + tid];
        for (int k = 0; k < 256; k++)
            s = fmaf(h2_s[k], pw2[(r*RHN + k)*REN + tid], s);
        out[(b*NRR + r)*REN + tid] = s;
    }
}

// ---------------- launch ----------------
extern "C" void kernel_launch(void* const* d_in, const int* in_sizes, int n_in,
                              void* d_out, int out_size)
{
    const float* data    = (const float*)d_in[0];
    const float* mask    = (const float*)d_in[1];
    const float* conv0_w = (const float*)d_in[2];
    // d_in[3] conv0_b: cancels under instance norm — unused
    const float* convk_w = (const float*)d_in[4];
    // d_in[5] convk_b: cancels under instance norm — unused
    const float* sw1 = (const float*)d_in[6];
    const float* sb1 = (const float*)d_in[7];
    const float* sw2 = (const float*)d_in[8];
    const float* sb2 = (const float*)d_in[9];
    const float* pw1 = (const float*)d_in[10];
    const float* pb1 = (const float*)d_in[11];
    const float* pw2 = (const float*)d_in[12];
    const float* pb2 = (const float*)d_in[13];
    float* out = (float*)d_out;

    float* buf0 = nullptr; cudaGetSymbolAddress((void**)&buf0, g_buf0);
    float* buf1 = nullptr; cudaGetSymbolAddress((void**)&buf1, g_buf1);
    float* ssum = nullptr; cudaGetSymbolAddress((void**)&ssum, g_ssum);
    float* ss0 = ssum + 0*BATCH*CH*2;
    float* ss1 = ssum + 1*BATCH*CH*2;
    float* ss2 = ssum + 2*BATCH*CH*2;
    float* ss3 = ssum + 3*BATCH*CH*2;

    const dim3 cgrid(3, 24, 96);        // x-tiles=3, y-tiles=24, z-tiles*batch=48*2
    const dim3 sgrid(54, 64);           // 54 chunks x 64 (b,c)
    const dim3 mgrid(27, 100);

    init_kernel<<<1, 256>>>();

    // conv0: 1 -> 32, raw input (no norm)
    conv3d_kernel<1, false><<<cgrid, 256>>>(data, conv0_w, nullptr, buf0);
    stats_kernel<<<sgrid, 256>>>(buf0, ss0);

    // conv1..3: 32 -> 32, input normalized+relu'd on the fly
    const size_t WSTRIDE = (size_t)CH*CH*27;
    conv3d_kernel<32, true><<<cgrid, 256>>>(buf0, convk_w + 0*WSTRIDE, ss0, buf1);
    stats_kernel<<<sgrid, 256>>>(buf1, ss1);

    conv3d_kernel<32, true><<<cgrid, 256>>>(buf1, convk_w + 1*WSTRIDE, ss1, buf0);
    stats_kernel<<<sgrid, 256>>>(buf0, ss2);

    conv3d_kernel<32, true><<<cgrid, 256>>>(buf0, convk_w + 2*WSTRIDE, ss2, buf1);
    stats_kernel<<<sgrid, 256>>>(buf1, ss3);

    masksum_kernel<<<mgrid, 256>>>(mask);
    pool_kernel<<<296, 256>>>(buf1, ss3, mask);

    mlp_kernel<<<BATCH*NRR, 256>>>(sw1, sb1, sw2, sb2, pw1, pb1, pw2, pb2, out);
}

// round 2
// speedup vs baseline: 1.0002x; 1.0002x over previous
#include <cuda_runtime.h>
#include <cuda_bf16.h>
#include <math.h>

// ---------------- problem constants ----------------
#define BATCH 2
#define CH    32
#define DD    96
#define VOL   (96*96*96)          // 884736
#define NRR   100
#define H1N   64
#define RHN   256
#define REN   128
#define INV_V (1.0f/884736.0f)
#define EPSN  1e-5f

// ---------------- scratch (static device globals; no allocation) ----------------
__device__ float g_buf0[BATCH*CH*VOL];
__device__ float g_buf1[BATCH*CH*VOL];
__device__ float g_ssum[4][BATCH*CH][2];   // per layer: sum, sumsq of raw conv output per (b,c)
__device__ float g_roi [BATCH*NRR*CH];     // pooled accumulators
__device__ float g_msum[NRR];              // mask row sums

// ---------------- init: zero all accumulators (runs every graph replay) ----------------
__global__ void init_kernel() {
    int t = threadIdx.x;
    float* ss = &g_ssum[0][0][0];
    for (int i = t; i < 4*BATCH*CH*2; i += 256) ss[i] = 0.f;
    for (int i = t; i < BATCH*NRR*CH; i += 256) g_roi[i] = 0.f;
    for (int i = t; i < NRR; i += 256) g_msum[i] = 0.f;
}

// ---------------- direct 3x3x3 conv, 32 output channels per thread ----------------
// Input is normalized+relu'd on the fly using stats of the *input* buffer (NORM_IN).
// Output is RAW conv (no bias: biases cancel under instance norm).
template<int CIN, bool NORM_IN>
__global__ void __launch_bounds__(256, 2)
conv3d_kernel(const float* __restrict__ in,
              const float* __restrict__ w,     // [32][CIN][27]
              const float* __restrict__ ss,    // [B*CIN][2] stats of input (ignored if !NORM_IN)
              float* __restrict__ out)
{
    constexpr int GC = (CIN < 8) ? CIN : 8;    // cin group staged in smem
    __shared__ float w_s[GC*27*32];            // [cil][tap][co], co contiguous

    const int tid = threadIdx.x;
    const int tx = tid & 31;
    const int ty = (tid >> 5) & 3;
    const int tz = tid >> 7;
    const int x0 = blockIdx.x * 32 + tx;
    const int y0 = blockIdx.y * 4 + ty;
    const int b  = blockIdx.z / 48;
    const int z0 = (blockIdx.z % 48) * 2 + tz;

    float acc[32];
    #pragma unroll
    for (int q = 0; q < 32; q++) acc[q] = 0.f;

    for (int cg = 0; cg < CIN; cg += GC) {
        __syncthreads();
        for (int i = tid; i < GC*27*32; i += 256) {
            int co  = i & 31;
            int rem = i >> 5;
            int tap = rem % 27;
            int cil = rem / 27;
            w_s[i] = w[(co*CIN + cg + cil)*27 + tap];
        }
        __syncthreads();

        #pragma unroll 1
        for (int cil = 0; cil < GC; cil++) {
            const int ci = cg + cil;
            const float* p = in + (size_t)(b*CIN + ci) * VOL;
            float na = 1.f, nb = 0.f;
            if (NORM_IN) {
                float s = ss[(b*CIN + ci)*2 + 0];
                float q = ss[(b*CIN + ci)*2 + 1];
                float m = s * INV_V;
                float var = fmaxf(q * INV_V - m*m, 0.f);
                float rstd = rsqrtf(var + EPSN);
                na = rstd; nb = -m * rstd;
            }
            // gather 3x3x3 neighborhood (zero-padded SAME)
            float xv[27];
            #pragma unroll
            for (int dz = 0; dz < 3; dz++) {
                int z = z0 + dz - 1;
                bool okz = ((unsigned)z < 96u);
                #pragma unroll
                for (int dy = 0; dy < 3; dy++) {
                    int y = y0 + dy - 1;
                    bool oky = okz && ((unsigned)y < 96u);
                    #pragma unroll
                    for (int dx = 0; dx < 3; dx++) {
                        int x = x0 + dx - 1;
                        float v = 0.f;
                        if (oky && ((unsigned)x < 96u)) {
                            v = __ldg(p + ((size_t)z*96 + y)*96 + x);
                            if (NORM_IN) v = fmaxf(fmaf(v, na, nb), 0.f);
                        }
                        xv[(dz*3 + dy)*3 + dx] = v;
                    }
                }
            }
            // accumulate into 32 output channels; weight reads are warp-broadcast LDS.128
            #pragma unroll
            for (int tap = 0; tap < 27; tap++) {
                float v = xv[tap];
                const float4* wp = reinterpret_cast<const float4*>(w_s + ((cil*27 + tap) << 5));
                #pragma unroll
                for (int q = 0; q < 8; q++) {
                    float4 ww = wp[q];
                    acc[q*4+0] = fmaf(v, ww.x, acc[q*4+0]);
                    acc[q*4+1] = fmaf(v, ww.y, acc[q*4+1]);
                    acc[q*4+2] = fmaf(v, ww.z, acc[q*4+2]);
                    acc[q*4+3] = fmaf(v, ww.w, acc[q*4+3]);
                }
            }
        }
    }

    const size_t sp = ((size_t)z0*96 + y0)*96 + x0;
    #pragma unroll
    for (int co = 0; co < 32; co++)
        out[(size_t)(b*CH + co)*VOL + sp] = acc[co];
}

// ---------------- per-(b,c) sum / sumsq of a raw buffer ----------------
__global__ void stats_kernel(const float* __restrict__ buf, float* __restrict__ ssum)
{
    const int bc = blockIdx.y;
    const float* p = buf + (size_t)bc * VOL + (size_t)blockIdx.x * 16384;
    float s = 0.f, q = 0.f;
    for (int i = threadIdx.x; i < 16384; i += 256) {
        float v = p[i];
        s += v;
        q = fmaf(v, v, q);
    }
    #pragma unroll
    for (int o = 16; o; o >>= 1) {
        s += __shfl_xor_sync(0xffffffffu, s, o);
        q += __shfl_xor_sync(0xffffffffu, q, o);
    }
    __shared__ float sh[2][8];
    int wrp = threadIdx.x >> 5, ln = threadIdx.x & 31;
    if (ln == 0) { sh[0][wrp] = s; sh[1][wrp] = q; }
    __syncthreads();
    if (threadIdx.x == 0) {
        float ts = 0.f, tq = 0.f;
        #pragma unroll
        for (int i = 0; i < 8; i++) { ts += sh[0][i]; tq += sh[1][i]; }
        atomicAdd(&ssum[bc*2 + 0], ts);
        atomicAdd(&ssum[bc*2 + 1], tq);
    }
}

// ---------------- mask row sums ----------------
__global__ void masksum_kernel(const float* __restrict__ mask)
{
    const int r = blockIdx.y;
    const float* p = mask + (size_t)r * VOL + (size_t)blockIdx.x * 32768;
    float s = 0.f;
    for (int i = threadIdx.x; i < 32768; i += 256) s += p[i];
    #pragma unroll
    for (int o = 16; o; o >>= 1) s += __shfl_xor_sync(0xffffffffu, s, o);
    __shared__ float sh[8];
    int wrp = threadIdx.x >> 5, ln = threadIdx.x & 31;
    if (ln == 0) sh[wrp] = s;
    __syncthreads();
    if (threadIdx.x == 0) {
        float ts = 0.f;
        #pragma unroll
        for (int i = 0; i < 8; i++) ts += sh[i];
        atomicAdd(&g_msum[r], ts);
    }
}

// ---------------- masked pooling: roi[b,r,c] = sum_v e[b,c,v]*mask[r,v] ----------------
// One block computes the full 64x100 output tile for its v-chunks; register
// accumulation across chunks; one atomicAdd set at the end.
#define PCHUNK 64
__global__ void __launch_bounds__(256, 2)
pool_kernel(const float* __restrict__ buf, const float* __restrict__ ss,
            const float* __restrict__ mask)
{
    __shared__ float e_s[64*PCHUNK];     // [bc][v]
    __shared__ float m_s[PCHUNK*100];    // [v][r]
    __shared__ float na_s[64], nb_s[64];

    const int tid = threadIdx.x;
    if (tid < 64) {
        float s = ss[tid*2], q = ss[tid*2+1];
        float m = s * INV_V;
        float var = fmaxf(q * INV_V - m*m, 0.f);
        float rstd = rsqrtf(var + EPSN);
        na_s[tid] = rstd; nb_s[tid] = -m * rstd;
    }
    __syncthreads();

    const int rg  = tid & 31;   // r = rg + 32*j, j=0..3 (j=3 only if rg<4)
    const int bcg = tid >> 5;   // bc = bcg*8 + k

    float acc[8][4];
    #pragma unroll
    for (int k = 0; k < 8; k++)
        #pragma unroll
        for (int j = 0; j < 4; j++) acc[k][j] = 0.f;

    const int nchunks = VOL / PCHUNK;   // 13824
    for (int ch = blockIdx.x; ch < nchunks; ch += gridDim.x) {
        const int v0 = ch * PCHUNK;
        __syncthreads();
        for (int i = tid; i < 64*PCHUNK; i += 256) {
            int bc = i / PCHUNK, v = i % PCHUNK;
            float raw = buf[(size_t)bc*VOL + v0 + v];
            e_s[i] = fmaxf(fmaf(raw, na_s[bc], nb_s[bc]), 0.f);
        }
        for (int i = tid; i < 100*PCHUNK; i += 256) {
            int r = i / PCHUNK, v = i % PCHUNK;
            m_s[v*100 + r] = mask[(size_t)r*VOL + v0 + v];
        }
        __syncthreads();
        for (int v = 0; v < PCHUNK; v++) {
            float mv[4];
            #pragma unroll
            for (int j = 0; j < 4; j++) {
                int r = rg + 32*j;
                mv[j] = (r < 100) ? m_s[v*100 + r] : 0.f;
            }
            #pragma unroll
            for (int k = 0; k < 8; k++) {
                float e = e_s[(bcg*8 + k)*PCHUNK + v];   // warp-broadcast
                #pragma unroll
                for (int j = 0; j < 4; j++)
                    acc[k][j] = fmaf(e, mv[j], acc[k][j]);
            }
        }
    }
    #pragma unroll
    for (int k = 0; k < 8; k++) {
        int bc = bcg*8 + k;
        int bb = bc >> 5, c = bc & 31;
        #pragma unroll
        for (int j = 0; j < 4; j++) {
            int r = rg + 32*j;
            if (r < 100)
                atomicAdd(&g_roi[(bb*NRR + r)*CH + c], acc[k][j]);
        }
    }
}

// ---------------- per-ROI MLPs + gating + projection ----------------
__global__ void mlp_kernel(const float* __restrict__ sw1, const float* __restrict__ sb1,
                           const float* __restrict__ sw2, const float* __restrict__ sb2,
                           const float* __restrict__ pw1, const float* __restrict__ pb1,
                           const float* __restrict__ pw2, const float* __restrict__ pb2,
                           float* __restrict__ out)
{
    const int b = blockIdx.x / NRR;
    const int r = blockIdx.x % NRR;
    const int tid = threadIdx.x;

    __shared__ float roi_s[32], h_s[64], sf_s[32], h2_s[256];

    if (tid < 32)
        roi_s[tid] = g_roi[(b*NRR + r)*CH + tid] / g_msum[r];
    __syncthreads();

    if (tid < 64) {
        float s = sb1[r*H1N + tid];
        #pragma unroll
        for (int c = 0; c < 32; c++)
            s = fmaf(roi_s[c], sw1[(r*CH + c)*H1N + tid], s);
        h_s[tid] = fmaxf(s, 0.f);
    }
    __syncthreads();

    if (tid < 32) {
        float s = sb2[r*CH + tid];
        #pragma unroll
        for (int j = 0; j < 64; j++)
            s = fmaf(h_s[j], sw2[(r*H1N + j)*CH + tid], s);
        float scale = 1.f / (1.f + expf(-s));
        sf_s[tid] = scale * roi_s[tid];
    }
    __syncthreads();

    {
        float s = pb1[r*RHN + tid];
        #pragma unroll
        for (int c = 0; c < 32; c++)
            s = fmaf(sf_s[c], pw1[(r*CH + c)*RHN + tid], s);
        h2_s[tid] = fmaxf(s, 0.f);
    }
    __syncthreads();

    if (tid < 128) {
        float s = pb2[r*REN + tid];
        for (int k = 0; k < 256; k++)
            s = fmaf(h2_s[k], pw2[(r*RHN + k)*REN + tid], s);
        out[(b*NRR + r)*REN + tid] = s;
    }
}

// ---------------- launch ----------------
extern "C" void kernel_launch(void* const* d_in, const int* in_sizes, int n_in,
                              void* d_out, int out_size)
{
    const float* data    = (const float*)d_in[0];
    const float* mask    = (const float*)d_in[1];
    const float* conv0_w = (const float*)d_in[2];
    // d_in[3] conv0_b: cancels under instance norm — unused
    const float* convk_w = (const float*)d_in[4];
    // d_in[5] convk_b: cancels under instance norm — unused
    const float* sw1 = (const float*)d_in[6];
    const float* sb1 = (const float*)d_in[7];
    const float* sw2 = (const float*)d_in[8];
    const float* sb2 = (const float*)d_in[9];
    const float* pw1 = (const float*)d_in[10];
    const float* pb1 = (const float*)d_in[11];
    const float* pw2 = (const float*)d_in[12];
    const float* pb2 = (const float*)d_in[13];
    float* out = (float*)d_out;

    float* buf0 = nullptr; cudaGetSymbolAddress((void**)&buf0, g_buf0);
    float* buf1 = nullptr; cudaGetSymbolAddress((void**)&buf1, g_buf1);
    float* ssum = nullptr; cudaGetSymbolAddress((void**)&ssum, g_ssum);
    float* ss0 = ssum + 0*BATCH*CH*2;
    float* ss1 = ssum + 1*BATCH*CH*2;
    float* ss2 = ssum + 2*BATCH*CH*2;
    float* ss3 = ssum + 3*BATCH*CH*2;

    const dim3 cgrid(3, 24, 96);        // x-tiles=3, y-tiles=24, z-tiles*batch=48*2
    const dim3 sgrid(54, 64);           // 54 chunks x 64 (b,c)
    const dim3 mgrid(27, 100);

    init_kernel<<<1, 256>>>();

    // conv0: 1 -> 32, raw input (no norm)
    conv3d_kernel<1, false><<<cgrid, 256>>>(data, conv0_w, nullptr, buf0);
    stats_kernel<<<sgrid, 256>>>(buf0, ss0);

    // conv1..3: 32 -> 32, input normalized+relu'd on the fly
    const size_t WSTRIDE = (size_t)CH*CH*27;
    conv3d_kernel<32, true><<<cgrid, 256>>>(buf0, convk_w + 0*WSTRIDE, ss0, buf1);
    stats_kernel<<<sgrid, 256>>>(buf1, ss1);

    conv3d_kernel<32, true><<<cgrid, 256>>>(buf1, convk_w + 1*WSTRIDE, ss1, buf0);
    stats_kernel<<<sgrid, 256>>>(buf0, ss2);

    conv3d_kernel<32, true><<<cgrid, 256>>>(buf0, convk_w + 2*WSTRIDE, ss2, buf1);
    stats_kernel<<<sgrid, 256>>>(buf1, ss3);

    masksum_kernel<<<mgrid, 256>>>(mask);
    pool_kernel<<<296, 256>>>(buf1, ss3, mask);

    mlp_kernel<<<BATCH*NRR, 256>>>(sw1, sb1, sw2, sb2, pw1, pb1, pw2, pb2, out);
}

// round 3
// speedup vs baseline: 1.3681x; 1.3679x over previous
#include <cuda_runtime.h>
#include <cuda_bf16.h>
#include <math.h>

// ---------------- problem constants ----------------
#define BATCH 2
#define CH    32
#define VOL   (96*96*96)          // 884736
#define NRR   100
#define H1N   64
#define RHN   256
#define REN   128
#define INV_V (1.0f/884736.0f)
#define EPSN  1e-5f

typedef unsigned long long ull;

// ---------------- f32x2 helpers (Blackwell packed fp32) ----------------
__device__ __forceinline__ void fma2(ull& d, ull a, ull b) {
    asm("fma.rn.f32x2 %0, %1, %2, %3;" : "=l"(d) : "l"(a), "l"(b), "l"(d));
}
__device__ __forceinline__ ull pack2(float v) {
    ull r; asm("mov.b64 %0, {%1, %1};" : "=l"(r) : "f"(v)); return r;
}
__device__ __forceinline__ ull packpair(float lo, float hi) {
    ull r; asm("mov.b64 %0, {%1, %2};" : "=l"(r) : "f"(lo), "f"(hi)); return r;
}
__device__ __forceinline__ void unpack2(float& lo, float& hi, ull a) {
    asm("mov.b64 {%0, %1}, %2;" : "=f"(lo), "=f"(hi) : "l"(a));
}

// ---------------- scratch (static device globals; no allocation) ----------------
__device__ float g_buf0[BATCH*CH*VOL];
__device__ float g_buf1[BATCH*CH*VOL];
__device__ float g_ssum[4][BATCH*CH][2];
__device__ float g_roi [BATCH*NRR*CH];
__device__ float g_msum[NRR];

// ---------------- init: zero accumulators (runs every replay) ----------------
__global__ void init_kernel() {
    int t = threadIdx.x;
    float* ss = &g_ssum[0][0][0];
    for (int i = t; i < 4*BATCH*CH*2; i += 256) ss[i] = 0.f;
    for (int i = t; i < BATCH*NRR*CH; i += 256) g_roi[i] = 0.f;
    for (int i = t; i < NRR; i += 256) g_msum[i] = 0.f;
}

// ---------------- direct 3x3x3 conv with f32x2 math ----------------
// Each thread: 4 x-consecutive voxels x 16 output channels (co-pair packed accs).
// Input already normalized+relu'd (or raw for layer 0). Output RAW conv
// (biases cancel under instance norm).
template<int CIN, int GC>
__global__ void __launch_bounds__(192, 2)
conv3d_kernel(const float* __restrict__ in,
              const float* __restrict__ w,     // [32][CIN][27]
              float* __restrict__ out)
{
    __shared__ float w_s[GC*27*32];            // [cil][tap][co], co contiguous

    const int tid = threadIdx.x;
    const int xg  = tid % 12;
    const int cg  = (tid / 12) & 1;            // co half: 0 or 1
    const int ty  = (tid / 24) % 4;
    const int tz  = tid / 96;
    const int x0  = blockIdx.x * 48 + xg * 4;  // 16B-aligned
    const int y0  = blockIdx.y * 4 + ty;
    const int b   = blockIdx.z / 48;
    const int z0  = (blockIdx.z % 48) * 2 + tz;
    const int cobase = cg * 16;

    ull acc[4][8];                              // [voxel][co-pair]
    #pragma unroll
    for (int m = 0; m < 4; m++)
        #pragma unroll
        for (int q = 0; q < 8; q++) acc[m][q] = 0ULL;

    for (int cgrp = 0; cgrp < CIN; cgrp += GC) {
        __syncthreads();
        for (int i = tid; i < GC*27*32; i += 192) {
            int co  = i & 31;
            int rem = i >> 5;
            int tap = rem % 27;
            int cil = rem / 27;
            w_s[i] = w[(co*CIN + cgrp + cil)*27 + tap];
        }
        __syncthreads();

        #pragma unroll 1
        for (int cil = 0; cil < GC; cil++) {
            const float* p = in + (size_t)(b*CIN + cgrp + cil) * VOL;

            #pragma unroll 1
            for (int dz = 0; dz < 3; dz++) {
                const int z = z0 + dz - 1;
                const bool zok = ((unsigned)z < 96u);
                #pragma unroll
                for (int dy = 0; dy < 3; dy++) {
                    const int y = y0 + dy - 1;
                    if (!(zok && ((unsigned)y < 96u))) continue;
                    const float* base = p + ((size_t)z*96 + y)*96;

                    // 6 input values v[-1..4] for 4 voxels x 3 dx taps
                    float4 f = *reinterpret_cast<const float4*>(base + x0);
                    float vm1 = (x0 > 0)      ? base[x0-1] : 0.f;
                    float v4  = (x0 + 4 < 96) ? base[x0+4] : 0.f;
                    ull vv[6];
                    vv[0] = pack2(vm1); vv[1] = pack2(f.x); vv[2] = pack2(f.y);
                    vv[3] = pack2(f.z); vv[4] = pack2(f.w); vv[5] = pack2(v4);

                    #pragma unroll
                    for (int dx = 0; dx < 3; dx++) {
                        const int tap = (dz*3 + dy)*3 + dx;
                        const ulonglong2* wp = reinterpret_cast<const ulonglong2*>(
                            w_s + ((cil*27 + tap) << 5) + cobase);
                        ulonglong2 w0 = wp[0], w1 = wp[1], w2 = wp[2], w3 = wp[3];
                        ull wq[8] = { w0.x, w0.y, w1.x, w1.y, w2.x, w2.y, w3.x, w3.y };
                        #pragma unroll
                        for (int m = 0; m < 4; m++) {
                            ull v = vv[m + dx];
                            #pragma unroll
                            for (int q = 0; q < 8; q++)
                                fma2(acc[m][q], v, wq[q]);
                        }
                    }
                }
            }
        }
    }

    const size_t sp = ((size_t)z0*96 + y0)*96 + x0;
    #pragma unroll
    for (int q = 0; q < 8; q++) {
        float lo[4], hi[4];
        #pragma unroll
        for (int m = 0; m < 4; m++) unpack2(lo[m], hi[m], acc[m][q]);
        float4 a = make_float4(lo[0], lo[1], lo[2], lo[3]);
        float4 bx = make_float4(hi[0], hi[1], hi[2], hi[3]);
        *reinterpret_cast<float4*>(out + (size_t)(b*CH + cobase + 2*q    )*VOL + sp) = a;
        *reinterpret_cast<float4*>(out + (size_t)(b*CH + cobase + 2*q + 1)*VOL + sp) = bx;
    }
}

// ---------------- per-(b,c) sum / sumsq (vectorized) ----------------
__global__ void stats_kernel(const float* __restrict__ buf, float* __restrict__ ssum)
{
    const int bc = blockIdx.y;
    const float4* p = reinterpret_cast<const float4*>(buf + (size_t)bc * VOL)
                      + (size_t)blockIdx.x * 4096;
    float s = 0.f, q = 0.f;
    for (int i = threadIdx.x; i < 4096; i += 256) {
        float4 v = p[i];
        s += v.x + v.y + v.z + v.w;
        q = fmaf(v.x, v.x, q); q = fmaf(v.y, v.y, q);
        q = fmaf(v.z, v.z, q); q = fmaf(v.w, v.w, q);
    }
    #pragma unroll
    for (int o = 16; o; o >>= 1) {
        s += __shfl_xor_sync(0xffffffffu, s, o);
        q += __shfl_xor_sync(0xffffffffu, q, o);
    }
    __shared__ float sh[2][8];
    int wrp = threadIdx.x >> 5, ln = threadIdx.x & 31;
    if (ln == 0) { sh[0][wrp] = s; sh[1][wrp] = q; }
    __syncthreads();
    if (threadIdx.x == 0) {
        float ts = 0.f, tq = 0.f;
        #pragma unroll
        for (int i = 0; i < 8; i++) { ts += sh[0][i]; tq += sh[1][i]; }
        atomicAdd(&ssum[bc*2 + 0], ts);
        atomicAdd(&ssum[bc*2 + 1], tq);
    }
}

// ---------------- in-place normalize + relu ----------------
__global__ void norm_relu_kernel(float* __restrict__ buf, const float* __restrict__ ss)
{
    const int bc = blockIdx.y;
    const float s = ss[bc*2 + 0];
    const float q = ss[bc*2 + 1];
    const float m = s * INV_V;
    const float var = fmaxf(q * INV_V - m*m, 0.f);
    const float rstd = rsqrtf(var + EPSN);
    const float na = rstd, nb = -m * rstd;

    float4* p = reinterpret_cast<float4*>(buf + (size_t)bc * VOL)
                + (size_t)blockIdx.x * 4096;
    for (int i = threadIdx.x; i < 4096; i += 256) {
        float4 v = p[i];
        v.x = fmaxf(fmaf(v.x, na, nb), 0.f);
        v.y = fmaxf(fmaf(v.y, na, nb), 0.f);
        v.z = fmaxf(fmaf(v.z, na, nb), 0.f);
        v.w = fmaxf(fmaf(v.w, na, nb), 0.f);
        p[i] = v;
    }
}

// ---------------- mask row sums ----------------
__global__ void masksum_kernel(const float* __restrict__ mask)
{
    const int r = blockIdx.y;
    const float4* p = reinterpret_cast<const float4*>(mask + (size_t)r * VOL)
                      + (size_t)blockIdx.x * 8192;
    float s = 0.f;
    for (int i = threadIdx.x; i < 8192; i += 256) {
        float4 v = p[i];
        s += v.x + v.y + v.z + v.w;
    }
    #pragma unroll
    for (int o = 16; o; o >>= 1) s += __shfl_xor_sync(0xffffffffu, s, o);
    __shared__ float sh[8];
    int wrp = threadIdx.x >> 5, ln = threadIdx.x & 31;
    if (ln == 0) sh[wrp] = s;
    __syncthreads();
    if (threadIdx.x == 0) {
        float ts = 0.f;
        #pragma unroll
        for (int i = 0; i < 8; i++) ts += sh[i];
        atomicAdd(&g_msum[r], ts);
    }
}

// ---------------- masked pooling (input already normalized) ----------------
#define PCHUNK 64
__global__ void __launch_bounds__(256, 2)
pool_kernel(const float* __restrict__ buf, const float* __restrict__ mask)
{
    __shared__ float e_s[64*PCHUNK];     // [bc][v]
    __shared__ float m_s[PCHUNK*100];    // [v][r]

    const int tid = threadIdx.x;
    const int rg  = tid & 31;            // r = rg + 32*j
    const int bcg = tid >> 5;            // bc = bcg*8 + k

    ull acc[8][2];                        // [k][j-pair: (rg, rg+32) / (rg+64, rg+96)]
    #pragma unroll
    for (int k = 0; k < 8; k++) { acc[k][0] = 0ULL; acc[k][1] = 0ULL; }

    const int nchunks = VOL / PCHUNK;    // 13824
    for (int chn = blockIdx.x; chn < nchunks; chn += gridDim.x) {
        const int v0 = chn * PCHUNK;
        __syncthreads();
        for (int i = tid; i < 64*PCHUNK/4; i += 256) {
            int bc = i / (PCHUNK/4), vq = i % (PCHUNK/4);
            float4 f = *reinterpret_cast<const float4*>(buf + (size_t)bc*VOL + v0 + vq*4);
            *reinterpret_cast<float4*>(e_s + bc*PCHUNK + vq*4) = f;
        }
        for (int i = tid; i < 100*PCHUNK/4; i += 256) {
            int r = i / (PCHUNK/4), vq = i % (PCHUNK/4);
            float4 f = *reinterpret_cast<const float4*>(mask + (size_t)r*VOL + v0 + vq*4);
            m_s[(vq*4+0)*100 + r] = f.x;
            m_s[(vq*4+1)*100 + r] = f.y;
            m_s[(vq*4+2)*100 + r] = f.z;
            m_s[(vq*4+3)*100 + r] = f.w;
        }
        __syncthreads();
        for (int v = 0; v < PCHUNK; v++) {
            float mv0 = m_s[v*100 + rg];
            float mv1 = m_s[v*100 + rg + 32];
            float mv2 = m_s[v*100 + rg + 64];
            float mv3 = (rg < 4) ? m_s[v*100 + rg + 96] : 0.f;
            ull mp01 = packpair(mv0, mv1);
            ull mp23 = packpair(mv2, mv3);
            #pragma unroll
            for (int k = 0; k < 8; k++) {
                ull ee = pack2(e_s[(bcg*8 + k)*PCHUNK + v]);
                fma2(acc[k][0], ee, mp01);
                fma2(acc[k][1], ee, mp23);
            }
        }
    }
    #pragma unroll
    for (int k = 0; k < 8; k++) {
        int bc = bcg*8 + k;
        int bb = bc >> 5, c = bc & 31;
        float a0, a1, a2, a3;
        unpack2(a0, a1, acc[k][0]);
        unpack2(a2, a3, acc[k][1]);
        atomicAdd(&g_roi[(bb*NRR + rg     )*CH + c], a0);
        atomicAdd(&g_roi[(bb*NRR + rg + 32)*CH + c], a1);
        atomicAdd(&g_roi[(bb*NRR + rg + 64)*CH + c], a2);
        if (rg < 4)
            atomicAdd(&g_roi[(bb*NRR + rg + 96)*CH + c], a3);
    }
}

// ---------------- per-ROI MLPs + gating + projection ----------------
__global__ void mlp_kernel(const float* __restrict__ sw1, const float* __restrict__ sb1,
                           const float* __restrict__ sw2, const float* __restrict__ sb2,
                           const float* __restrict__ pw1, const float* __restrict__ pb1,
                           const float* __restrict__ pw2, const float* __restrict__ pb2,
                           float* __restrict__ out)
{
    const int b = blockIdx.x / NRR;
    const int r = blockIdx.x % NRR;
    const int tid = threadIdx.x;

    __shared__ float roi_s[32], h_s[64], sf_s[32], h2_s[256];

    if (tid < 32)
        roi_s[tid] = g_roi[(b*NRR + r)*CH + tid] / g_msum[r];
    __syncthreads();

    if (tid < 64) {
        float s = sb1[r*H1N + tid];
        #pragma unroll
        for (int c = 0; c < 32; c++)
            s = fmaf(roi_s[c], sw1[(r*CH + c)*H1N + tid], s);
        h_s[tid] = fmaxf(s, 0.f);
    }
    __syncthreads();

    if (tid < 32) {
        float s = sb2[r*CH + tid];
        #pragma unroll
        for (int j = 0; j < 64; j++)
            s = fmaf(h_s[j], sw2[(r*H1N + j)*CH + tid], s);
        float scale = 1.f / (1.f + expf(-s));
        sf_s[tid] = scale * roi_s[tid];
    }
    __syncthreads();

    {
        float s = pb1[r*RHN + tid];
        #pragma unroll
        for (int c = 0; c < 32; c++)
            s = fmaf(sf_s[c], pw1[(r*CH + c)*RHN + tid], s);
        h2_s[tid] = fmaxf(s, 0.f);
    }
    __syncthreads();

    if (tid < 128) {
        float s = pb2[r*REN + tid];
        for (int k = 0; k < 256; k++)
            s = fmaf(h2_s[k], pw2[(r*RHN + k)*REN + tid], s);
        out[(b*NRR + r)*REN + tid] = s;
    }
}

// ---------------- launch ----------------
extern "C" void kernel_launch(void* const* d_in, const int* in_sizes, int n_in,
                              void* d_out, int out_size)
{
    const float* data    = (const float*)d_in[0];
    const float* mask    = (const float*)d_in[1];
    const float* conv0_w = (const float*)d_in[2];
    const float* convk_w = (const float*)d_in[4];
    const float* sw1 = (const float*)d_in[6];
    const float* sb1 = (const float*)d_in[7];
    const float* sw2 = (const float*)d_in[8];
    const float* sb2 = (const float*)d_in[9];
    const float* pw1 = (const float*)d_in[10];
    const float* pb1 = (const float*)d_in[11];
    const float* pw2 = (const float*)d_in[12];
    const float* pb2 = (const float*)d_in[13];
    float* out = (float*)d_out;

    float* buf0 = nullptr; cudaGetSymbolAddress((void**)&buf0, g_buf0);
    float* buf1 = nullptr; cudaGetSymbolAddress((void**)&buf1, g_buf1);
    float* ssum = nullptr; cudaGetSymbolAddress((void**)&ssum, g_ssum);
    float* ss0 = ssum + 0*BATCH*CH*2;
    float* ss1 = ssum + 1*BATCH*CH*2;
    float* ss2 = ssum + 2*BATCH*CH*2;
    float* ss3 = ssum + 3*BATCH*CH*2;

    const dim3 cgrid(2, 24, 96);        // x-tiles=2(48w), y=24, z-tiles*batch
    const dim3 sgrid(54, 64);           // 54 chunks x 64 (b,c)
    const dim3 mgrid(27, 100);

    init_kernel<<<1, 256>>>();

    // conv0: 1 -> 32 on raw input
    conv3d_kernel<1, 1><<<cgrid, 192>>>(data, conv0_w, buf0);
    stats_kernel<<<sgrid, 256>>>(buf0, ss0);
    norm_relu_kernel<<<sgrid, 256>>>(buf0, ss0);

    const size_t WSTRIDE = (size_t)CH*CH*27;
    conv3d_kernel<32, 8><<<cgrid, 192>>>(buf0, convk_w + 0*WSTRIDE, buf1);
    stats_kernel<<<sgrid, 256>>>(buf1, ss1);
    norm_relu_kernel<<<sgrid, 256>>>(buf1, ss1);

    conv3d_kernel<32, 8><<<cgrid, 192>>>(buf1, convk_w + 1*WSTRIDE, buf0);
    stats_kernel<<<sgrid, 256>>>(buf0, ss2);
    norm_relu_kernel<<<sgrid, 256>>>(buf0, ss2);

    conv3d_kernel<32, 8><<<cgrid, 192>>>(buf0, convk_w + 2*WSTRIDE, buf1);
    stats_kernel<<<sgrid, 256>>>(buf1, ss3);
    norm_relu_kernel<<<sgrid, 256>>>(buf1, ss3);

    masksum_kernel<<<mgrid, 256>>>(mask);
    pool_kernel<<<296, 256>>>(buf1, mask);

    mlp_kernel<<<BATCH*NRR, 256>>>(sw1, sb1, sw2, sb2, pw1, pb1, pw2, pb2, out);
}

// round 4
// speedup vs baseline: 1.3699x; 1.0013x over previous
#include <cuda_runtime.h>
#include <cuda_bf16.h>
#include <math.h>

// ---------------- problem constants ----------------
#define BATCH 2
#define CH    32
#define VOL   (96*96*96)          // 884736
#define NRR   100
#define H1N   64
#define RHN   256
#define REN   128
#define INV_V (1.0f/884736.0f)
#define EPSN  1e-5f

typedef unsigned long long ull;

// ---------------- f32x2 helpers (Blackwell packed fp32) ----------------
__device__ __forceinline__ void fma2(ull& d, ull a, ull b) {
    asm("fma.rn.f32x2 %0, %1, %2, %3;" : "=l"(d) : "l"(a), "l"(b), "l"(d));
}
__device__ __forceinline__ ull pack2(float v) {
    ull r; asm("mov.b64 %0, {%1, %1};" : "=l"(r) : "f"(v)); return r;
}
__device__ __forceinline__ ull packpair(float lo, float hi) {
    ull r; asm("mov.b64 %0, {%1, %2};" : "=l"(r) : "f"(lo), "f"(hi)); return r;
}
__device__ __forceinline__ void unpack2(float& lo, float& hi, ull a) {
    asm("mov.b64 {%0, %1}, %2;" : "=f"(lo), "=f"(hi) : "l"(a));
}

// ---------------- scratch (static device globals; no allocation) ----------------
__device__ float g_buf0[BATCH*CH*VOL];
__device__ float g_buf1[BATCH*CH*VOL];
__device__ float g_ssum[4][BATCH*CH][2];
__device__ float g_roi [BATCH*NRR*CH];
__device__ float g_msum[NRR];

// ---------------- init: zero accumulators (runs every replay) ----------------
__global__ void init_kernel() {
    int t = threadIdx.x;
    float* ss = &g_ssum[0][0][0];
    for (int i = t; i < 4*BATCH*CH*2; i += 256) ss[i] = 0.f;
    for (int i = t; i < BATCH*NRR*CH; i += 256) g_roi[i] = 0.f;
    for (int i = t; i < NRR; i += 256) g_msum[i] = 0.f;
}

// ---------------- direct 3x3x3 conv with f32x2 math ----------------
// Each thread: 4 x-consecutive voxels x 16 output channels (co-pair packed accs).
// Input already normalized+relu'd (or raw for layer 0). Output RAW conv
// (biases cancel under instance norm).
template<int CIN, int GC>
__global__ void __launch_bounds__(192, 2)
conv3d_kernel(const float* __restrict__ in,
              const float* __restrict__ w,     // [32][CIN][27]
              float* __restrict__ out)
{
    __shared__ float w_s[GC*27*32];            // [cil][tap][co], co contiguous

    const int tid = threadIdx.x;
    const int xg  = tid % 12;
    const int cg  = (tid / 12) & 1;            // co half: 0 or 1
    const int ty  = (tid / 24) % 4;
    const int tz  = tid / 96;
    const int x0  = blockIdx.x * 48 + xg * 4;  // 16B-aligned
    const int y0  = blockIdx.y * 4 + ty;
    const int b   = blockIdx.z / 48;
    const int z0  = (blockIdx.z % 48) * 2 + tz;
    const int cobase = cg * 16;

    ull acc[4][8];                              // [voxel][co-pair]
    #pragma unroll
    for (int m = 0; m < 4; m++)
        #pragma unroll
        for (int q = 0; q < 8; q++) acc[m][q] = 0ULL;

    for (int cgrp = 0; cgrp < CIN; cgrp += GC) {
        __syncthreads();
        for (int i = tid; i < GC*27*32; i += 192) {
            int co  = i & 31;
            int rem = i >> 5;
            int tap = rem % 27;
            int cil = rem / 27;
            w_s[i] = w[(co*CIN + cgrp + cil)*27 + tap];
        }
        __syncthreads();

        #pragma unroll 1
        for (int cil = 0; cil < GC; cil++) {
            const float* p = in + (size_t)(b*CIN + cgrp + cil) * VOL;

            #pragma unroll 1
            for (int dz = 0; dz < 3; dz++) {
                const int z = z0 + dz - 1;
                const bool zok = ((unsigned)z < 96u);
                #pragma unroll
                for (int dy = 0; dy < 3; dy++) {
                    const int y = y0 + dy - 1;
                    if (!(zok && ((unsigned)y < 96u))) continue;
                    const float* base = p + ((size_t)z*96 + y)*96;

                    // 6 input values v[-1..4] for 4 voxels x 3 dx taps
                    float4 f = *reinterpret_cast<const float4*>(base + x0);
                    float vm1 = (x0 > 0)      ? base[x0-1] : 0.f;
                    float v4  = (x0 + 4 < 96) ? base[x0+4] : 0.f;
                    ull vv[6];
                    vv[0] = pack2(vm1); vv[1] = pack2(f.x); vv[2] = pack2(f.y);
                    vv[3] = pack2(f.z); vv[4] = pack2(f.w); vv[5] = pack2(v4);

                    #pragma unroll
                    for (int dx = 0; dx < 3; dx++) {
                        const int tap = (dz*3 + dy)*3 + dx;
                        const ulonglong2* wp = reinterpret_cast<const ulonglong2*>(
                            w_s + ((cil*27 + tap) << 5) + cobase);
                        ulonglong2 w0 = wp[0], w1 = wp[1], w2 = wp[2], w3 = wp[3];
                        ull wq[8] = { w0.x, w0.y, w1.x, w1.y, w2.x, w2.y, w3.x, w3.y };
                        #pragma unroll
                        for (int m = 0; m < 4; m++) {
                            ull v = vv[m + dx];
                            #pragma unroll
                            for (int q = 0; q < 8; q++)
                                fma2(acc[m][q], v, wq[q]);
                        }
                    }
                }
            }
        }
    }

    const size_t sp = ((size_t)z0*96 + y0)*96 + x0;
    #pragma unroll
    for (int q = 0; q < 8; q++) {
        float lo[4], hi[4];
        #pragma unroll
        for (int m = 0; m < 4; m++) unpack2(lo[m], hi[m], acc[m][q]);
        float4 a = make_float4(lo[0], lo[1], lo[2], lo[3]);
        float4 bx = make_float4(hi[0], hi[1], hi[2], hi[3]);
        *reinterpret_cast<float4*>(out + (size_t)(b*CH + cobase + 2*q    )*VOL + sp) = a;
        *reinterpret_cast<float4*>(out + (size_t)(b*CH + cobase + 2*q + 1)*VOL + sp) = bx;
    }
}

// ---------------- per-(b,c) sum / sumsq (vectorized) ----------------
__global__ void stats_kernel(const float* __restrict__ buf, float* __restrict__ ssum)
{
    const int bc = blockIdx.y;
    const float4* p = reinterpret_cast<const float4*>(buf + (size_t)bc * VOL)
                      + (size_t)blockIdx.x * 4096;
    float s = 0.f, q = 0.f;
    for (int i = threadIdx.x; i < 4096; i += 256) {
        float4 v = p[i];
        s += v.x + v.y + v.z + v.w;
        q = fmaf(v.x, v.x, q); q = fmaf(v.y, v.y, q);
        q = fmaf(v.z, v.z, q); q = fmaf(v.w, v.w, q);
    }
    #pragma unroll
    for (int o = 16; o; o >>= 1) {
        s += __shfl_xor_sync(0xffffffffu, s, o);
        q += __shfl_xor_sync(0xffffffffu, q, o);
    }
    __shared__ float sh[2][8];
    int wrp = threadIdx.x >> 5, ln = threadIdx.x & 31;
    if (ln == 0) { sh[0][wrp] = s; sh[1][wrp] = q; }
    __syncthreads();
    if (threadIdx.x == 0) {
        float ts = 0.f, tq = 0.f;
        #pragma unroll
        for (int i = 0; i < 8; i++) { ts += sh[0][i]; tq += sh[1][i]; }
        atomicAdd(&ssum[bc*2 + 0], ts);
        atomicAdd(&ssum[bc*2 + 1], tq);
    }
}

// ---------------- in-place normalize + relu ----------------
__global__ void norm_relu_kernel(float* __restrict__ buf, const float* __restrict__ ss)
{
    const int bc = blockIdx.y;
    const float s = ss[bc*2 + 0];
    const float q = ss[bc*2 + 1];
    const float m = s * INV_V;
    const float var = fmaxf(q * INV_V - m*m, 0.f);
    const float rstd = rsqrtf(var + EPSN);
    const float na = rstd, nb = -m * rstd;

    float4* p = reinterpret_cast<float4*>(buf + (size_t)bc * VOL)
                + (size_t)blockIdx.x * 4096;
    for (int i = threadIdx.x; i < 4096; i += 256) {
        float4 v = p[i];
        v.x = fmaxf(fmaf(v.x, na, nb), 0.f);
        v.y = fmaxf(fmaf(v.y, na, nb), 0.f);
        v.z = fmaxf(fmaf(v.z, na, nb), 0.f);
        v.w = fmaxf(fmaf(v.w, na, nb), 0.f);
        p[i] = v;
    }
}

// ---------------- mask row sums ----------------
__global__ void masksum_kernel(const float* __restrict__ mask)
{
    const int r = blockIdx.y;
    const float4* p = reinterpret_cast<const float4*>(mask + (size_t)r * VOL)
                      + (size_t)blockIdx.x * 8192;
    float s = 0.f;
    for (int i = threadIdx.x; i < 8192; i += 256) {
        float4 v = p[i];
        s += v.x + v.y + v.z + v.w;
    }
    #pragma unroll
    for (int o = 16; o; o >>= 1) s += __shfl_xor_sync(0xffffffffu, s, o);
    __shared__ float sh[8];
    int wrp = threadIdx.x >> 5, ln = threadIdx.x & 31;
    if (ln == 0) sh[wrp] = s;
    __syncthreads();
    if (threadIdx.x == 0) {
        float ts = 0.f;
        #pragma unroll
        for (int i = 0; i < 8; i++) ts += sh[i];
        atomicAdd(&g_msum[r], ts);
    }
}

// ---------------- masked pooling (input already normalized) ----------------
#define PCHUNK 64
__global__ void __launch_bounds__(256, 2)
pool_kernel(const float* __restrict__ buf, const float* __restrict__ mask)
{
    __shared__ float e_s[64*PCHUNK];     // [bc][v]
    __shared__ float m_s[PCHUNK*100];    // [v][r]

    const int tid = threadIdx.x;
    const int rg  = tid & 31;            // r = rg + 32*j
    const int bcg = tid >> 5;            // bc = bcg*8 + k

    ull acc[8][2];                        // [k][j-pair: (rg, rg+32) / (rg+64, rg+96)]
    #pragma unroll
    for (int k = 0; k < 8; k++) { acc[k][0] = 0ULL; acc[k][1] = 0ULL; }

    const int nchunks = VOL / PCHUNK;    // 13824
    for (int chn = blockIdx.x; chn < nchunks; chn += gridDim.x) {
        const int v0 = chn * PCHUNK;
        __syncthreads();
        for (int i = tid; i < 64*PCHUNK/4; i += 256) {
            int bc = i / (PCHUNK/4), vq = i % (PCHUNK/4);
            float4 f = *reinterpret_cast<const float4*>(buf + (size_t)bc*VOL + v0 + vq*4);
            *reinterpret_cast<float4*>(e_s + bc*PCHUNK + vq*4) = f;
        }
        for (int i = tid; i < 100*PCHUNK/4; i += 256) {
            int r = i / (PCHUNK/4), vq = i % (PCHUNK/4);
            float4 f = *reinterpret_cast<const float4*>(mask + (size_t)r*VOL + v0 + vq*4);
            m_s[(vq*4+0)*100 + r] = f.x;
            m_s[(vq*4+1)*100 + r] = f.y;
            m_s[(vq*4+2)*100 + r] = f.z;
            m_s[(vq*4+3)*100 + r] = f.w;
        }
        __syncthreads();
        for (int v = 0; v < PCHUNK; v++) {
            float mv0 = m_s[v*100 + rg];
            float mv1 = m_s[v*100 + rg + 32];
            float mv2 = m_s[v*100 + rg + 64];
            float mv3 = (rg < 4) ? m_s[v*100 + rg + 96] : 0.f;
            ull mp01 = packpair(mv0, mv1);
            ull mp23 = packpair(mv2, mv3);
            #pragma unroll
            for (int k = 0; k < 8; k++) {
                ull ee = pack2(e_s[(bcg*8 + k)*PCHUNK + v]);
                fma2(acc[k][0], ee, mp01);
                fma2(acc[k][1], ee, mp23);
            }
        }
    }
    #pragma unroll
    for (int k = 0; k < 8; k++) {
        int bc = bcg*8 + k;
        int bb = bc >> 5, c = bc & 31;
        float a0, a1, a2, a3;
        unpack2(a0, a1, acc[k][0]);
        unpack2(a2, a3, acc[k][1]);
        atomicAdd(&g_roi[(bb*NRR + rg     )*CH + c], a0);
        atomicAdd(&g_roi[(bb*NRR + rg + 32)*CH + c], a1);
        atomicAdd(&g_roi[(bb*NRR + rg + 64)*CH + c], a2);
        if (rg < 4)
            atomicAdd(&g_roi[(bb*NRR + rg + 96)*CH + c], a3);
    }
}

// ---------------- per-ROI MLPs + gating + projection ----------------
__global__ void mlp_kernel(const float* __restrict__ sw1, const float* __restrict__ sb1,
                           const float* __restrict__ sw2, const float* __restrict__ sb2,
                           const float* __restrict__ pw1, const float* __restrict__ pb1,
                           const float* __restrict__ pw2, const float* __restrict__ pb2,
                           float* __restrict__ out)
{
    const int b = blockIdx.x / NRR;
    const int r = blockIdx.x % NRR;
    const int tid = threadIdx.x;

    __shared__ float roi_s[32], h_s[64], sf_s[32], h2_s[256];

    if (tid < 32)
        roi_s[tid] = g_roi[(b*NRR + r)*CH + tid] / g_msum[r];
    __syncthreads();

    if (tid < 64) {
        float s = sb1[r*H1N + tid];
        #pragma unroll
        for (int c = 0; c < 32; c++)
            s = fmaf(roi_s[c], sw1[(r*CH + c)*H1N + tid], s);
        h_s[tid] = fmaxf(s, 0.f);
    }
    __syncthreads();

    if (tid < 32) {
        float s = sb2[r*CH + tid];
        #pragma unroll
        for (int j = 0; j < 64; j++)
            s = fmaf(h_s[j], sw2[(r*H1N + j)*CH + tid], s);
        float scale = 1.f / (1.f + expf(-s));
        sf_s[tid] = scale * roi_s[tid];
    }
    __syncthreads();

    {
        float s = pb1[r*RHN + tid];
        #pragma unroll
        for (int c = 0; c < 32; c++)
            s = fmaf(sf_s[c], pw1[(r*CH + c)*RHN + tid], s);
        h2_s[tid] = fmaxf(s, 0.f);
    }
    __syncthreads();

    if (tid < 128) {
        float s = pb2[r*REN + tid];
        for (int k = 0; k < 256; k++)
            s = fmaf(h2_s[k], pw2[(r*RHN + k)*REN + tid], s);
        out[(b*NRR + r)*REN + tid] = s;
    }
}

// ---------------- launch ----------------
extern "C" void kernel_launch(void* const* d_in, const int* in_sizes, int n_in,
                              void* d_out, int out_size)
{
    const float* data    = (const float*)d_in[0];
    const float* mask    = (const float*)d_in[1];
    const float* conv0_w = (const float*)d_in[2];
    const float* convk_w = (const float*)d_in[4];
    const float* sw1 = (const float*)d_in[6];
    const float* sb1 = (const float*)d_in[7];
    const float* sw2 = (const float*)d_in[8];
    const float* sb2 = (const float*)d_in[9];
    const float* pw1 = (const float*)d_in[10];
    const float* pb1 = (const float*)d_in[11];
    const float* pw2 = (const float*)d_in[12];
    const float* pb2 = (const float*)d_in[13];
    float* out = (float*)d_out;

    float* buf0 = nullptr; cudaGetSymbolAddress((void**)&buf0, g_buf0);
    float* buf1 = nullptr; cudaGetSymbolAddress((void**)&buf1, g_buf1);
    float* ssum = nullptr; cudaGetSymbolAddress((void**)&ssum, g_ssum);
    float* ss0 = ssum + 0*BATCH*CH*2;
    float* ss1 = ssum + 1*BATCH*CH*2;
    float* ss2 = ssum + 2*BATCH*CH*2;
    float* ss3 = ssum + 3*BATCH*CH*2;

    const dim3 cgrid(2, 24, 96);        // x-tiles=2(48w), y=24, z-tiles*batch
    const dim3 sgrid(54, 64);           // 54 chunks x 64 (b,c)
    const dim3 mgrid(27, 100);

    init_kernel<<<1, 256>>>();

    // conv0: 1 -> 32 on raw input
    conv3d_kernel<1, 1><<<cgrid, 192>>>(data, conv0_w, buf0);
    stats_kernel<<<sgrid, 256>>>(buf0, ss0);
    norm_relu_kernel<<<sgrid, 256>>>(buf0, ss0);

    const size_t WSTRIDE = (size_t)CH*CH*27;
    conv3d_kernel<32, 8><<<cgrid, 192>>>(buf0, convk_w + 0*WSTRIDE, buf1);
    stats_kernel<<<sgrid, 256>>>(buf1, ss1);
    norm_relu_kernel<<<sgrid, 256>>>(buf1, ss1);

    conv3d_kernel<32, 8><<<cgrid, 192>>>(buf1, convk_w + 1*WSTRIDE, buf0);
    stats_kernel<<<sgrid, 256>>>(buf0, ss2);
    norm_relu_kernel<<<sgrid, 256>>>(buf0, ss2);

    conv3d_kernel<32, 8><<<cgrid, 192>>>(buf0, convk_w + 2*WSTRIDE, buf1);
    stats_kernel<<<sgrid, 256>>>(buf1, ss3);
    norm_relu_kernel<<<sgrid, 256>>>(buf1, ss3);

    masksum_kernel<<<mgrid, 256>>>(mask);
    pool_kernel<<<296, 256>>>(buf1, mask);

    mlp_kernel<<<BATCH*NRR, 256>>>(sw1, sb1, sw2, sb2, pw1, pb1, pw2, pb2, out);
}

// round 6
// speedup vs baseline: 2.3783x; 1.7361x over previous
#include <cuda_runtime.h>
#include <cuda_bf16.h>
#include <math.h>
#include <stdint.h>

#define BATCH 2
#define CH    32
#define VOL   (96*96*96)
#define NRR   100
#define RHN   256
#define REN   128
#define INV_V (1.0f/884736.0f)
#define EPSN  1e-5f
#define PXD 132
#define PYD 98
#define PZD 98
#define PVOX (PZD*PYD*PXD)
#define BSTRIDE 104                       // bf16 elems per weight row (conflict-free, 16B-aligned)
#define BTILE   (32*BSTRIDE)              // 3328 elems per (dzdy, ver) weight tile

typedef unsigned long long ull;

// ---------------- f32x2 helpers ----------------
__device__ __forceinline__ void fma2(ull& d, ull a, ull b) {
    asm("fma.rn.f32x2 %0, %1, %2, %3;" : "=l"(d) : "l"(a), "l"(b), "l"(d));
}
__device__ __forceinline__ ull pack2(float v) {
    ull r; asm("mov.b64 %0, {%1, %1};" : "=l"(r) : "f"(v)); return r;
}
__device__ __forceinline__ ull packpair(float lo, float hi) {
    ull r; asm("mov.b64 %0, {%1, %2};" : "=l"(r) : "f"(lo), "f"(hi)); return r;
}
__device__ __forceinline__ void unpack2(float& lo, float& hi, ull a) {
    asm("mov.b64 {%0, %1}, %2;" : "=f"(lo), "=f"(hi) : "l"(a));
}

// ---------------- warp MMA helpers (sm_80-class, works on compute_100) ----------------
__device__ __forceinline__ uint32_t smem_u32(const void* p) {
    uint32_t a;
    asm("{ .reg .u64 t; cvta.to.shared.u64 t, %1; cvt.u32.u64 %0, t; }" : "=r"(a) : "l"(p));
    return a;
}
#define LDSM_X4(r0,r1,r2,r3,addr) \
    asm volatile("ldmatrix.sync.aligned.m8n8.x4.shared.b16 {%0,%1,%2,%3}, [%4];" \
        : "=r"(r0),"=r"(r1),"=r"(r2),"=r"(r3) : "r"(addr))
#define MMA16816(d, a0,a1,a2,a3, b0,b1) \
    asm volatile("mma.sync.aligned.m16n8k16.row.col.f32.bf16.bf16.f32 " \
        "{%0,%1,%2,%3}, {%4,%5,%6,%7}, {%8,%9}, {%0,%1,%2,%3};" \
        : "+f"((d)[0]),"+f"((d)[1]),"+f"((d)[2]),"+f"((d)[3]) \
        : "r"(a0),"r"(a1),"r"(a2),"r"(a3), "r"(b0),"r"(b1))

// ---------------- scratch ----------------
__device__ float g_raw[(size_t)BATCH*VOL*CH];                         // channels-last conv out
__device__ __nv_bfloat16 g_padh[(size_t)BATCH*PVOX*CH];
__device__ __nv_bfloat16 g_padl[(size_t)BATCH*PVOX*CH];
__device__ __align__(16) __nv_bfloat16 g_wprep[3*9*2*BTILE];          // [L][dzdy][h/l][co][104]
__device__ float g_ssum[4][BATCH*CH][2];
__device__ float g_roi [BATCH*NRR*CH];
__device__ float g_msum[NRR];

__global__ void init_kernel() {
    int t = threadIdx.x;
    float* ss = &g_ssum[0][0][0];
    for (int i = t; i < 4*BATCH*CH*2; i += 256) ss[i] = 0.f;
    for (int i = t; i < BATCH*NRR*CH; i += 256) g_roi[i] = 0.f;
    for (int i = t; i < NRR; i += 256) g_msum[i] = 0.f;
}

// ---------------- weight prep: bf16 hi/lo tiles, [co][k=dx*32+ci] stride 104 ----------------
__global__ void wprep_kernel(const float* __restrict__ convk_w) {
    const int L = blockIdx.x / 9;
    const int r = blockIdx.x % 9;
    const int dz = r / 3, dy = r % 3;
    __nv_bfloat16* bh = g_wprep + ((size_t)(L*9 + r)*2 + 0)*BTILE;
    __nv_bfloat16* bl = bh + BTILE;
    for (int i = threadIdx.x; i < 32*BSTRIDE; i += 256) {
        int co = i / BSTRIDE, k = i % BSTRIDE;
        float wv = 0.f;
        if (k < 96) {
            int dx = k >> 5, ci = k & 31;
            wv = convk_w[(size_t)((L*32 + co)*32 + ci)*27 + (dz*3 + dy)*3 + dx];
        }
        __nv_bfloat16 h = __float2bfloat16(wv);
        bh[i] = h;
        bl[i] = __float2bfloat16(wv - __bfloat162float(h));
    }
}

// ---------------- conv0: 1->32 direct, channels-last out ----------------
__global__ void conv0_kernel(const float* __restrict__ data,
                             const float* __restrict__ w0,
                             float* __restrict__ raw) {
    __shared__ float ws[27*32];
    for (int i = threadIdx.x; i < 864; i += 256) {
        int tap = i / 32, c = i % 32;
        ws[tap*32 + c] = w0[c*27 + tap];
    }
    __syncthreads();
    int v = blockIdx.x*256 + threadIdx.x;
    int b = v / VOL, s = v % VOL;
    int z = s / 9216, y = (s / 96) % 96, x = s % 96;
    const float* p = data + (size_t)b * VOL;
    float acc[32];
    #pragma unroll
    for (int q = 0; q < 32; q++) acc[q] = 0.f;
    #pragma unroll
    for (int dz = 0; dz < 3; dz++) {
        int zz = z + dz - 1; if ((unsigned)zz >= 96u) continue;
        #pragma unroll
        for (int dy = 0; dy < 3; dy++) {
            int yy = y + dy - 1; if ((unsigned)yy >= 96u) continue;
            #pragma unroll
            for (int dx = 0; dx < 3; dx++) {
                int xx = x + dx - 1; if ((unsigned)xx >= 96u) continue;
                float val = __ldg(p + ((size_t)zz*96 + yy)*96 + xx);
                const float4* wp = (const float4*)(ws + ((dz*3+dy)*3+dx)*32);
                #pragma unroll
                for (int q = 0; q < 8; q++) {
                    float4 ww = wp[q];
                    acc[q*4+0] = fmaf(val, ww.x, acc[q*4+0]);
                    acc[q*4+1] = fmaf(val, ww.y, acc[q*4+1]);
                    acc[q*4+2] = fmaf(val, ww.z, acc[q*4+2]);
                    acc[q*4+3] = fmaf(val, ww.w, acc[q*4+3]);
                }
            }
        }
    }
    float* o = raw + (size_t)v * 32;
    #pragma unroll
    for (int q = 0; q < 8; q++)
        ((float4*)o)[q] = make_float4(acc[q*4], acc[q*4+1], acc[q*4+2], acc[q*4+3]);
}

// ---------------- per-(b,c) stats over channels-last raw ----------------
__global__ void stats_kernel(const float* __restrict__ raw, float* __restrict__ ss) {
    const int b = blockIdx.y;
    const int c = threadIdx.x & 31;
    const int w = threadIdx.x >> 5;
    const float* p = raw + ((size_t)b*VOL + (size_t)blockIdx.x*8192)*32;
    float s = 0.f, q = 0.f;
    for (int v = w; v < 8192; v += 8) {
        float x = p[(size_t)v*32 + c];
        s += x; q = fmaf(x, x, q);
    }
    __shared__ float sh[2][8][32];
    sh[0][w][c] = s; sh[1][w][c] = q;
    __syncthreads();
    if (threadIdx.x < 32) {
        float ts = 0.f, tq = 0.f;
        #pragma unroll
        for (int i = 0; i < 8; i++) { ts += sh[0][i][threadIdx.x]; tq += sh[1][i][threadIdx.x]; }
        atomicAdd(&ss[(b*32 + threadIdx.x)*2 + 0], ts);
        atomicAdd(&ss[(b*32 + threadIdx.x)*2 + 1], tq);
    }
}

// ---------------- normalize + relu + bf16 hi/lo split into padded layout ----------------
__global__ void norm_split_kernel(const float* __restrict__ raw, const float* __restrict__ ss,
                                  __nv_bfloat16* __restrict__ padh, __nv_bfloat16* __restrict__ padl) {
    __shared__ float na_s[64], nb_s[64];
    if (threadIdx.x < 64) {
        float s = ss[threadIdx.x*2], q = ss[threadIdx.x*2+1];
        float mm = s * INV_V;
        float var = fmaxf(q * INV_V - mm*mm, 0.f);
        float rstd = rsqrtf(var + EPSN);
        na_s[threadIdx.x] = rstd; nb_s[threadIdx.x] = -mm * rstd;
    }
    __syncthreads();
    size_t pv = (size_t)blockIdx.x*256 + threadIdx.x;
    if (pv >= (size_t)BATCH*PVOX) return;
    int px = (int)(pv % PXD);
    size_t t1 = pv / PXD;
    int py = (int)(t1 % PYD);
    size_t t2 = t1 / PYD;
    int pz = (int)(t2 % PZD);
    int b  = (int)(t2 / PZD);

    uint32_t wh[16], wl[16];
    #pragma unroll
    for (int j = 0; j < 16; j++) { wh[j] = 0u; wl[j] = 0u; }

    if (px >= 1 && px <= 96 && py >= 1 && py <= 96 && pz >= 1 && pz <= 96) {
        const float* rp = raw + ((((size_t)b*96 + (pz-1))*96 + (py-1))*96 + (px-1))*32;
        const float* na = na_s + b*32;
        const float* nb = nb_s + b*32;
        #pragma unroll
        for (int j = 0; j < 16; j++) {
            float v0 = fmaxf(fmaf(rp[2*j],   na[2*j],   nb[2*j]),   0.f);
            float v1 = fmaxf(fmaf(rp[2*j+1], na[2*j+1], nb[2*j+1]), 0.f);
            __nv_bfloat16 h0 = __float2bfloat16(v0);
            __nv_bfloat16 h1 = __float2bfloat16(v1);
            __nv_bfloat16 l0 = __float2bfloat16(v0 - __bfloat162float(h0));
            __nv_bfloat16 l1 = __float2bfloat16(v1 - __bfloat162float(h1));
            __nv_bfloat162 ph2; ph2.x = h0; ph2.y = h1;
            __nv_bfloat162 pl2; pl2.x = l0; pl2.y = l1;
            wh[j] = *(uint32_t*)&ph2;
            wl[j] = *(uint32_t*)&pl2;
        }
    }
    uint4* oh = (uint4*)(padh + pv*32);
    uint4* ol = (uint4*)(padl + pv*32);
    #pragma unroll
    for (int q = 0; q < 4; q++) {
        oh[q] = make_uint4(wh[q*4], wh[q*4+1], wh[q*4+2], wh[q*4+3]);
        ol[q] = make_uint4(wl[q*4], wl[q*4+1], wl[q*4+2], wl[q*4+3]);
    }
}

// ---------------- warp-MMA implicit-GEMM conv 32->32 (bf16 hi/lo, 3 passes) ----------------
// Block = 384 thr = 12 warps = 2 output rows; warp = 16 voxels x 32 co.
// A fragments loaded direct from global; B via ldmatrix from SMEM.
__global__ void __launch_bounds__(384, 1)
conv_mma_kernel(const __nv_bfloat16* __restrict__ padh,
                const __nv_bfloat16* __restrict__ padl,
                const __nv_bfloat16* __restrict__ wp,
                float* __restrict__ raw)
{
    extern __shared__ __nv_bfloat16 bsm[];           // 18 * BTILE
    const int tid = threadIdx.x;
    {   // stage this layer's 18 weight tiles (117 KB)
        const uint4* s = (const uint4*)wp;
        uint4* d = (uint4*)bsm;
        for (int i = tid; i < 18*BTILE/8; i += 384) d[i] = s[i];
    }
    __syncthreads();

    const uint32_t bbase0 = smem_u32(bsm);
    const int lane = tid & 31;
    const int warp = tid >> 5;
    const int rowsel = warp / 6;
    const int x0 = (warp % 6) * 16;
    const int tg  = lane & 3;
    const int gid = lane >> 2;
    // ldmatrix lane->row mapping for B (two n-tiles + both k-halves per x4)
    const int bg = lane >> 3;
    const int b_n  = ((bg >> 1) << 3) + (lane & 7);   // 0..15
    const int b_kh = bg & 1;

    for (int t = blockIdx.x; t < BATCH*96*48; t += gridDim.x) {
        const int b  = t / (96*48);
        const int rm = t % (96*48);
        const int z  = rm / 48;
        const int y  = (rm % 48)*2 + rowsel;

        float dacc[4][4];
        #pragma unroll
        for (int nt = 0; nt < 4; nt++)
            #pragma unroll
            for (int j = 0; j < 4; j++) dacc[nt][j] = 0.f;

        #pragma unroll 1
        for (int r = 0; r < 9; r++) {
            const int dz = r / 3, dy = r % 3;
            const size_t rowb = (((size_t)(b*PZD + z + dz))*PYD + (y + dy))*PXD;
            const uint32_t bb_h = bbase0 + (uint32_t)(r*2 + 0)*(BTILE*2);
            const uint32_t bb_l = bbase0 + (uint32_t)(r*2 + 1)*(BTILE*2);

            #pragma unroll
            for (int kc = 0; kc < 6; kc++) {
                const int dx = kc >> 1;
                const int j0 = (kc & 1)*16;
                const size_t ab = (rowb + (size_t)(x0 + gid + dx))*32 + j0 + tg*2;
                uint32_t ah0 = *(const uint32_t*)(padh + ab);
                uint32_t ah1 = *(const uint32_t*)(padh + ab + 256);
                uint32_t ah2 = *(const uint32_t*)(padh + ab + 8);
                uint32_t ah3 = *(const uint32_t*)(padh + ab + 264);
                uint32_t al0 = *(const uint32_t*)(padl + ab);
                uint32_t al1 = *(const uint32_t*)(padl + ab + 256);
                uint32_t al2 = *(const uint32_t*)(padl + ab + 8);
                uint32_t al3 = *(const uint32_t*)(padl + ab + 264);

                const uint32_t ko = (uint32_t)(kc*32 + b_kh*16);   // bytes within row
                const uint32_t ro = (uint32_t)b_n * (BSTRIDE*2) + ko;
                uint32_t bh[8], bl[8];
                LDSM_X4(bh[0],bh[1],bh[2],bh[3], bb_h + ro);
                LDSM_X4(bh[4],bh[5],bh[6],bh[7], bb_h + ro + 16u*(BSTRIDE*2));
                LDSM_X4(bl[0],bl[1],bl[2],bl[3], bb_l + ro);
                LDSM_X4(bl[4],bl[5],bl[6],bl[7], bb_l + ro + 16u*(BSTRIDE*2));

                #pragma unroll
                for (int nt = 0; nt < 4; nt++) {
                    MMA16816(dacc[nt], ah0,ah1,ah2,ah3, bh[nt*2], bh[nt*2+1]);
                    MMA16816(dacc[nt], al0,al1,al2,al3, bh[nt*2], bh[nt*2+1]);
                    MMA16816(dacc[nt], ah0,ah1,ah2,ah3, bl[nt*2], bl[nt*2+1]);
                }
            }
        }

        float* orow = raw + ((size_t)b*VOL + (size_t)z*9216 + (size_t)y*96 + x0)*32;
        #pragma unroll
        for (int nt = 0; nt < 4; nt++) {
            const int col = nt*8 + tg*2;
            *(float2*)(orow + (size_t)gid*32 + col)      = make_float2(dacc[nt][0], dacc[nt][1]);
            *(float2*)(orow + (size_t)(gid+8)*32 + col)  = make_float2(dacc[nt][2], dacc[nt][3]);
        }
    }
}

// ---------------- mask row sums ----------------
__global__ void masksum_kernel(const float* __restrict__ mask) {
    const int r = blockIdx.y;
    const float4* p = (const float4*)(mask + (size_t)r * VOL) + (size_t)blockIdx.x * 8192;
    float s = 0.f;
    for (int i = threadIdx.x; i < 8192; i += 256) {
        float4 v = p[i];
        s += v.x + v.y + v.z + v.w;
    }
    #pragma unroll
    for (int o = 16; o; o >>= 1) s += __shfl_xor_sync(0xffffffffu, s, o);
    __shared__ float sh[8];
    if ((threadIdx.x & 31) == 0) sh[threadIdx.x >> 5] = s;
    __syncthreads();
    if (threadIdx.x == 0) {
        float ts = 0.f;
        #pragma unroll
        for (int i = 0; i < 8; i++) ts += sh[i];
        atomicAdd(&g_msum[r], ts);
    }
}

// ---------------- masked pooling over channels-last raw (inline norm) ----------------
#define PCHUNK 64
__global__ void __launch_bounds__(256, 2)
pool_kernel(const float* __restrict__ raw, const float* __restrict__ ss,
            const float* __restrict__ mask)
{
    __shared__ float e_s[PCHUNK][68];
    __shared__ float m_s[PCHUNK*100];
    __shared__ float na_s[64], nb_s[64];

    const int tid = threadIdx.x;
    if (tid < 64) {
        float s = ss[tid*2], q = ss[tid*2+1];
        float mm = s * INV_V;
        float var = fmaxf(q * INV_V - mm*mm, 0.f);
        float rstd = rsqrtf(var + EPSN);
        na_s[tid] = rstd; nb_s[tid] = -mm * rstd;
    }
    __syncthreads();

    const int rg  = tid & 31;
    const int bcg = tid >> 5;

    ull acc[8][2];
    #pragma unroll
    for (int k = 0; k < 8; k++) { acc[k][0] = 0ULL; acc[k][1] = 0ULL; }

    const int nchunks = VOL / PCHUNK;
    for (int chn = blockIdx.x; chn < nchunks; chn += gridDim.x) {
        const int v0 = chn * PCHUNK;
        __syncthreads();
        for (int i = tid; i < 2*PCHUNK*8; i += 256) {
            int bb = i / (PCHUNK*8);
            int rem = i % (PCHUNK*8);
            int v = rem / 8, cq = rem % 8;
            float4 f = *(const float4*)(raw + ((size_t)bb*VOL + v0 + v)*32 + cq*4);
            int bc = bb*32 + cq*4;
            e_s[v][bc+0] = fmaxf(fmaf(f.x, na_s[bc+0], nb_s[bc+0]), 0.f);
            e_s[v][bc+1] = fmaxf(fmaf(f.y, na_s[bc+1], nb_s[bc+1]), 0.f);
            e_s[v][bc+2] = fmaxf(fmaf(f.z, na_s[bc+2], nb_s[bc+2]), 0.f);
            e_s[v][bc+3] = fmaxf(fmaf(f.w, na_s[bc+3], nb_s[bc+3]), 0.f);
        }
        for (int i = tid; i < 100*PCHUNK/4; i += 256) {
            int r = i / (PCHUNK/4), vq = i % (PCHUNK/4);
            float4 f = *(const float4*)(mask + (size_t)r*VOL + v0 + vq*4);
            m_s[(vq*4+0)*100 + r] = f.x;
            m_s[(vq*4+1)*100 + r] = f.y;
            m_s[(vq*4+2)*100 + r] = f.z;
            m_s[(vq*4+3)*100 + r] = f.w;
        }
        __syncthreads();
        for (int v = 0; v < PCHUNK; v++) {
            float mv0 = m_s[v*100 + rg];
            float mv1 = m_s[v*100 + rg + 32];
            float mv2 = m_s[v*100 + rg + 64];
            float mv3 = (rg < 4) ? m_s[v*100 + rg + 96] : 0.f;
            ull mp01 = packpair(mv0, mv1);
            ull mp23 = packpair(mv2, mv3);
            #pragma unroll
            for (int k = 0; k < 8; k++) {
                ull ee = pack2(e_s[v][bcg*8 + k]);
                fma2(acc[k][0], ee, mp01);
                fma2(acc[k][1], ee, mp23);
            }
        }
    }
    #pragma unroll
    for (int k = 0; k < 8; k++) {
        int bc = bcg*8 + k;
        int bb = bc >> 5, c = bc & 31;
        float a0, a1, a2, a3;
        unpack2(a0, a1, acc[k][0]);
        unpack2(a2, a3, acc[k][1]);
        atomicAdd(&g_roi[(bb*NRR + rg     )*CH + c], a0);
        atomicAdd(&g_roi[(bb*NRR + rg + 32)*CH + c], a1);
        atomicAdd(&g_roi[(bb*NRR + rg + 64)*CH + c], a2);
        if (rg < 4)
            atomicAdd(&g_roi[(bb*NRR + rg + 96)*CH + c], a3);
    }
}

// ---------------- per-ROI MLPs ----------------
__global__ void mlp_kernel(const float* __restrict__ sw1, const float* __restrict__ sb1,
                           const float* __restrict__ sw2, const float* __restrict__ sb2,
                           const float* __restrict__ pw1, const float* __restrict__ pb1,
                           const float* __restrict__ pw2, const float* __restrict__ pb2,
                           float* __restrict__ out)
{
    const int b = blockIdx.x / NRR;
    const int r = blockIdx.x % NRR;
    const int tid = threadIdx.x;
    __shared__ float roi_s[32], h_s[64], sf_s[32], h2_s[256];

    if (tid < 32)
        roi_s[tid] = g_roi[(b*NRR + r)*CH + tid] / g_msum[r];
    __syncthreads();
    if (tid < 64) {
        float s = sb1[r*64 + tid];
        #pragma unroll
        for (int c = 0; c < 32; c++)
            s = fmaf(roi_s[c], sw1[(r*CH + c)*64 + tid], s);
        h_s[tid] = fmaxf(s, 0.f);
    }
    __syncthreads();
    if (tid < 32) {
        float s = sb2[r*CH + tid];
        #pragma unroll
        for (int j = 0; j < 64; j++)
            s = fmaf(h_s[j], sw2[(r*64 + j)*CH + tid], s);
        sf_s[tid] = roi_s[tid] / (1.f + expf(-s));
    }
    __syncthreads();
    {
        float s = pb1[r*RHN + tid];
        #pragma unroll
        for (int c = 0; c < 32; c++)
            s = fmaf(sf_s[c], pw1[(r*CH + c)*RHN + tid], s);
        h2_s[tid] = fmaxf(s, 0.f);
    }
    __syncthreads();
    if (tid < 128) {
        float s = pb2[r*REN + tid];
        for (int k = 0; k < 256; k++)
            s = fmaf(h2_s[k], pw2[(r*RHN + k)*REN + tid], s);
        out[(b*NRR + r)*REN + tid] = s;
    }
}

// ---------------- launch ----------------
extern "C" void kernel_launch(void* const* d_in, const int* in_sizes, int n_in,
                              void* d_out, int out_size)
{
    const float* data    = (const float*)d_in[0];
    const float* mask    = (const float*)d_in[1];
    const float* conv0_w = (const float*)d_in[2];
    const float* convk_w = (const float*)d_in[4];
    const float* sw1 = (const float*)d_in[6];
    const float* sb1 = (const float*)d_in[7];
    const float* sw2 = (const float*)d_in[8];
    const float* sb2 = (const float*)d_in[9];
    const float* pw1 = (const float*)d_in[10];
    const float* pb1 = (const float*)d_in[11];
    const float* pw2 = (const float*)d_in[12];
    const float* pb2 = (const float*)d_in[13];
    float* out = (float*)d_out;

    float* raw = nullptr;  cudaGetSymbolAddress((void**)&raw,  g_raw);
    __nv_bfloat16* padh = nullptr; cudaGetSymbolAddress((void**)&padh, g_padh);
    __nv_bfloat16* padl = nullptr; cudaGetSymbolAddress((void**)&padl, g_padl);
    __nv_bfloat16* wpre = nullptr; cudaGetSymbolAddress((void**)&wpre, g_wprep);
    float* ssum = nullptr; cudaGetSymbolAddress((void**)&ssum, g_ssum);
    float* ss0 = ssum + 0*BATCH*CH*2;
    float* ss1 = ssum + 1*BATCH*CH*2;
    float* ss2 = ssum + 2*BATCH*CH*2;
    float* ss3 = ssum + 3*BATCH*CH*2;

    const int SMEMB = 18*BTILE*2;   // 119808 B
    cudaFuncSetAttribute(conv_mma_kernel, cudaFuncAttributeMaxDynamicSharedMemorySize, SMEMB);

    const dim3 sgrid(108, 2);
    const int nsb = (int)(((size_t)BATCH*PVOX + 255) / 256);
    const size_t LW = (size_t)9*2*BTILE;   // weight elems per layer

    init_kernel<<<1, 256>>>();
    wprep_kernel<<<27, 256>>>(convk_w);

    conv0_kernel<<<BATCH*VOL/256, 256>>>(data, conv0_w, raw);
    stats_kernel<<<sgrid, 256>>>(raw, ss0);
    norm_split_kernel<<<nsb, 256>>>(raw, ss0, padh, padl);

    conv_mma_kernel<<<148, 384, SMEMB>>>(padh, padl, wpre + 0*LW, raw);
    stats_kernel<<<sgrid, 256>>>(raw, ss1);
    norm_split_kernel<<<nsb, 256>>>(raw, ss1, padh, padl);

    conv_mma_kernel<<<148, 384, SMEMB>>>(padh, padl, wpre + 1*LW, raw);
    stats_kernel<<<sgrid, 256>>>(raw, ss2);
    norm_split_kernel<<<nsb, 256>>>(raw, ss2, padh, padl);

    conv_mma_kernel<<<148, 384, SMEMB>>>(padh, padl, wpre + 2*LW, raw);
    stats_kernel<<<sgrid, 256>>>(raw, ss3);

    masksum_kernel<<<dim3(27, 100), 256>>>(mask);
    pool_kernel<<<296, 256>>>(raw, ss3, mask);

    mlp_kernel<<<BATCH*NRR, 256>>>(sw1, sb1, sw2, sb2, pw1, pb1, pw2, pb2, out);
}

// round 7
// speedup vs baseline: 2.4882x; 1.0462x over previous
#include <cuda_runtime.h>
#include <cuda_bf16.h>
#include <math.h>
#include <stdint.h>

#define BATCH 2
#define CH    32
#define VOL   (96*96*96)
#define NRR   100
#define RHN   256
#define REN   128
#define INV_V (1.0f/884736.0f)
#define EPSN  1e-5f
#define PXD 132
#define PYD 98
#define PZD 98
#define PVOX (PZD*PYD*PXD)
#define BSTRIDE 104
#define BTILE   (32*BSTRIDE)

typedef unsigned long long ull;

// ---------------- f32x2 helpers ----------------
__device__ __forceinline__ void fma2(ull& d, ull a, ull b) {
    asm("fma.rn.f32x2 %0, %1, %2, %3;" : "=l"(d) : "l"(a), "l"(b), "l"(d));
}
__device__ __forceinline__ ull pack2(float v) {
    ull r; asm("mov.b64 %0, {%1, %1};" : "=l"(r) : "f"(v)); return r;
}
__device__ __forceinline__ ull packpair(float lo, float hi) {
    ull r; asm("mov.b64 %0, {%1, %2};" : "=l"(r) : "f"(lo), "f"(hi)); return r;
}
__device__ __forceinline__ void unpack2(float& lo, float& hi, ull a) {
    asm("mov.b64 {%0, %1}, %2;" : "=f"(lo), "=f"(hi) : "l"(a));
}

// ---------------- warp MMA helpers ----------------
__device__ __forceinline__ uint32_t smem_u32(const void* p) {
    uint32_t a;
    asm("{ .reg .u64 t; cvta.to.shared.u64 t, %1; cvt.u32.u64 %0, t; }" : "=r"(a) : "l"(p));
    return a;
}
#define LDSM_X4(r0,r1,r2,r3,addr) \
    asm volatile("ldmatrix.sync.aligned.m8n8.x4.shared.b16 {%0,%1,%2,%3}, [%4];" \
        : "=r"(r0),"=r"(r1),"=r"(r2),"=r"(r3) : "r"(addr))
#define MMA16816(d, a0,a1,a2,a3, b0,b1) \
    asm volatile("mma.sync.aligned.m16n8k16.row.col.f32.bf16.bf16.f32 " \
        "{%0,%1,%2,%3}, {%4,%5,%6,%7}, {%8,%9}, {%0,%1,%2,%3};" \
        : "+f"((d)[0]),"+f"((d)[1]),"+f"((d)[2]),"+f"((d)[3]) \
        : "r"(a0),"r"(a1),"r"(a2),"r"(a3), "r"(b0),"r"(b1))

// ---------------- scratch ----------------
__device__ float g_raw[(size_t)BATCH*VOL*CH];
__device__ __nv_bfloat16 g_padh[(size_t)BATCH*PVOX*CH];     // borders stay zero forever
__device__ __nv_bfloat16 g_padl[(size_t)BATCH*PVOX*CH];
__device__ __align__(16) __nv_bfloat16 g_wprep[3*9*2*BTILE];
__device__ float g_ssum[4][BATCH*CH][2];
__device__ float g_roi [BATCH*NRR*CH];
__device__ float g_msum[NRR];

__global__ void init_kernel() {
    int t = threadIdx.x;
    float* ss = &g_ssum[0][0][0];
    for (int i = t; i < 4*BATCH*CH*2; i += 256) ss[i] = 0.f;
    for (int i = t; i < BATCH*NRR*CH; i += 256) g_roi[i] = 0.f;
    for (int i = t; i < NRR; i += 256) g_msum[i] = 0.f;
}

// ---------------- weight prep ----------------
__global__ void wprep_kernel(const float* __restrict__ convk_w) {
    const int L = blockIdx.x / 9;
    const int r = blockIdx.x % 9;
    const int dz = r / 3, dy = r % 3;
    __nv_bfloat16* bh = g_wprep + ((size_t)(L*9 + r)*2 + 0)*BTILE;
    __nv_bfloat16* bl = bh + BTILE;
    for (int i = threadIdx.x; i < 32*BSTRIDE; i += 256) {
        int co = i / BSTRIDE, k = i % BSTRIDE;
        float wv = 0.f;
        if (k < 96) {
            int dx = k >> 5, ci = k & 31;
            wv = convk_w[(size_t)((L*32 + co)*32 + ci)*27 + (dz*3 + dy)*3 + dx];
        }
        __nv_bfloat16 h = __float2bfloat16(wv);
        bh[i] = h;
        bl[i] = __float2bfloat16(wv - __bfloat162float(h));
    }
}

// ---------------- conv0: 1->32 direct, channels-last ----------------
__global__ void conv0_kernel(const float* __restrict__ data,
                             const float* __restrict__ w0,
                             float* __restrict__ raw) {
    __shared__ float ws[27*32];
    for (int i = threadIdx.x; i < 864; i += 256) {
        int tap = i / 32, c = i % 32;
        ws[tap*32 + c] = w0[c*27 + tap];
    }
    __syncthreads();
    int v = blockIdx.x*256 + threadIdx.x;
    int b = v / VOL, s = v % VOL;
    int z = s / 9216, y = (s / 96) % 96, x = s % 96;
    const float* p = data + (size_t)b * VOL;
    float acc[32];
    #pragma unroll
    for (int q = 0; q < 32; q++) acc[q] = 0.f;
    #pragma unroll
    for (int dz = 0; dz < 3; dz++) {
        int zz = z + dz - 1; if ((unsigned)zz >= 96u) continue;
        #pragma unroll
        for (int dy = 0; dy < 3; dy++) {
            int yy = y + dy - 1; if ((unsigned)yy >= 96u) continue;
            #pragma unroll
            for (int dx = 0; dx < 3; dx++) {
                int xx = x + dx - 1; if ((unsigned)xx >= 96u) continue;
                float val = __ldg(p + ((size_t)zz*96 + yy)*96 + xx);
                const float4* wp = (const float4*)(ws + ((dz*3+dy)*3+dx)*32);
                #pragma unroll
                for (int q = 0; q < 8; q++) {
                    float4 ww = wp[q];
                    acc[q*4+0] = fmaf(val, ww.x, acc[q*4+0]);
                    acc[q*4+1] = fmaf(val, ww.y, acc[q*4+1]);
                    acc[q*4+2] = fmaf(val, ww.z, acc[q*4+2]);
                    acc[q*4+3] = fmaf(val, ww.w, acc[q*4+3]);
                }
            }
        }
    }
    float* o = raw + (size_t)v * 32;
    #pragma unroll
    for (int q = 0; q < 8; q++)
        ((float4*)o)[q] = make_float4(acc[q*4], acc[q*4+1], acc[q*4+2], acc[q*4+3]);
}

// ---------------- coalesced stats (conv0 output only) ----------------
__global__ void stats0_kernel(const float* __restrict__ raw, float* __restrict__ ss) {
    const int b = blockIdx.y;
    const int tid = threadIdx.x;
    const int lane = tid & 31;
    const float4* p = (const float4*)(raw + ((size_t)b*VOL + (size_t)blockIdx.x*2048)*32);
    float s[4] = {0,0,0,0}, q[4] = {0,0,0,0};
    for (int it = 0; it < 64; it++) {
        float4 f = p[it*256 + tid];
        s[0] += f.x; q[0] = fmaf(f.x, f.x, q[0]);
        s[1] += f.y; q[1] = fmaf(f.y, f.y, q[1]);
        s[2] += f.z; q[2] = fmaf(f.z, f.z, q[2]);
        s[3] += f.w; q[3] = fmaf(f.w, f.w, q[3]);
    }
    // lanes with same lane%8 hold same 4 channels (cq = lane%8)
    #pragma unroll
    for (int o = 8; o < 32; o <<= 1) {
        #pragma unroll
        for (int j = 0; j < 4; j++) {
            s[j] += __shfl_xor_sync(0xffffffffu, s[j], o);
            q[j] += __shfl_xor_sync(0xffffffffu, q[j], o);
        }
    }
    __shared__ float sa[32], qa[32];
    if (tid < 32) { sa[tid] = 0.f; qa[tid] = 0.f; }
    __syncthreads();
    if (lane < 8) {
        #pragma unroll
        for (int j = 0; j < 4; j++) {
            atomicAdd(&sa[lane*4 + j], s[j]);
            atomicAdd(&qa[lane*4 + j], q[j]);
        }
    }
    __syncthreads();
    if (tid < 32) {
        atomicAdd(&ss[(b*32 + tid)*2 + 0], sa[tid]);
        atomicAdd(&ss[(b*32 + tid)*2 + 1], qa[tid]);
    }
}

// ---------------- normalize + relu + bf16 hi/lo split (interior only) ----------------
__global__ void norm_split_kernel(const float* __restrict__ raw, const float* __restrict__ ss,
                                  __nv_bfloat16* __restrict__ padh, __nv_bfloat16* __restrict__ padl) {
    __shared__ float na_s[64], nb_s[64];
    if (threadIdx.x < 64) {
        float s = ss[threadIdx.x*2], q = ss[threadIdx.x*2+1];
        float mm = s * INV_V;
        float var = fmaxf(q * INV_V - mm*mm, 0.f);
        float rstd = rsqrtf(var + EPSN);
        na_s[threadIdx.x] = rstd; nb_s[threadIdx.x] = -mm * rstd;
    }
    __syncthreads();
    int v = blockIdx.x*256 + threadIdx.x;
    int b = v / VOL, sidx = v % VOL;
    int z = sidx / 9216, y = (sidx / 96) % 96, x = sidx % 96;
    size_t pv = (((size_t)(b*PZD + z + 1))*PYD + (y + 1))*PXD + (x + 1);

    const float* rp = raw + (size_t)v * 32;
    const float* na = na_s + b*32;
    const float* nb = nb_s + b*32;
    uint32_t wh[16], wl[16];
    #pragma unroll
    for (int j = 0; j < 16; j++) {
        float v0 = fmaxf(fmaf(rp[2*j],   na[2*j],   nb[2*j]),   0.f);
        float v1 = fmaxf(fmaf(rp[2*j+1], na[2*j+1], nb[2*j+1]), 0.f);
        __nv_bfloat16 h0 = __float2bfloat16(v0);
        __nv_bfloat16 h1 = __float2bfloat16(v1);
        __nv_bfloat16 l0 = __float2bfloat16(v0 - __bfloat162float(h0));
        __nv_bfloat16 l1 = __float2bfloat16(v1 - __bfloat162float(h1));
        __nv_bfloat162 ph2; ph2.x = h0; ph2.y = h1;
        __nv_bfloat162 pl2; pl2.x = l0; pl2.y = l1;
        wh[j] = *(uint32_t*)&ph2;
        wl[j] = *(uint32_t*)&pl2;
    }
    uint4* oh = (uint4*)(padh + pv*32);
    uint4* ol = (uint4*)(padl + pv*32);
    #pragma unroll
    for (int q = 0; q < 4; q++) {
        oh[q] = make_uint4(wh[q*4], wh[q*4+1], wh[q*4+2], wh[q*4+3]);
        ol[q] = make_uint4(wl[q*4], wl[q*4+1], wl[q*4+2], wl[q*4+3]);
    }
}

// ---------------- warp-MMA conv 32->32 + fused stats ----------------
// 576 threads = 18 warps = 3 output rows; warp = 16 voxels x 32 co.
__global__ void __launch_bounds__(576, 1)
conv_mma_kernel(const __nv_bfloat16* __restrict__ padh,
                const __nv_bfloat16* __restrict__ padl,
                const __nv_bfloat16* __restrict__ wp,
                float* __restrict__ raw,
                float* __restrict__ ss)
{
    extern __shared__ __nv_bfloat16 bsm[];
    __shared__ float s_sm[64], q_sm[64];
    const int tid = threadIdx.x;
    {
        const uint4* s = (const uint4*)wp;
        uint4* d = (uint4*)bsm;
        for (int i = tid; i < 18*BTILE/8; i += 576) d[i] = s[i];
    }
    if (tid < 64) { s_sm[tid] = 0.f; q_sm[tid] = 0.f; }
    __syncthreads();

    const uint32_t bbase0 = smem_u32(bsm);
    const int lane = tid & 31;
    const int warp = tid >> 5;
    const int rowsel = warp / 6;          // 0..2
    const int x0 = (warp % 6) * 16;
    const int tg  = lane & 3;
    const int gid = lane >> 2;
    const int bg = lane >> 3;
    const int b_n  = ((bg >> 1) << 3) + (lane & 7);
    const int b_kh = bg & 1;

    for (int t = blockIdx.x; t < BATCH*96*32; t += gridDim.x) {
        const int b  = t / (96*32);
        const int rm = t % (96*32);
        const int z  = rm / 32;
        const int y  = (rm % 32)*3 + rowsel;

        float dacc[4][4];
        #pragma unroll
        for (int nt = 0; nt < 4; nt++)
            #pragma unroll
            for (int j = 0; j < 4; j++) dacc[nt][j] = 0.f;

        #pragma unroll 1
        for (int r = 0; r < 9; r++) {
            const int dz = r / 3, dy = r % 3;
            const size_t rowb = (((size_t)(b*PZD + z + dz))*PYD + (y + dy))*PXD;
            const uint32_t bb_h = bbase0 + (uint32_t)(r*2 + 0)*(BTILE*2);
            const uint32_t bb_l = bbase0 + (uint32_t)(r*2 + 1)*(BTILE*2);

            #pragma unroll
            for (int kc = 0; kc < 6; kc++) {
                const int dx = kc >> 1;
                const int j0 = (kc & 1)*16;
                const size_t ab = (rowb + (size_t)(x0 + gid + dx))*32 + j0 + tg*2;
                uint32_t ah0 = *(const uint32_t*)(padh + ab);
                uint32_t ah1 = *(const uint32_t*)(padh + ab + 256);
                uint32_t ah2 = *(const uint32_t*)(padh + ab + 8);
                uint32_t ah3 = *(const uint32_t*)(padh + ab + 264);
                uint32_t al0 = *(const uint32_t*)(padl + ab);
                uint32_t al1 = *(const uint32_t*)(padl + ab + 256);
                uint32_t al2 = *(const uint32_t*)(padl + ab + 8);
                uint32_t al3 = *(const uint32_t*)(padl + ab + 264);

                const uint32_t ko = (uint32_t)(kc*32 + b_kh*16);
                const uint32_t ro = (uint32_t)b_n * (BSTRIDE*2) + ko;
                uint32_t bh[8], bl[8];
                LDSM_X4(bh[0],bh[1],bh[2],bh[3], bb_h + ro);
                LDSM_X4(bh[4],bh[5],bh[6],bh[7], bb_h + ro + 16u*(BSTRIDE*2));
                LDSM_X4(bl[0],bl[1],bl[2],bl[3], bb_l + ro);
                LDSM_X4(bl[4],bl[5],bl[6],bl[7], bb_l + ro + 16u*(BSTRIDE*2));

                #pragma unroll
                for (int nt = 0; nt < 4; nt++) {
                    MMA16816(dacc[nt], ah0,ah1,ah2,ah3, bh[nt*2], bh[nt*2+1]);
                    MMA16816(dacc[nt], al0,al1,al2,al3, bh[nt*2], bh[nt*2+1]);
                    MMA16816(dacc[nt], ah0,ah1,ah2,ah3, bl[nt*2], bl[nt*2+1]);
                }
            }
        }

        float* orow = raw + ((size_t)b*VOL + (size_t)z*9216 + (size_t)y*96 + x0)*32;
        #pragma unroll
        for (int nt = 0; nt < 4; nt++) {
            const int col = nt*8 + tg*2;
            *(float2*)(orow + (size_t)gid*32 + col)      = make_float2(dacc[nt][0], dacc[nt][1]);
            *(float2*)(orow + (size_t)(gid+8)*32 + col)  = make_float2(dacc[nt][2], dacc[nt][3]);
        }

        // fused stats: per-channel sum & sumsq over this warp's 16 voxels
        float sv[8], qv[8];
        #pragma unroll
        for (int nt = 0; nt < 4; nt++) {
            sv[nt*2+0] = dacc[nt][0] + dacc[nt][2];
            sv[nt*2+1] = dacc[nt][1] + dacc[nt][3];
            qv[nt*2+0] = fmaf(dacc[nt][0], dacc[nt][0], dacc[nt][2]*dacc[nt][2]);
            qv[nt*2+1] = fmaf(dacc[nt][1], dacc[nt][1], dacc[nt][3]*dacc[nt][3]);
        }
        #pragma unroll
        for (int o = 4; o < 32; o <<= 1) {
            #pragma unroll
            for (int j = 0; j < 8; j++) {
                sv[j] += __shfl_xor_sync(0xffffffffu, sv[j], o);
                qv[j] += __shfl_xor_sync(0xffffffffu, qv[j], o);
            }
        }
        if (gid == 0) {
            #pragma unroll
            for (int nt = 0; nt < 4; nt++) {
                int c = b*32 + nt*8 + tg*2;
                atomicAdd(&s_sm[c],   sv[nt*2+0]);
                atomicAdd(&s_sm[c+1], sv[nt*2+1]);
                atomicAdd(&q_sm[c],   qv[nt*2+0]);
                atomicAdd(&q_sm[c+1], qv[nt*2+1]);
            }
        }
    }
    __syncthreads();
    if (tid < 64) {
        atomicAdd(&ss[tid*2 + 0], s_sm[tid]);
        atomicAdd(&ss[tid*2 + 1], q_sm[tid]);
    }
}

// ---------------- pool + fused mask row-sums ----------------
#define PCHUNK 64
__global__ void __launch_bounds__(256, 2)
pool_kernel(const float* __restrict__ raw, const float* __restrict__ ss,
            const float* __restrict__ mask)
{
    __shared__ float e_s[PCHUNK][68];
    __shared__ float m_s[PCHUNK*100];
    __shared__ float na_s[64], nb_s[64];

    const int tid = threadIdx.x;
    if (tid < 64) {
        float s = ss[tid*2], q = ss[tid*2+1];
        float mm = s * INV_V;
        float var = fmaxf(q * INV_V - mm*mm, 0.f);
        float rstd = rsqrtf(var + EPSN);
        na_s[tid] = rstd; nb_s[tid] = -mm * rstd;
    }
    __syncthreads();

    const int rg  = tid & 31;
    const int bcg = tid >> 5;

    ull acc[8][2];
    #pragma unroll
    for (int k = 0; k < 8; k++) { acc[k][0] = 0ULL; acc[k][1] = 0ULL; }
    float ms0 = 0.f, ms1 = 0.f, ms2 = 0.f, ms3 = 0.f;

    const int nchunks = VOL / PCHUNK;
    for (int chn = blockIdx.x; chn < nchunks; chn += gridDim.x) {
        const int v0 = chn * PCHUNK;
        __syncthreads();
        for (int i = tid; i < 2*PCHUNK*8; i += 256) {
            int bb = i / (PCHUNK*8);
            int rem = i % (PCHUNK*8);
            int v = rem / 8, cq = rem % 8;
            float4 f = *(const float4*)(raw + ((size_t)bb*VOL + v0 + v)*32 + cq*4);
            int bc = bb*32 + cq*4;
            e_s[v][bc+0] = fmaxf(fmaf(f.x, na_s[bc+0], nb_s[bc+0]), 0.f);
            e_s[v][bc+1] = fmaxf(fmaf(f.y, na_s[bc+1], nb_s[bc+1]), 0.f);
            e_s[v][bc+2] = fmaxf(fmaf(f.z, na_s[bc+2], nb_s[bc+2]), 0.f);
            e_s[v][bc+3] = fmaxf(fmaf(f.w, na_s[bc+3], nb_s[bc+3]), 0.f);
        }
        for (int i = tid; i < 100*PCHUNK/4; i += 256) {
            int r = i / (PCHUNK/4), vq = i % (PCHUNK/4);
            float4 f = *(const float4*)(mask + (size_t)r*VOL + v0 + vq*4);
            m_s[(vq*4+0)*100 + r] = f.x;
            m_s[(vq*4+1)*100 + r] = f.y;
            m_s[(vq*4+2)*100 + r] = f.z;
            m_s[(vq*4+3)*100 + r] = f.w;
        }
        __syncthreads();
        for (int v = 0; v < PCHUNK; v++) {
            float mv0 = m_s[v*100 + rg];
            float mv1 = m_s[v*100 + rg + 32];
            float mv2 = m_s[v*100 + rg + 64];
            float mv3 = (rg < 4) ? m_s[v*100 + rg + 96] : 0.f;
            if (bcg == 0) { ms0 += mv0; ms1 += mv1; ms2 += mv2; ms3 += mv3; }
            ull mp01 = packpair(mv0, mv1);
            ull mp23 = packpair(mv2, mv3);
            #pragma unroll
            for (int k = 0; k < 8; k++) {
                ull ee = pack2(e_s[v][bcg*8 + k]);
                fma2(acc[k][0], ee, mp01);
                fma2(acc[k][1], ee, mp23);
            }
        }
    }
    #pragma unroll
    for (int k = 0; k < 8; k++) {
        int bc = bcg*8 + k;
        int bb = bc >> 5, c = bc & 31;
        float a0, a1, a2, a3;
        unpack2(a0, a1, acc[k][0]);
        unpack2(a2, a3, acc[k][1]);
        atomicAdd(&g_roi[(bb*NRR + rg     )*CH + c], a0);
        atomicAdd(&g_roi[(bb*NRR + rg + 32)*CH + c], a1);
        atomicAdd(&g_roi[(bb*NRR + rg + 64)*CH + c], a2);
        if (rg < 4)
            atomicAdd(&g_roi[(bb*NRR + rg + 96)*CH + c], a3);
    }
    if (bcg == 0) {
        atomicAdd(&g_msum[rg], ms0);
        atomicAdd(&g_msum[rg + 32], ms1);
        atomicAdd(&g_msum[rg + 64], ms2);
        if (rg < 4) atomicAdd(&g_msum[rg + 96], ms3);
    }
}

// ---------------- per-ROI MLPs ----------------
__global__ void mlp_kernel(const float* __restrict__ sw1, const float* __restrict__ sb1,
                           const float* __restrict__ sw2, const float* __restrict__ sb2,
                           const float* __restrict__ pw1, const float* __restrict__ pb1,
                           const float* __restrict__ pw2, const float* __restrict__ pb2,
                           float* __restrict__ out)
{
    const int b = blockIdx.x / NRR;
    const int r = blockIdx.x % NRR;
    const int tid = threadIdx.x;
    __shared__ float roi_s[32], h_s[64], sf_s[32], h2_s[256];

    if (tid < 32)
        roi_s[tid] = g_roi[(b*NRR + r)*CH + tid] / g_msum[r];
    __syncthreads();
    if (tid < 64) {
        float s = sb1[r*64 + tid];
        #pragma unroll
        for (int c = 0; c < 32; c++)
            s = fmaf(roi_s[c], sw1[(r*CH + c)*64 + tid], s);
        h_s[tid] = fmaxf(s, 0.f);
    }
    __syncthreads();
    if (tid < 32) {
        float s = sb2[r*CH + tid];
        #pragma unroll
        for (int j = 0; j < 64; j++)
            s = fmaf(h_s[j], sw2[(r*64 + j)*CH + tid], s);
        sf_s[tid] = roi_s[tid] / (1.f + expf(-s));
    }
    __syncthreads();
    {
        float s = pb1[r*RHN + tid];
        #pragma unroll
        for (int c = 0; c < 32; c++)
            s = fmaf(sf_s[c], pw1[(r*CH + c)*RHN + tid], s);
        h2_s[tid] = fmaxf(s, 0.f);
    }
    __syncthreads();
    if (tid < 128) {
        float s = pb2[r*REN + tid];
        for (int k = 0; k < 256; k++)
            s = fmaf(h2_s[k], pw2[(r*RHN + k)*REN + tid], s);
        out[(b*NRR + r)*REN + tid] = s;
    }
}

// ---------------- launch ----------------
extern "C" void kernel_launch(void* const* d_in, const int* in_sizes, int n_in,
                              void* d_out, int out_size)
{
    const float* data    = (const float*)d_in[0];
    const float* mask    = (const float*)d_in[1];
    const float* conv0_w = (const float*)d_in[2];
    const float* convk_w = (const float*)d_in[4];
    const float* sw1 = (const float*)d_in[6];
    const float* sb1 = (const float*)d_in[7];
    const float* sw2 = (const float*)d_in[8];
    const float* sb2 = (const float*)d_in[9];
    const float* pw1 = (const float*)d_in[10];
    const float* pb1 = (const float*)d_in[11];
    const float* pw2 = (const float*)d_in[12];
    const float* pb2 = (const float*)d_in[13];
    float* out = (float*)d_out;

    float* raw = nullptr;  cudaGetSymbolAddress((void**)&raw,  g_raw);
    __nv_bfloat16* padh = nullptr; cudaGetSymbolAddress((void**)&padh, g_padh);
    __nv_bfloat16* padl = nullptr; cudaGetSymbolAddress((void**)&padl, g_padl);
    __nv_bfloat16* wpre = nullptr; cudaGetSymbolAddress((void**)&wpre, g_wprep);
    float* ssum = nullptr; cudaGetSymbolAddress((void**)&ssum, g_ssum);
    float* ss0 = ssum + 0*BATCH*CH*2;
    float* ss1 = ssum + 1*BATCH*CH*2;
    float* ss2 = ssum + 2*BATCH*CH*2;
    float* ss3 = ssum + 3*BATCH*CH*2;

    const int SMEMB = 18*BTILE*2;
    cudaFuncSetAttribute(conv_mma_kernel, cudaFuncAttributeMaxDynamicSharedMemorySize, SMEMB);

    const int nnb = BATCH*VOL/256;
    const size_t LW = (size_t)9*2*BTILE;

    init_kernel<<<1, 256>>>();
    wprep_kernel<<<27, 256>>>(convk_w);

    conv0_kernel<<<nnb, 256>>>(data, conv0_w, raw);
    stats0_kernel<<<dim3(432, 2), 256>>>(raw, ss0);
    norm_split_kernel<<<nnb, 256>>>(raw, ss0, padh, padl);

    conv_mma_kernel<<<148, 576, SMEMB>>>(padh, padl, wpre + 0*LW, raw, ss1);
    norm_split_kernel<<<nnb, 256>>>(raw, ss1, padh, padl);

    conv_mma_kernel<<<148, 576, SMEMB>>>(padh, padl, wpre + 1*LW, raw, ss2);
    norm_split_kernel<<<nnb, 256>>>(raw, ss2, padh, padl);

    conv_mma_kernel<<<148, 576, SMEMB>>>(padh, padl, wpre + 2*LW, raw, ss3);

    pool_kernel<<<296, 256>>>(raw, ss3, mask);
    mlp_kernel<<<BATCH*NRR, 256>>>(sw1, sb1, sw2, sb2, pw1, pb1, pw2, pb2, out);
}

// round 8
// speedup vs baseline: 2.5363x; 1.0193x over previous
#include <cuda_runtime.h>
#include <cuda_bf16.h>
#include <math.h>
#include <stdint.h>

#define BATCH 2
#define CH    32
#define VOL   (96*96*96)
#define NRR   100
#define RHN   256
#define REN   128
#define INV_V (1.0f/884736.0f)
#define EPSN  1e-5f
#define PXD 132
#define PYD 98
#define PZD 98
#define PVOX (PZD*PYD*PXD)
#define BSTRIDE 104
#define BTILE   (32*BSTRIDE)

typedef unsigned long long ull;

// ---------------- warp MMA helpers ----------------
__device__ __forceinline__ uint32_t smem_u32(const void* p) {
    uint32_t a;
    asm("{ .reg .u64 t; cvta.to.shared.u64 t, %1; cvt.u32.u64 %0, t; }" : "=r"(a) : "l"(p));
    return a;
}
#define LDSM_X4(r0,r1,r2,r3,addr) \
    asm volatile("ldmatrix.sync.aligned.m8n8.x4.shared.b16 {%0,%1,%2,%3}, [%4];" \
        : "=r"(r0),"=r"(r1),"=r"(r2),"=r"(r3) : "r"(addr))
#define LDSM_X4_T(r0,r1,r2,r3,addr) \
    asm volatile("ldmatrix.sync.aligned.m8n8.x4.trans.shared.b16 {%0,%1,%2,%3}, [%4];" \
        : "=r"(r0),"=r"(r1),"=r"(r2),"=r"(r3) : "r"(addr))
#define MMA16816(d, a0,a1,a2,a3, b0,b1) \
    asm volatile("mma.sync.aligned.m16n8k16.row.col.f32.bf16.bf16.f32 " \
        "{%0,%1,%2,%3}, {%4,%5,%6,%7}, {%8,%9}, {%0,%1,%2,%3};" \
        : "+f"((d)[0]),"+f"((d)[1]),"+f"((d)[2]),"+f"((d)[3]) \
        : "r"(a0),"r"(a1),"r"(a2),"r"(a3), "r"(b0),"r"(b1))
#define CVTBF2(res, lo, hi) \
    asm("cvt.rn.bf16x2.f32 %0, %1, %2;" : "=r"(res) : "f"(hi), "f"(lo))

// ---------------- scratch ----------------
__device__ float g_raw[(size_t)BATCH*VOL*CH];
__device__ __nv_bfloat16 g_padh[(size_t)BATCH*PVOX*CH];     // borders stay zero forever
__device__ __nv_bfloat16 g_padl[(size_t)BATCH*PVOX*CH];
__device__ __align__(16) __nv_bfloat16 g_wprep[3*9*2*BTILE];
__device__ float g_ssum[4][BATCH*CH][2];
__device__ float g_roi [BATCH*NRR*CH];
__device__ float g_msum[NRR];

__global__ void init_kernel() {
    int t = threadIdx.x;
    float* ss = &g_ssum[0][0][0];
    for (int i = t; i < 4*BATCH*CH*2; i += 256) ss[i] = 0.f;
    for (int i = t; i < BATCH*NRR*CH; i += 256) g_roi[i] = 0.f;
    for (int i = t; i < NRR; i += 256) g_msum[i] = 0.f;
}

// ---------------- weight prep ----------------
__global__ void wprep_kernel(const float* __restrict__ convk_w) {
    const int L = blockIdx.x / 9;
    const int r = blockIdx.x % 9;
    const int dz = r / 3, dy = r % 3;
    __nv_bfloat16* bh = g_wprep + ((size_t)(L*9 + r)*2 + 0)*BTILE;
    __nv_bfloat16* bl = bh + BTILE;
    for (int i = threadIdx.x; i < 32*BSTRIDE; i += 256) {
        int co = i / BSTRIDE, k = i % BSTRIDE;
        float wv = 0.f;
        if (k < 96) {
            int dx = k >> 5, ci = k & 31;
            wv = convk_w[(size_t)((L*32 + co)*32 + ci)*27 + (dz*3 + dy)*3 + dx];
        }
        __nv_bfloat16 h = __float2bfloat16(wv);
        bh[i] = h;
        bl[i] = __float2bfloat16(wv - __bfloat162float(h));
    }
}

// ---------------- conv0: 1->32 direct, channels-last ----------------
__global__ void conv0_kernel(const float* __restrict__ data,
                             const float* __restrict__ w0,
                             float* __restrict__ raw) {
    __shared__ float ws[27*32];
    for (int i = threadIdx.x; i < 864; i += 256) {
        int tap = i / 32, c = i % 32;
        ws[tap*32 + c] = w0[c*27 + tap];
    }
    __syncthreads();
    int v = blockIdx.x*256 + threadIdx.x;
    int b = v / VOL, s = v % VOL;
    int z = s / 9216, y = (s / 96) % 96, x = s % 96;
    const float* p = data + (size_t)b * VOL;
    float acc[32];
    #pragma unroll
    for (int q = 0; q < 32; q++) acc[q] = 0.f;
    #pragma unroll
    for (int dz = 0; dz < 3; dz++) {
        int zz = z + dz - 1; if ((unsigned)zz >= 96u) continue;
        #pragma unroll
        for (int dy = 0; dy < 3; dy++) {
            int yy = y + dy - 1; if ((unsigned)yy >= 96u) continue;
            #pragma unroll
            for (int dx = 0; dx < 3; dx++) {
                int xx = x + dx - 1; if ((unsigned)xx >= 96u) continue;
                float val = __ldg(p + ((size_t)zz*96 + yy)*96 + xx);
                const float4* wp = (const float4*)(ws + ((dz*3+dy)*3+dx)*32);
                #pragma unroll
                for (int q = 0; q < 8; q++) {
                    float4 ww = wp[q];
                    acc[q*4+0] = fmaf(val, ww.x, acc[q*4+0]);
                    acc[q*4+1] = fmaf(val, ww.y, acc[q*4+1]);
                    acc[q*4+2] = fmaf(val, ww.z, acc[q*4+2]);
                    acc[q*4+3] = fmaf(val, ww.w, acc[q*4+3]);
                }
            }
        }
    }
    float* o = raw + (size_t)v * 32;
    #pragma unroll
    for (int q = 0; q < 8; q++)
        ((float4*)o)[q] = make_float4(acc[q*4], acc[q*4+1], acc[q*4+2], acc[q*4+3]);
}

// ---------------- coalesced stats (conv0 output only) ----------------
__global__ void stats0_kernel(const float* __restrict__ raw, float* __restrict__ ss) {
    const int b = blockIdx.y;
    const int tid = threadIdx.x;
    const int lane = tid & 31;
    const float4* p = (const float4*)(raw + ((size_t)b*VOL + (size_t)blockIdx.x*2048)*32);
    float s[4] = {0,0,0,0}, q[4] = {0,0,0,0};
    for (int it = 0; it < 64; it++) {
        float4 f = p[it*256 + tid];
        s[0] += f.x; q[0] = fmaf(f.x, f.x, q[0]);
        s[1] += f.y; q[1] = fmaf(f.y, f.y, q[1]);
        s[2] += f.z; q[2] = fmaf(f.z, f.z, q[2]);
        s[3] += f.w; q[3] = fmaf(f.w, f.w, q[3]);
    }
    #pragma unroll
    for (int o = 8; o < 32; o <<= 1) {
        #pragma unroll
        for (int j = 0; j < 4; j++) {
            s[j] += __shfl_xor_sync(0xffffffffu, s[j], o);
            q[j] += __shfl_xor_sync(0xffffffffu, q[j], o);
        }
    }
    __shared__ float sa[32], qa[32];
    if (tid < 32) { sa[tid] = 0.f; qa[tid] = 0.f; }
    __syncthreads();
    if (lane < 8) {
        #pragma unroll
        for (int j = 0; j < 4; j++) {
            atomicAdd(&sa[lane*4 + j], s[j]);
            atomicAdd(&qa[lane*4 + j], q[j]);
        }
    }
    __syncthreads();
    if (tid < 32) {
        atomicAdd(&ss[(b*32 + tid)*2 + 0], sa[tid]);
        atomicAdd(&ss[(b*32 + tid)*2 + 1], qa[tid]);
    }
}

// ---------------- normalize + relu + bf16 hi/lo split (interior only) ----------------
__global__ void norm_split_kernel(const float* __restrict__ raw, const float* __restrict__ ss,
                                  __nv_bfloat16* __restrict__ padh, __nv_bfloat16* __restrict__ padl) {
    __shared__ float na_s[64], nb_s[64];
    if (threadIdx.x < 64) {
        float s = ss[threadIdx.x*2], q = ss[threadIdx.x*2+1];
        float mm = s * INV_V;
        float var = fmaxf(q * INV_V - mm*mm, 0.f);
        float rstd = rsqrtf(var + EPSN);
        na_s[threadIdx.x] = rstd; nb_s[threadIdx.x] = -mm * rstd;
    }
    __syncthreads();
    int v = blockIdx.x*256 + threadIdx.x;
    int b = v / VOL, sidx = v % VOL;
    int z = sidx / 9216, y = (sidx / 96) % 96, x = sidx % 96;
    size_t pv = (((size_t)(b*PZD + z + 1))*PYD + (y + 1))*PXD + (x + 1);

    const float* rp = raw + (size_t)v * 32;
    const float* na = na_s + b*32;
    const float* nb = nb_s + b*32;
    uint32_t wh[16], wl[16];
    #pragma unroll
    for (int j = 0; j < 16; j++) {
        float v0 = fmaxf(fmaf(rp[2*j],   na[2*j],   nb[2*j]),   0.f);
        float v1 = fmaxf(fmaf(rp[2*j+1], na[2*j+1], nb[2*j+1]), 0.f);
        __nv_bfloat16 h0 = __float2bfloat16(v0);
        __nv_bfloat16 h1 = __float2bfloat16(v1);
        __nv_bfloat16 l0 = __float2bfloat16(v0 - __bfloat162float(h0));
        __nv_bfloat16 l1 = __float2bfloat16(v1 - __bfloat162float(h1));
        __nv_bfloat162 ph2; ph2.x = h0; ph2.y = h1;
        __nv_bfloat162 pl2; pl2.x = l0; pl2.y = l1;
        wh[j] = *(uint32_t*)&ph2;
        wl[j] = *(uint32_t*)&pl2;
    }
    uint4* oh = (uint4*)(padh + pv*32);
    uint4* ol = (uint4*)(padl + pv*32);
    #pragma unroll
    for (int q = 0; q < 4; q++) {
        oh[q] = make_uint4(wh[q*4], wh[q*4+1], wh[q*4+2], wh[q*4+3]);
        ol[q] = make_uint4(wl[q*4], wl[q*4+1], wl[q*4+2], wl[q*4+3]);
    }
}

// ---------------- warp-MMA conv 32->32 + fused stats ----------------
__global__ void __launch_bounds__(576, 1)
conv_mma_kernel(const __nv_bfloat16* __restrict__ padh,
                const __nv_bfloat16* __restrict__ padl,
                const __nv_bfloat16* __restrict__ wp,
                float* __restrict__ raw,
                float* __restrict__ ss)
{
    extern __shared__ __nv_bfloat16 bsm[];
    __shared__ float s_sm[64], q_sm[64];
    const int tid = threadIdx.x;
    {
        const uint4* s = (const uint4*)wp;
        uint4* d = (uint4*)bsm;
        for (int i = tid; i < 18*BTILE/8; i += 576) d[i] = s[i];
    }
    if (tid < 64) { s_sm[tid] = 0.f; q_sm[tid] = 0.f; }
    __syncthreads();

    const uint32_t bbase0 = smem_u32(bsm);
    const int lane = tid & 31;
    const int warp = tid >> 5;
    const int rowsel = warp / 6;
    const int x0 = (warp % 6) * 16;
    const int tg  = lane & 3;
    const int gid = lane >> 2;
    const int bg = lane >> 3;
    const int b_n  = ((bg >> 1) << 3) + (lane & 7);
    const int b_kh = bg & 1;

    for (int t = blockIdx.x; t < BATCH*96*32; t += gridDim.x) {
        const int b  = t / (96*32);
        const int rm = t % (96*32);
        const int z  = rm / 32;
        const int y  = (rm % 32)*3 + rowsel;

        float dacc[4][4];
        #pragma unroll
        for (int nt = 0; nt < 4; nt++)
            #pragma unroll
            for (int j = 0; j < 4; j++) dacc[nt][j] = 0.f;

        #pragma unroll 1
        for (int r = 0; r < 9; r++) {
            const int dz = r / 3, dy = r % 3;
            const size_t rowb = (((size_t)(b*PZD + z + dz))*PYD + (y + dy))*PXD;
            const uint32_t bb_h = bbase0 + (uint32_t)(r*2 + 0)*(BTILE*2);
            const uint32_t bb_l = bbase0 + (uint32_t)(r*2 + 1)*(BTILE*2);

            #pragma unroll
            for (int kc = 0; kc < 6; kc++) {
                const int dx = kc >> 1;
                const int j0 = (kc & 1)*16;
                const size_t ab = (rowb + (size_t)(x0 + gid + dx))*32 + j0 + tg*2;
                uint32_t ah0 = *(const uint32_t*)(padh + ab);
                uint32_t ah1 = *(const uint32_t*)(padh + ab + 256);
                uint32_t ah2 = *(const uint32_t*)(padh + ab + 8);
                uint32_t ah3 = *(const uint32_t*)(padh + ab + 264);
                uint32_t al0 = *(const uint32_t*)(padl + ab);
                uint32_t al1 = *(const uint32_t*)(padl + ab + 256);
                uint32_t al2 = *(const uint32_t*)(padl + ab + 8);
                uint32_t al3 = *(const uint32_t*)(padl + ab + 264);

                const uint32_t ko = (uint32_t)(kc*32 + b_kh*16);
                const uint32_t ro = (uint32_t)b_n * (BSTRIDE*2) + ko;
                uint32_t bh[8], bl[8];
                LDSM_X4(bh[0],bh[1],bh[2],bh[3], bb_h + ro);
                LDSM_X4(bh[4],bh[5],bh[6],bh[7], bb_h + ro + 16u*(BSTRIDE*2));
                LDSM_X4(bl[0],bl[1],bl[2],bl[3], bb_l + ro);
                LDSM_X4(bl[4],bl[5],bl[6],bl[7], bb_l + ro + 16u*(BSTRIDE*2));

                #pragma unroll
                for (int nt = 0; nt < 4; nt++) {
                    MMA16816(dacc[nt], ah0,ah1,ah2,ah3, bh[nt*2], bh[nt*2+1]);
                    MMA16816(dacc[nt], al0,al1,al2,al3, bh[nt*2], bh[nt*2+1]);
                    MMA16816(dacc[nt], ah0,ah1,ah2,ah3, bl[nt*2], bl[nt*2+1]);
                }
            }
        }

        float* orow = raw + ((size_t)b*VOL + (size_t)z*9216 + (size_t)y*96 + x0)*32;
        #pragma unroll
        for (int nt = 0; nt < 4; nt++) {
            const int col = nt*8 + tg*2;
            *(float2*)(orow + (size_t)gid*32 + col)      = make_float2(dacc[nt][0], dacc[nt][1]);
            *(float2*)(orow + (size_t)(gid+8)*32 + col)  = make_float2(dacc[nt][2], dacc[nt][3]);
        }

        float sv[8], qv[8];
        #pragma unroll
        for (int nt = 0; nt < 4; nt++) {
            sv[nt*2+0] = dacc[nt][0] + dacc[nt][2];
            sv[nt*2+1] = dacc[nt][1] + dacc[nt][3];
            qv[nt*2+0] = fmaf(dacc[nt][0], dacc[nt][0], dacc[nt][2]*dacc[nt][2]);
            qv[nt*2+1] = fmaf(dacc[nt][1], dacc[nt][1], dacc[nt][3]*dacc[nt][3]);
        }
        #pragma unroll
        for (int o = 4; o < 32; o <<= 1) {
            #pragma unroll
            for (int j = 0; j < 8; j++) {
                sv[j] += __shfl_xor_sync(0xffffffffu, sv[j], o);
                qv[j] += __shfl_xor_sync(0xffffffffu, qv[j], o);
            }
        }
        if (gid == 0) {
            #pragma unroll
            for (int nt = 0; nt < 4; nt++) {
                int c = b*32 + nt*8 + tg*2;
                atomicAdd(&s_sm[c],   sv[nt*2+0]);
                atomicAdd(&s_sm[c+1], sv[nt*2+1]);
                atomicAdd(&q_sm[c],   qv[nt*2+0]);
                atomicAdd(&q_sm[c+1], qv[nt*2+1]);
            }
        }
    }
    __syncthreads();
    if (tid < 64) {
        atomicAdd(&ss[tid*2 + 0], s_sm[tid]);
        atomicAdd(&ss[tid*2 + 1], q_sm[tid]);
    }
}

// ---------------- pool as warp-MMA GEMM: roi[r][bc] = sum_v mask_h[r][v] * (e_h+e_l)[bc][v]
// chunk = 32 voxels (within one x-row, pad-contiguous). A = mask bf16 [128 r][40 k-stride],
// B = pad hi/lo [(b,s)][32 v][40 c-stride], ldmatrix.trans. msum fused (exact f32).
__global__ void __launch_bounds__(256, 2)
pool_kernel(const __nv_bfloat16* __restrict__ padh,
            const __nv_bfloat16* __restrict__ padl,
            const float* __restrict__ mask)
{
    __shared__ __nv_bfloat16 a_sm[128*40];     // mask rows, stride 40 elems (80B)
    __shared__ __nv_bfloat16 e_sm[4*32*40];    // [(b*2+s)][v][c], stride 40

    const int tid  = threadIdx.x;
    const int lane = tid & 31;
    const int warp = tid >> 5;
    const int m0   = warp * 16;
    const int r0   = tid >> 3;     // 0..31
    const int vq   = tid & 7;      // float4 within 32-elem row

    // zero A rows 100..127 once (never overwritten)
    for (int i = tid; i < 28*40; i += 256)
        a_sm[100*40 + i] = __float2bfloat16(0.f);

    float acc[8][4];
    #pragma unroll
    for (int j = 0; j < 8; j++)
        #pragma unroll
        for (int q = 0; q < 4; q++) acc[j][q] = 0.f;
    float msl[4] = {0.f, 0.f, 0.f, 0.f};

    const uint32_t abase = smem_u32(a_sm);
    const uint32_t ebase = smem_u32(e_sm);
    const int nch = VOL / 32;      // 27648

    for (int chn = blockIdx.x; chn < nch; chn += gridDim.x) {
        const int v0 = chn * 32;
        const int z  = v0 / 9216;
        const int y  = (v0 / 96) % 96;
        const int x0 = v0 % 96;
        __syncthreads();

        // mask rows -> bf16 smem + exact f32 row sums
        #pragma unroll
        for (int j = 0; j < 4; j++) {
            if (j == 3 && tid >= 32) break;
            const int r = r0 + j*32;
            float4 f = *(const float4*)(mask + (size_t)r*VOL + v0 + vq*4);
            msl[j] += (f.x + f.y) + (f.z + f.w);
            uint32_t p0, p1;
            CVTBF2(p0, f.x, f.y);
            CVTBF2(p1, f.z, f.w);
            asm volatile("st.shared.v2.b32 [%0], {%1, %2};"
                :: "r"(abase + (uint32_t)(r*80 + vq*8)), "r"(p0), "r"(p1) : "memory");
        }

        // e hi/lo tiles: 4 regions x 128 uint4 (pad-contiguous)
        #pragma unroll
        for (int ii = 0; ii < 2; ii++) {
            const int i = tid + ii*256;
            const int reg = i >> 7;          // (b*2+s)
            const int bb  = reg >> 1, s = reg & 1;
            const int idx = i & 127;
            const int v   = idx >> 2;
            const int cq  = idx & 3;
            const __nv_bfloat16* src = (s ? padl : padh)
                + ((((size_t)(bb*PZD + z + 1))*PYD + (y + 1))*PXD + (x0 + 1) + v)*32;
            uint4 val = *(const uint4*)(src + cq*8);
            *(uint4*)((char*)e_sm + (size_t)(reg*32 + v)*80 + cq*16) = val;
        }
        __syncthreads();

        #pragma unroll
        for (int ks = 0; ks < 2; ks++) {
            uint32_t a0, a1, a2, a3;
            LDSM_X4(a0, a1, a2, a3,
                abase + (uint32_t)((m0 + (lane & 15))*80 + ks*32 + (lane >> 4)*16));
            #pragma unroll
            for (int reg = 0; reg < 4; reg++) {
                const int bb = reg >> 1;
                const uint32_t eb = ebase + (uint32_t)((reg*32 + ks*16)*80)
                                 + (uint32_t)((lane & 15)*80 + (lane >> 4)*16);
                uint32_t b0,b1,b2,b3, c0,c1,c2,c3;
                LDSM_X4_T(b0, b1, b2, b3, eb);
                LDSM_X4_T(c0, c1, c2, c3, eb + 32);
                const int j0 = bb*4;
                MMA16816(acc[j0+0], a0,a1,a2,a3, b0,b1);
                MMA16816(acc[j0+1], a0,a1,a2,a3, b2,b3);
                MMA16816(acc[j0+2], a0,a1,a2,a3, c0,c1);
                MMA16816(acc[j0+3], a0,a1,a2,a3, c2,c3);
            }
        }
    }

    // epilogue
    const int rlo = m0 + (lane >> 2);
    const int cc  = (lane & 3) * 2;
    #pragma unroll
    for (int j = 0; j < 8; j++) {
        const int bb = j >> 2, q = j & 3;
        const int c = q*8 + cc;
        if (rlo < NRR) {
            atomicAdd(&g_roi[(bb*NRR + rlo)*CH + c    ], acc[j][0]);
            atomicAdd(&g_roi[(bb*NRR + rlo)*CH + c + 1], acc[j][1]);
        }
        if (rlo + 8 < NRR) {
            atomicAdd(&g_roi[(bb*NRR + rlo + 8)*CH + c    ], acc[j][2]);
            atomicAdd(&g_roi[(bb*NRR + rlo + 8)*CH + c + 1], acc[j][3]);
        }
    }
    atomicAdd(&g_msum[r0],      msl[0]);
    atomicAdd(&g_msum[r0 + 32], msl[1]);
    atomicAdd(&g_msum[r0 + 64], msl[2]);
    if (tid < 32) atomicAdd(&g_msum[96 + r0], msl[3]);
}

// ---------------- per-ROI MLPs ----------------
__global__ void mlp_kernel(const float* __restrict__ sw1, const float* __restrict__ sb1,
                           const float* __restrict__ sw2, const float* __restrict__ sb2,
                           const float* __restrict__ pw1, const float* __restrict__ pb1,
                           const float* __restrict__ pw2, const float* __restrict__ pb2,
                           float* __restrict__ out)
{
    const int b = blockIdx.x / NRR;
    const int r = blockIdx.x % NRR;
    const int tid = threadIdx.x;
    __shared__ float roi_s[32], h_s[64], sf_s[32], h2_s[256];

    if (tid < 32)
        roi_s[tid] = g_roi[(b*NRR + r)*CH + tid] / g_msum[r];
    __syncthreads();
    if (tid < 64) {
        float s = sb1[r*64 + tid];
        #pragma unroll
        for (int c = 0; c < 32; c++)
            s = fmaf(roi_s[c], sw1[(r*CH + c)*64 + tid], s);
        h_s[tid] = fmaxf(s, 0.f);
    }
    __syncthreads();
    if (tid < 32) {
        float s = sb2[r*CH + tid];
        #pragma unroll
        for (int j = 0; j < 64; j++)
            s = fmaf(h_s[j], sw2[(r*64 + j)*CH + tid], s);
        sf_s[tid] = roi_s[tid] / (1.f + expf(-s));
    }
    __syncthreads();
    {
        float s = pb1[r*RHN + tid];
        #pragma unroll
        for (int c = 0; c < 32; c++)
            s = fmaf(sf_s[c], pw1[(r*CH + c)*RHN + tid], s);
        h2_s[tid] = fmaxf(s, 0.f);
    }
    __syncthreads();
    if (tid < 128) {
        float s = pb2[r*REN + tid];
        for (int k = 0; k < 256; k++)
            s = fmaf(h2_s[k], pw2[(r*RHN + k)*REN + tid], s);
        out[(b*NRR + r)*REN + tid] = s;
    }
}

// ---------------- launch ----------------
extern "C" void kernel_launch(void* const* d_in, const int* in_sizes, int n_in,
                              void* d_out, int out_size)
{
    const float* data    = (const float*)d_in[0];
    const float* mask    = (const float*)d_in[1];
    const float* conv0_w = (const float*)d_in[2];
    const float* convk_w = (const float*)d_in[4];
    const float* sw1 = (const float*)d_in[6];
    const float* sb1 = (const float*)d_in[7];
    const float* sw2 = (const float*)d_in[8];
    const float* sb2 = (const float*)d_in[9];
    const float* pw1 = (const float*)d_in[10];
    const float* pb1 = (const float*)d_in[11];
    const float* pw2 = (const float*)d_in[12];
    const float* pb2 = (const float*)d_in[13];
    float* out = (float*)d_out;

    float* raw = nullptr;  cudaGetSymbolAddress((void**)&raw,  g_raw);
    __nv_bfloat16* padh = nullptr; cudaGetSymbolAddress((void**)&padh, g_padh);
    __nv_bfloat16* padl = nullptr; cudaGetSymbolAddress((void**)&padl, g_padl);
    __nv_bfloat16* wpre = nullptr; cudaGetSymbolAddress((void**)&wpre, g_wprep);
    float* ssum = nullptr; cudaGetSymbolAddress((void**)&ssum, g_ssum);
    float* ss0 = ssum + 0*BATCH*CH*2;
    float* ss1 = ssum + 1*BATCH*CH*2;
    float* ss2 = ssum + 2*BATCH*CH*2;
    float* ss3 = ssum + 3*BATCH*CH*2;

    const int SMEMB = 18*BTILE*2;
    cudaFuncSetAttribute(conv_mma_kernel, cudaFuncAttributeMaxDynamicSharedMemorySize, SMEMB);

    const int nnb = BATCH*VOL/256;
    const size_t LW = (size_t)9*2*BTILE;

    init_kernel<<<1, 256>>>();
    wprep_kernel<<<27, 256>>>(convk_w);

    conv0_kernel<<<nnb, 256>>>(data, conv0_w, raw);
    stats0_kernel<<<dim3(432, 2), 256>>>(raw, ss0);
    norm_split_kernel<<<nnb, 256>>>(raw, ss0, padh, padl);

    conv_mma_kernel<<<148, 576, SMEMB>>>(padh, padl, wpre + 0*LW, raw, ss1);
    norm_split_kernel<<<nnb, 256>>>(raw, ss1, padh, padl);

    conv_mma_kernel<<<148, 576, SMEMB>>>(padh, padl, wpre + 1*LW, raw, ss2);
    norm_split_kernel<<<nnb, 256>>>(raw, ss2, padh, padl);

    conv_mma_kernel<<<148, 576, SMEMB>>>(padh, padl, wpre + 2*LW, raw, ss3);
    norm_split_kernel<<<nnb, 256>>>(raw, ss3, padh, padl);

    pool_kernel<<<296, 256>>>(padh, padl, mask);
    mlp_kernel<<<BATCH*NRR, 256>>>(sw1, sb1, sw2, sb2, pw1, pb1, pw2, pb2, out);
}

// round 9
// speedup vs baseline: 2.8735x; 1.1329x over previous
#include <cuda_runtime.h>
#include <cuda_bf16.h>
#include <math.h>
#include <stdint.h>

#define BATCH 2
#define CH    32
#define VOL   (96*96*96)
#define NRR   100
#define RHN   256
#define REN   128
#define INV_V (1.0f/884736.0f)
#define EPSN  1e-5f
#define PXD 132
#define PYD 98
#define PZD 98
#define PVOX (PZD*PYD*PXD)
#define BSTRIDE 104
#define BTILE   (32*BSTRIDE)

typedef unsigned long long ull;

// ---------------- warp MMA helpers ----------------
__device__ __forceinline__ uint32_t smem_u32(const void* p) {
    uint32_t a;
    asm("{ .reg .u64 t; cvta.to.shared.u64 t, %1; cvt.u32.u64 %0, t; }" : "=r"(a) : "l"(p));
    return a;
}
#define LDSM_X4(r0,r1,r2,r3,addr) \
    asm volatile("ldmatrix.sync.aligned.m8n8.x4.shared.b16 {%0,%1,%2,%3}, [%4];" \
        : "=r"(r0),"=r"(r1),"=r"(r2),"=r"(r3) : "r"(addr))
#define LDSM_X4_T(r0,r1,r2,r3,addr) \
    asm volatile("ldmatrix.sync.aligned.m8n8.x4.trans.shared.b16 {%0,%1,%2,%3}, [%4];" \
        : "=r"(r0),"=r"(r1),"=r"(r2),"=r"(r3) : "r"(addr))
#define MMA16816(d, a0,a1,a2,a3, b0,b1) \
    asm volatile("mma.sync.aligned.m16n8k16.row.col.f32.bf16.bf16.f32 " \
        "{%0,%1,%2,%3}, {%4,%5,%6,%7}, {%8,%9}, {%0,%1,%2,%3};" \
        : "+f"((d)[0]),"+f"((d)[1]),"+f"((d)[2]),"+f"((d)[3]) \
        : "r"(a0),"r"(a1),"r"(a2),"r"(a3), "r"(b0),"r"(b1))
#define CVTBF2(res, lo, hi) \
    asm("cvt.rn.bf16x2.f32 %0, %1, %2;" : "=r"(res) : "f"(hi), "f"(lo))

// ---------------- scratch ----------------
__device__ float g_raw[(size_t)BATCH*VOL*CH];
__device__ __nv_bfloat16 g_padh[(size_t)BATCH*PVOX*CH];     // borders stay zero forever
__device__ __nv_bfloat16 g_padl[(size_t)BATCH*PVOX*CH];
__device__ __align__(16) __nv_bfloat16 g_wprep[3*9*2*BTILE];
__device__ float g_ssum[4][BATCH*CH][2];
__device__ float g_roi [BATCH*NRR*CH];
__device__ float g_msum[NRR];

__global__ void init_kernel() {
    int t = threadIdx.x;
    float* ss = &g_ssum[0][0][0];
    for (int i = t; i < 4*BATCH*CH*2; i += 256) ss[i] = 0.f;
    for (int i = t; i < BATCH*NRR*CH; i += 256) g_roi[i] = 0.f;
    for (int i = t; i < NRR; i += 256) g_msum[i] = 0.f;
}

// ---------------- weight prep ----------------
__global__ void wprep_kernel(const float* __restrict__ convk_w) {
    const int L = blockIdx.x / 9;
    const int r = blockIdx.x % 9;
    const int dz = r / 3, dy = r % 3;
    __nv_bfloat16* bh = g_wprep + ((size_t)(L*9 + r)*2 + 0)*BTILE;
    __nv_bfloat16* bl = bh + BTILE;
    for (int i = threadIdx.x; i < 32*BSTRIDE; i += 256) {
        int co = i / BSTRIDE, k = i % BSTRIDE;
        float wv = 0.f;
        if (k < 96) {
            int dx = k >> 5, ci = k & 31;
            wv = convk_w[(size_t)((L*32 + co)*32 + ci)*27 + (dz*3 + dy)*3 + dx];
        }
        __nv_bfloat16 h = __float2bfloat16(wv);
        bh[i] = h;
        bl[i] = __float2bfloat16(wv - __bfloat162float(h));
    }
}

// ---------------- conv0: 1->32 direct, channels-last ----------------
__global__ void conv0_kernel(const float* __restrict__ data,
                             const float* __restrict__ w0,
                             float* __restrict__ raw) {
    __shared__ float ws[27*32];
    for (int i = threadIdx.x; i < 864; i += 256) {
        int tap = i / 32, c = i % 32;
        ws[tap*32 + c] = w0[c*27 + tap];
    }
    __syncthreads();
    int v = blockIdx.x*256 + threadIdx.x;
    int b = v / VOL, s = v % VOL;
    int z = s / 9216, y = (s / 96) % 96, x = s % 96;
    const float* p = data + (size_t)b * VOL;
    float acc[32];
    #pragma unroll
    for (int q = 0; q < 32; q++) acc[q] = 0.f;
    #pragma unroll
    for (int dz = 0; dz < 3; dz++) {
        int zz = z + dz - 1; if ((unsigned)zz >= 96u) continue;
        #pragma unroll
        for (int dy = 0; dy < 3; dy++) {
            int yy = y + dy - 1; if ((unsigned)yy >= 96u) continue;
            #pragma unroll
            for (int dx = 0; dx < 3; dx++) {
                int xx = x + dx - 1; if ((unsigned)xx >= 96u) continue;
                float val = __ldg(p + ((size_t)zz*96 + yy)*96 + xx);
                const float4* wp = (const float4*)(ws + ((dz*3+dy)*3+dx)*32);
                #pragma unroll
                for (int q = 0; q < 8; q++) {
                    float4 ww = wp[q];
                    acc[q*4+0] = fmaf(val, ww.x, acc[q*4+0]);
                    acc[q*4+1] = fmaf(val, ww.y, acc[q*4+1]);
                    acc[q*4+2] = fmaf(val, ww.z, acc[q*4+2]);
                    acc[q*4+3] = fmaf(val, ww.w, acc[q*4+3]);
                }
            }
        }
    }
    float* o = raw + (size_t)v * 32;
    #pragma unroll
    for (int q = 0; q < 8; q++)
        ((float4*)o)[q] = make_float4(acc[q*4], acc[q*4+1], acc[q*4+2], acc[q*4+3]);
}

// ---------------- coalesced stats (conv0 output only) ----------------
__global__ void stats0_kernel(const float* __restrict__ raw, float* __restrict__ ss) {
    const int b = blockIdx.y;
    const int tid = threadIdx.x;
    const int lane = tid & 31;
    const float4* p = (const float4*)(raw + ((size_t)b*VOL + (size_t)blockIdx.x*2048)*32);
    float s[4] = {0,0,0,0}, q[4] = {0,0,0,0};
    for (int it = 0; it < 64; it++) {
        float4 f = p[it*256 + tid];
        s[0] += f.x; q[0] = fmaf(f.x, f.x, q[0]);
        s[1] += f.y; q[1] = fmaf(f.y, f.y, q[1]);
        s[2] += f.z; q[2] = fmaf(f.z, f.z, q[2]);
        s[3] += f.w; q[3] = fmaf(f.w, f.w, q[3]);
    }
    #pragma unroll
    for (int o = 8; o < 32; o <<= 1) {
        #pragma unroll
        for (int j = 0; j < 4; j++) {
            s[j] += __shfl_xor_sync(0xffffffffu, s[j], o);
            q[j] += __shfl_xor_sync(0xffffffffu, q[j], o);
        }
    }
    __shared__ float sa[32], qa[32];
    if (tid < 32) { sa[tid] = 0.f; qa[tid] = 0.f; }
    __syncthreads();
    if (lane < 8) {
        #pragma unroll
        for (int j = 0; j < 4; j++) {
            atomicAdd(&sa[lane*4 + j], s[j]);
            atomicAdd(&qa[lane*4 + j], q[j]);
        }
    }
    __syncthreads();
    if (tid < 32) {
        atomicAdd(&ss[(b*32 + tid)*2 + 0], sa[tid]);
        atomicAdd(&ss[(b*32 + tid)*2 + 1], qa[tid]);
    }
}

// ---------------- normalize + relu + bf16 hi/lo split (interior only) ----------------
__global__ void norm_split_kernel(const float* __restrict__ raw, const float* __restrict__ ss,
                                  __nv_bfloat16* __restrict__ padh, __nv_bfloat16* __restrict__ padl) {
    __shared__ float na_s[64], nb_s[64];
    if (threadIdx.x < 64) {
        float s = ss[threadIdx.x*2], q = ss[threadIdx.x*2+1];
        float mm = s * INV_V;
        float var = fmaxf(q * INV_V - mm*mm, 0.f);
        float rstd = rsqrtf(var + EPSN);
        na_s[threadIdx.x] = rstd; nb_s[threadIdx.x] = -mm * rstd;
    }
    __syncthreads();
    int v = blockIdx.x*256 + threadIdx.x;
    int b = v / VOL, sidx = v % VOL;
    int z = sidx / 9216, y = (sidx / 96) % 96, x = sidx % 96;
    size_t pv = (((size_t)(b*PZD + z + 1))*PYD + (y + 1))*PXD + (x + 1);

    const float* rp = raw + (size_t)v * 32;
    const float* na = na_s + b*32;
    const float* nb = nb_s + b*32;
    uint32_t wh[16], wl[16];
    #pragma unroll
    for (int j = 0; j < 16; j++) {
        float v0 = fmaxf(fmaf(rp[2*j],   na[2*j],   nb[2*j]),   0.f);
        float v1 = fmaxf(fmaf(rp[2*j+1], na[2*j+1], nb[2*j+1]), 0.f);
        __nv_bfloat16 h0 = __float2bfloat16(v0);
        __nv_bfloat16 h1 = __float2bfloat16(v1);
        __nv_bfloat16 l0 = __float2bfloat16(v0 - __bfloat162float(h0));
        __nv_bfloat16 l1 = __float2bfloat16(v1 - __bfloat162float(h1));
        __nv_bfloat162 ph2; ph2.x = h0; ph2.y = h1;
        __nv_bfloat162 pl2; pl2.x = l0; pl2.y = l1;
        wh[j] = *(uint32_t*)&ph2;
        wl[j] = *(uint32_t*)&pl2;
    }
    uint4* oh = (uint4*)(padh + pv*32);
    uint4* ol = (uint4*)(padl + pv*32);
    #pragma unroll
    for (int q = 0; q < 4; q++) {
        oh[q] = make_uint4(wh[q*4], wh[q*4+1], wh[q*4+2], wh[q*4+3]);
        ol[q] = make_uint4(wl[q*4], wl[q*4+1], wl[q*4+2], wl[q*4+3]);
    }
}

// ---------------- warp-MMA conv 32->32 + fused stats ----------------
// 576 threads = 18 warps = 6 rows x 3 x-warps; warp = 32 voxels (2 m16 subtiles) x 32 co.
__global__ void __launch_bounds__(576, 1)
conv_mma_kernel(const __nv_bfloat16* __restrict__ padh,
                const __nv_bfloat16* __restrict__ padl,
                const __nv_bfloat16* __restrict__ wp,
                float* __restrict__ raw,
                float* __restrict__ ss)
{
    extern __shared__ __nv_bfloat16 bsm[];
    __shared__ float s_sm[64], q_sm[64];
    const int tid = threadIdx.x;
    {
        const uint4* s = (const uint4*)wp;
        uint4* d = (uint4*)bsm;
        for (int i = tid; i < 18*BTILE/8; i += 576) d[i] = s[i];
    }
    if (tid < 64) { s_sm[tid] = 0.f; q_sm[tid] = 0.f; }
    __syncthreads();

    const uint32_t bbase0 = smem_u32(bsm);
    const int lane = tid & 31;
    const int warp = tid >> 5;
    const int rowsel = warp / 3;          // 0..5
    const int x0 = (warp % 3) * 32;
    const int tg  = lane & 3;
    const int gid = lane >> 2;
    const int bg = lane >> 3;
    const int b_n  = ((bg >> 1) << 3) + (lane & 7);
    const int b_kh = bg & 1;

    for (int t = blockIdx.x; t < BATCH*96*16; t += gridDim.x) {
        const int b  = t / (96*16);
        const int rm = t % (96*16);
        const int z  = rm / 16;
        const int y  = (rm % 16)*6 + rowsel;

        float dacc[2][4][4];
        #pragma unroll
        for (int st = 0; st < 2; st++)
            #pragma unroll
            for (int nt = 0; nt < 4; nt++)
                #pragma unroll
                for (int j = 0; j < 4; j++) dacc[st][nt][j] = 0.f;

        #pragma unroll 1
        for (int r = 0; r < 9; r++) {
            const int dz = r / 3, dy = r % 3;
            const size_t rowb = (((size_t)(b*PZD + z + dz))*PYD + (y + dy))*PXD;
            const uint32_t bb_h = bbase0 + (uint32_t)(r*2 + 0)*(BTILE*2);
            const uint32_t bb_l = bbase0 + (uint32_t)(r*2 + 1)*(BTILE*2);

            #pragma unroll
            for (int kc = 0; kc < 6; kc++) {
                const int dx = kc >> 1;
                const int j0 = (kc & 1)*16;

                const uint32_t ko = (uint32_t)(kc*32 + b_kh*16);
                const uint32_t ro = (uint32_t)b_n * (BSTRIDE*2) + ko;
                uint32_t bh[8], bl[8];
                LDSM_X4(bh[0],bh[1],bh[2],bh[3], bb_h + ro);
                LDSM_X4(bh[4],bh[5],bh[6],bh[7], bb_h + ro + 16u*(BSTRIDE*2));
                LDSM_X4(bl[0],bl[1],bl[2],bl[3], bb_l + ro);
                LDSM_X4(bl[4],bl[5],bl[6],bl[7], bb_l + ro + 16u*(BSTRIDE*2));

                #pragma unroll
                for (int st = 0; st < 2; st++) {
                    const size_t ab = (rowb + (size_t)(x0 + st*16 + gid + dx))*32 + j0 + tg*2;
                    uint32_t ah0 = *(const uint32_t*)(padh + ab);
                    uint32_t ah1 = *(const uint32_t*)(padh + ab + 256);
                    uint32_t ah2 = *(const uint32_t*)(padh + ab + 8);
                    uint32_t ah3 = *(const uint32_t*)(padh + ab + 264);
                    uint32_t al0 = *(const uint32_t*)(padl + ab);
                    uint32_t al1 = *(const uint32_t*)(padl + ab + 256);
                    uint32_t al2 = *(const uint32_t*)(padl + ab + 8);
                    uint32_t al3 = *(const uint32_t*)(padl + ab + 264);
                    #pragma unroll
                    for (int nt = 0; nt < 4; nt++) {
                        MMA16816(dacc[st][nt], ah0,ah1,ah2,ah3, bh[nt*2], bh[nt*2+1]);
                        MMA16816(dacc[st][nt], al0,al1,al2,al3, bh[nt*2], bh[nt*2+1]);
                        MMA16816(dacc[st][nt], ah0,ah1,ah2,ah3, bl[nt*2], bl[nt*2+1]);
                    }
                }
            }
        }

        #pragma unroll
        for (int st = 0; st < 2; st++) {
            float* orow = raw + ((size_t)b*VOL + (size_t)z*9216 + (size_t)y*96 + x0 + st*16)*32;
            #pragma unroll
            for (int nt = 0; nt < 4; nt++) {
                const int col = nt*8 + tg*2;
                *(float2*)(orow + (size_t)gid*32 + col)      = make_float2(dacc[st][nt][0], dacc[st][nt][1]);
                *(float2*)(orow + (size_t)(gid+8)*32 + col)  = make_float2(dacc[st][nt][2], dacc[st][nt][3]);
            }
        }

        // fused stats over both subtiles
        float sv[8], qv[8];
        #pragma unroll
        for (int nt = 0; nt < 4; nt++) {
            sv[nt*2+0] = (dacc[0][nt][0] + dacc[0][nt][2]) + (dacc[1][nt][0] + dacc[1][nt][2]);
            sv[nt*2+1] = (dacc[0][nt][1] + dacc[0][nt][3]) + (dacc[1][nt][1] + dacc[1][nt][3]);
            float q0 = fmaf(dacc[0][nt][0], dacc[0][nt][0], dacc[0][nt][2]*dacc[0][nt][2]);
            float q1 = fmaf(dacc[0][nt][1], dacc[0][nt][1], dacc[0][nt][3]*dacc[0][nt][3]);
            qv[nt*2+0] = fmaf(dacc[1][nt][0], dacc[1][nt][0], fmaf(dacc[1][nt][2], dacc[1][nt][2], q0));
            qv[nt*2+1] = fmaf(dacc[1][nt][1], dacc[1][nt][1], fmaf(dacc[1][nt][3], dacc[1][nt][3], q1));
        }
        #pragma unroll
        for (int o = 4; o < 32; o <<= 1) {
            #pragma unroll
            for (int j = 0; j < 8; j++) {
                sv[j] += __shfl_xor_sync(0xffffffffu, sv[j], o);
                qv[j] += __shfl_xor_sync(0xffffffffu, qv[j], o);
            }
        }
        if (gid == 0) {
            #pragma unroll
            for (int nt = 0; nt < 4; nt++) {
                int c = b*32 + nt*8 + tg*2;
                atomicAdd(&s_sm[c],   sv[nt*2+0]);
                atomicAdd(&s_sm[c+1], sv[nt*2+1]);
                atomicAdd(&q_sm[c],   qv[nt*2+0]);
                atomicAdd(&q_sm[c+1], qv[nt*2+1]);
            }
        }
    }
    __syncthreads();
    if (tid < 64) {
        atomicAdd(&ss[tid*2 + 0], s_sm[tid]);
        atomicAdd(&ss[tid*2 + 1], q_sm[tid]);
    }
}

// ---------------- pool as warp-MMA GEMM ----------------
__global__ void __launch_bounds__(256, 2)
pool_kernel(const __nv_bfloat16* __restrict__ padh,
            const __nv_bfloat16* __restrict__ padl,
            const float* __restrict__ mask)
{
    __shared__ __nv_bfloat16 a_sm[128*40];
    __shared__ __nv_bfloat16 e_sm[4*32*40];

    const int tid  = threadIdx.x;
    const int lane = tid & 31;
    const int warp = tid >> 5;
    const int m0   = warp * 16;
    const int r0   = tid >> 3;
    const int vq   = tid & 7;

    for (int i = tid; i < 28*40; i += 256)
        a_sm[100*40 + i] = __float2bfloat16(0.f);

    float acc[8][4];
    #pragma unroll
    for (int j = 0; j < 8; j++)
        #pragma unroll
        for (int q = 0; q < 4; q++) acc[j][q] = 0.f;
    float msl[4] = {0.f, 0.f, 0.f, 0.f};

    const uint32_t abase = smem_u32(a_sm);
    const uint32_t ebase = smem_u32(e_sm);
    const int nch = VOL / 32;

    for (int chn = blockIdx.x; chn < nch; chn += gridDim.x) {
        const int v0 = chn * 32;
        const int z  = v0 / 9216;
        const int y  = (v0 / 96) % 96;
        const int x0 = v0 % 96;
        __syncthreads();

        #pragma unroll
        for (int j = 0; j < 4; j++) {
            if (j == 3 && tid >= 32) break;
            const int r = r0 + j*32;
            float4 f = *(const float4*)(mask + (size_t)r*VOL + v0 + vq*4);
            msl[j] += (f.x + f.y) + (f.z + f.w);
            uint32_t p0, p1;
            CVTBF2(p0, f.x, f.y);
            CVTBF2(p1, f.z, f.w);
            asm volatile("st.shared.v2.b32 [%0], {%1, %2};"
                :: "r"(abase + (uint32_t)(r*80 + vq*8)), "r"(p0), "r"(p1) : "memory");
        }

        #pragma unroll
        for (int ii = 0; ii < 2; ii++) {
            const int i = tid + ii*256;
            const int reg = i >> 7;
            const int bb  = reg >> 1, s = reg & 1;
            const int idx = i & 127;
            const int v   = idx >> 2;
            const int cq  = idx & 3;
            const __nv_bfloat16* src = (s ? padl : padh)
                + ((((size_t)(bb*PZD + z + 1))*PYD + (y + 1))*PXD + (x0 + 1) + v)*32;
            uint4 val = *(const uint4*)(src + cq*8);
            *(uint4*)((char*)e_sm + (size_t)(reg*32 + v)*80 + cq*16) = val;
        }
        __syncthreads();

        #pragma unroll
        for (int ks = 0; ks < 2; ks++) {
            uint32_t a0, a1, a2, a3;
            LDSM_X4(a0, a1, a2, a3,
                abase + (uint32_t)((m0 + (lane & 15))*80 + ks*32 + (lane >> 4)*16));
            #pragma unroll
            for (int reg = 0; reg < 4; reg++) {
                const int bb = reg >> 1;
                const uint32_t eb = ebase + (uint32_t)((reg*32 + ks*16)*80)
                                 + (uint32_t)((lane & 15)*80 + (lane >> 4)*16);
                uint32_t b0,b1,b2,b3, c0,c1,c2,c3;
                LDSM_X4_T(b0, b1, b2, b3, eb);
                LDSM_X4_T(c0, c1, c2, c3, eb + 32);
                const int j0 = bb*4;
                MMA16816(acc[j0+0], a0,a1,a2,a3, b0,b1);
                MMA16816(acc[j0+1], a0,a1,a2,a3, b2,b3);
                MMA16816(acc[j0+2], a0,a1,a2,a3, c0,c1);
                MMA16816(acc[j0+3], a0,a1,a2,a3, c2,c3);
            }
        }
    }

    const int rlo = m0 + (lane >> 2);
    const int cc  = (lane & 3) * 2;
    #pragma unroll
    for (int j = 0; j < 8; j++) {
        const int bb = j >> 2, q = j & 3;
        const int c = q*8 + cc;
        if (rlo < NRR) {
            atomicAdd(&g_roi[(bb*NRR + rlo)*CH + c    ], acc[j][0]);
            atomicAdd(&g_roi[(bb*NRR + rlo)*CH + c + 1], acc[j][1]);
        }
        if (rlo + 8 < NRR) {
            atomicAdd(&g_roi[(bb*NRR + rlo + 8)*CH + c    ], acc[j][2]);
            atomicAdd(&g_roi[(bb*NRR + rlo + 8)*CH + c + 1], acc[j][3]);
        }
    }
    atomicAdd(&g_msum[r0],      msl[0]);
    atomicAdd(&g_msum[r0 + 32], msl[1]);
    atomicAdd(&g_msum[r0 + 64], msl[2]);
    if (tid < 32) atomicAdd(&g_msum[96 + r0], msl[3]);
}

// ---------------- per-ROI MLPs ----------------
__global__ void mlp_kernel(const float* __restrict__ sw1, const float* __restrict__ sb1,
                           const float* __restrict__ sw2, const float* __restrict__ sb2,
                           const float* __restrict__ pw1, const float* __restrict__ pb1,
                           const float* __restrict__ pw2, const float* __restrict__ pb2,
                           float* __restrict__ out)
{
    const int b = blockIdx.x / NRR;
    const int r = blockIdx.x % NRR;
    const int tid = threadIdx.x;
    __shared__ float roi_s[32], h_s[64], sf_s[32], h2_s[256];

    if (tid < 32)
        roi_s[tid] = g_roi[(b*NRR + r)*CH + tid] / g_msum[r];
    __syncthreads();
    if (tid < 64) {
        float s = sb1[r*64 + tid];
        #pragma unroll
        for (int c = 0; c < 32; c++)
            s = fmaf(roi_s[c], sw1[(r*CH + c)*64 + tid], s);
        h_s[tid] = fmaxf(s, 0.f);
    }
    __syncthreads();
    if (tid < 32) {
        float s = sb2[r*CH + tid];
        #pragma unroll
        for (int j = 0; j < 64; j++)
            s = fmaf(h_s[j], sw2[(r*64 + j)*CH + tid], s);
        sf_s[tid] = roi_s[tid] / (1.f + expf(-s));
    }
    __syncthreads();
    {
        float s = pb1[r*RHN + tid];
        #pragma unroll
        for (int c = 0; c < 32; c++)
            s = fmaf(sf_s[c], pw1[(r*CH + c)*RHN + tid], s);
        h2_s[tid] = fmaxf(s, 0.f);
    }
    __syncthreads();
    if (tid < 128) {
        float s = pb2[r*REN + tid];
        for (int k = 0; k < 256; k++)
            s = fmaf(h2_s[k], pw2[(r*RHN + k)*REN + tid], s);
        out[(b*NRR + r)*REN + tid] = s;
    }
}

// ---------------- launch ----------------
extern "C" void kernel_launch(void* const* d_in, const int* in_sizes, int n_in,
                              void* d_out, int out_size)
{
    const float* data    = (const float*)d_in[0];
    const float* mask    = (const float*)d_in[1];
    const float* conv0_w = (const float*)d_in[2];
    const float* convk_w = (const float*)d_in[4];
    const float* sw1 = (const float*)d_in[6];
    const float* sb1 = (const float*)d_in[7];
    const float* sw2 = (const float*)d_in[8];
    const float* sb2 = (const float*)d_in[9];
    const float* pw1 = (const float*)d_in[10];
    const float* pb1 = (const float*)d_in[11];
    const float* pw2 = (const float*)d_in[12];
    const float* pb2 = (const float*)d_in[13];
    float* out = (float*)d_out;

    float* raw = nullptr;  cudaGetSymbolAddress((void**)&raw,  g_raw);
    __nv_bfloat16* padh = nullptr; cudaGetSymbolAddress((void**)&padh, g_padh);
    __nv_bfloat16* padl = nullptr; cudaGetSymbolAddress((void**)&padl, g_padl);
    __nv_bfloat16* wpre = nullptr; cudaGetSymbolAddress((void**)&wpre, g_wprep);
    float* ssum = nullptr; cudaGetSymbolAddress((void**)&ssum, g_ssum);
    float* ss0 = ssum + 0*BATCH*CH*2;
    float* ss1 = ssum + 1*BATCH*CH*2;
    float* ss2 = ssum + 2*BATCH*CH*2;
    float* ss3 = ssum + 3*BATCH*CH*2;

    const int SMEMB = 18*BTILE*2;
    cudaFuncSetAttribute(conv_mma_kernel, cudaFuncAttributeMaxDynamicSharedMemorySize, SMEMB);

    const int nnb = BATCH*VOL/256;
    const size_t LW = (size_t)9*2*BTILE;

    init_kernel<<<1, 256>>>();
    wprep_kernel<<<27, 256>>>(convk_w);

    conv0_kernel<<<nnb, 256>>>(data, conv0_w, raw);
    stats0_kernel<<<dim3(432, 2), 256>>>(raw, ss0);
    norm_split_kernel<<<nnb, 256>>>(raw, ss0, padh, padl);

    conv_mma_kernel<<<148, 576, SMEMB>>>(padh, padl, wpre + 0*LW, raw, ss1);
    norm_split_kernel<<<nnb, 256>>>(raw, ss1, padh, padl);

    conv_mma_kernel<<<148, 576, SMEMB>>>(padh, padl, wpre + 1*LW, raw, ss2);
    norm_split_kernel<<<nnb, 256>>>(raw, ss2, padh, padl);

    conv_mma_kernel<<<148, 576, SMEMB>>>(padh, padl, wpre + 2*LW, raw, ss3);
    norm_split_kernel<<<nnb, 256>>>(raw, ss3, padh, padl);

    pool_kernel<<<296, 256>>>(padh, padl, mask);
    mlp_kernel<<<BATCH*NRR, 256>>>(sw1, sb1, sw2, sb2, pw1, pb1, pw2, pb2, out);
}

// round 10
// speedup vs baseline: 2.8973x; 1.0083x over previous
#include <cuda_runtime.h>
#include <cuda_bf16.h>
#include <math.h>
#include <stdint.h>

#define BATCH 2
#define CH    32
#define VOL   (96*96*96)
#define NRR   100
#define RHN   256
#define REN   128
#define INV_V (1.0f/884736.0f)
#define EPSN  1e-5f
#define PXD 132
#define PYD 98
#define PZD 98
#define PVOX (PZD*PYD*PXD)
#define BSTRIDE 104
#define BTILE   (32*BSTRIDE)

typedef unsigned long long ull;

// ---------------- warp MMA helpers ----------------
__device__ __forceinline__ uint32_t smem_u32(const void* p) {
    uint32_t a;
    asm("{ .reg .u64 t; cvta.to.shared.u64 t, %1; cvt.u32.u64 %0, t; }" : "=r"(a) : "l"(p));
    return a;
}
#define LDSM_X4(r0,r1,r2,r3,addr) \
    asm volatile("ldmatrix.sync.aligned.m8n8.x4.shared.b16 {%0,%1,%2,%3}, [%4];" \
        : "=r"(r0),"=r"(r1),"=r"(r2),"=r"(r3) : "r"(addr))
#define LDSM_X4_T(r0,r1,r2,r3,addr) \
    asm volatile("ldmatrix.sync.aligned.m8n8.x4.trans.shared.b16 {%0,%1,%2,%3}, [%4];" \
        : "=r"(r0),"=r"(r1),"=r"(r2),"=r"(r3) : "r"(addr))
#define MMA16816(d, a0,a1,a2,a3, b0,b1) \
    asm volatile("mma.sync.aligned.m16n8k16.row.col.f32.bf16.bf16.f32 " \
        "{%0,%1,%2,%3}, {%4,%5,%6,%7}, {%8,%9}, {%0,%1,%2,%3};" \
        : "+f"((d)[0]),"+f"((d)[1]),"+f"((d)[2]),"+f"((d)[3]) \
        : "r"(a0),"r"(a1),"r"(a2),"r"(a3), "r"(b0),"r"(b1))
#define CVTBF2(res, lo, hi) \
    asm("cvt.rn.bf16x2.f32 %0, %1, %2;" : "=r"(res) : "f"(hi), "f"(lo))

// ---------------- scratch ----------------
__device__ float g_raw[(size_t)BATCH*VOL*CH];
__device__ __nv_bfloat16 g_padh[(size_t)BATCH*PVOX*CH];     // borders stay zero forever
__device__ __nv_bfloat16 g_padl[(size_t)BATCH*PVOX*CH];
__device__ __align__(16) __nv_bfloat16 g_wprep[3*9*2*BTILE];
__device__ float g_ssum[4][BATCH*CH][2];
__device__ float g_roi [BATCH*NRR*CH];
__device__ float g_msum[NRR];

__global__ void init_kernel() {
    int t = threadIdx.x;
    float* ss = &g_ssum[0][0][0];
    for (int i = t; i < 4*BATCH*CH*2; i += 256) ss[i] = 0.f;
    for (int i = t; i < BATCH*NRR*CH; i += 256) g_roi[i] = 0.f;
    for (int i = t; i < NRR; i += 256) g_msum[i] = 0.f;
}

// ---------------- weight prep ----------------
__global__ void wprep_kernel(const float* __restrict__ convk_w) {
    const int L = blockIdx.x / 9;
    const int r = blockIdx.x % 9;
    const int dz = r / 3, dy = r % 3;
    __nv_bfloat16* bh = g_wprep + ((size_t)(L*9 + r)*2 + 0)*BTILE;
    __nv_bfloat16* bl = bh + BTILE;
    for (int i = threadIdx.x; i < 32*BSTRIDE; i += 256) {
        int co = i / BSTRIDE, k = i % BSTRIDE;
        float wv = 0.f;
        if (k < 96) {
            int dx = k >> 5, ci = k & 31;
            wv = convk_w[(size_t)((L*32 + co)*32 + ci)*27 + (dz*3 + dy)*3 + dx];
        }
        __nv_bfloat16 h = __float2bfloat16(wv);
        bh[i] = h;
        bl[i] = __float2bfloat16(wv - __bfloat162float(h));
    }
}

// ---------------- conv0: 1->32 direct, channels-last ----------------
__global__ void conv0_kernel(const float* __restrict__ data,
                             const float* __restrict__ w0,
                             float* __restrict__ raw) {
    __shared__ float ws[27*32];
    for (int i = threadIdx.x; i < 864; i += 256) {
        int tap = i / 32, c = i % 32;
        ws[tap*32 + c] = w0[c*27 + tap];
    }
    __syncthreads();
    int v = blockIdx.x*256 + threadIdx.x;
    int b = v / VOL, s = v % VOL;
    int z = s / 9216, y = (s / 96) % 96, x = s % 96;
    const float* p = data + (size_t)b * VOL;
    float acc[32];
    #pragma unroll
    for (int q = 0; q < 32; q++) acc[q] = 0.f;
    #pragma unroll
    for (int dz = 0; dz < 3; dz++) {
        int zz = z + dz - 1; if ((unsigned)zz >= 96u) continue;
        #pragma unroll
        for (int dy = 0; dy < 3; dy++) {
            int yy = y + dy - 1; if ((unsigned)yy >= 96u) continue;
            #pragma unroll
            for (int dx = 0; dx < 3; dx++) {
                int xx = x + dx - 1; if ((unsigned)xx >= 96u) continue;
                float val = __ldg(p + ((size_t)zz*96 + yy)*96 + xx);
                const float4* wp = (const float4*)(ws + ((dz*3+dy)*3+dx)*32);
                #pragma unroll
                for (int q = 0; q < 8; q++) {
                    float4 ww = wp[q];
                    acc[q*4+0] = fmaf(val, ww.x, acc[q*4+0]);
                    acc[q*4+1] = fmaf(val, ww.y, acc[q*4+1]);
                    acc[q*4+2] = fmaf(val, ww.z, acc[q*4+2]);
                    acc[q*4+3] = fmaf(val, ww.w, acc[q*4+3]);
                }
            }
        }
    }
    float* o = raw + (size_t)v * 32;
    #pragma unroll
    for (int q = 0; q < 8; q++)
        ((float4*)o)[q] = make_float4(acc[q*4], acc[q*4+1], acc[q*4+2], acc[q*4+3]);
}

// ---------------- coalesced stats (conv0 output only) ----------------
__global__ void stats0_kernel(const float* __restrict__ raw, float* __restrict__ ss) {
    const int b = blockIdx.y;
    const int tid = threadIdx.x;
    const int lane = tid & 31;
    const float4* p = (const float4*)(raw + ((size_t)b*VOL + (size_t)blockIdx.x*2048)*32);
    float s[4] = {0,0,0,0}, q[4] = {0,0,0,0};
    for (int it = 0; it < 64; it++) {
        float4 f = p[it*256 + tid];
        s[0] += f.x; q[0] = fmaf(f.x, f.x, q[0]);
        s[1] += f.y; q[1] = fmaf(f.y, f.y, q[1]);
        s[2] += f.z; q[2] = fmaf(f.z, f.z, q[2]);
        s[3] += f.w; q[3] = fmaf(f.w, f.w, q[3]);
    }
    #pragma unroll
    for (int o = 8; o < 32; o <<= 1) {
        #pragma unroll
        for (int j = 0; j < 4; j++) {
            s[j] += __shfl_xor_sync(0xffffffffu, s[j], o);
            q[j] += __shfl_xor_sync(0xffffffffu, q[j], o);
        }
    }
    __shared__ float sa[32], qa[32];
    if (tid < 32) { sa[tid] = 0.f; qa[tid] = 0.f; }
    __syncthreads();
    if (lane < 8) {
        #pragma unroll
        for (int j = 0; j < 4; j++) {
            atomicAdd(&sa[lane*4 + j], s[j]);
            atomicAdd(&qa[lane*4 + j], q[j]);
        }
    }
    __syncthreads();
    if (tid < 32) {
        atomicAdd(&ss[(b*32 + tid)*2 + 0], sa[tid]);
        atomicAdd(&ss[(b*32 + tid)*2 + 1], qa[tid]);
    }
}

// ---------------- normalize + relu + bf16 hi/lo split (interior only) ----------------
__global__ void norm_split_kernel(const float* __restrict__ raw, const float* __restrict__ ss,
                                  __nv_bfloat16* __restrict__ padh, __nv_bfloat16* __restrict__ padl) {
    __shared__ float na_s[64], nb_s[64];
    if (threadIdx.x < 64) {
        float s = ss[threadIdx.x*2], q = ss[threadIdx.x*2+1];
        float mm = s * INV_V;
        float var = fmaxf(q * INV_V - mm*mm, 0.f);
        float rstd = rsqrtf(var + EPSN);
        na_s[threadIdx.x] = rstd; nb_s[threadIdx.x] = -mm * rstd;
    }
    __syncthreads();
    int v = blockIdx.x*256 + threadIdx.x;
    int b = v / VOL, sidx = v % VOL;
    int z = sidx / 9216, y = (sidx / 96) % 96, x = sidx % 96;
    size_t pv = (((size_t)(b*PZD + z + 1))*PYD + (y + 1))*PXD + (x + 1);

    const float* rp = raw + (size_t)v * 32;
    const float* na = na_s + b*32;
    const float* nb = nb_s + b*32;
    uint32_t wh[16], wl[16];
    #pragma unroll
    for (int j = 0; j < 16; j++) {
        float v0 = fmaxf(fmaf(rp[2*j],   na[2*j],   nb[2*j]),   0.f);
        float v1 = fmaxf(fmaf(rp[2*j+1], na[2*j+1], nb[2*j+1]), 0.f);
        __nv_bfloat16 h0 = __float2bfloat16(v0);
        __nv_bfloat16 h1 = __float2bfloat16(v1);
        __nv_bfloat16 l0 = __float2bfloat16(v0 - __bfloat162float(h0));
        __nv_bfloat16 l1 = __float2bfloat16(v1 - __bfloat162float(h1));
        __nv_bfloat162 ph2; ph2.x = h0; ph2.y = h1;
        __nv_bfloat162 pl2; pl2.x = l0; pl2.y = l1;
        wh[j] = *(uint32_t*)&ph2;
        wl[j] = *(uint32_t*)&pl2;
    }
    uint4* oh = (uint4*)(padh + pv*32);
    uint4* ol = (uint4*)(padl + pv*32);
    #pragma unroll
    for (int q = 0; q < 4; q++) {
        oh[q] = make_uint4(wh[q*4], wh[q*4+1], wh[q*4+2], wh[q*4+3]);
        ol[q] = make_uint4(wl[q*4], wl[q*4+1], wl[q*4+2], wl[q*4+3]);
    }
}

// ---------------- warp-MMA conv 32->32 + fused stats ----------------
// 768 threads = 24 warps = 8 rows x 3 x-warps; warp = 32 voxels (2 m16 subtiles) x 32 co.
__global__ void __launch_bounds__(768, 1)
conv_mma_kernel(const __nv_bfloat16* __restrict__ padh,
                const __nv_bfloat16* __restrict__ padl,
                const __nv_bfloat16* __restrict__ wp,
                float* __restrict__ raw,
                float* __restrict__ ss)
{
    extern __shared__ __nv_bfloat16 bsm[];
    __shared__ float s_sm[64], q_sm[64];
    const int tid = threadIdx.x;
    {
        const uint4* s = (const uint4*)wp;
        uint4* d = (uint4*)bsm;
        for (int i = tid; i < 18*BTILE/8; i += 768) d[i] = s[i];
    }
    if (tid < 64) { s_sm[tid] = 0.f; q_sm[tid] = 0.f; }
    __syncthreads();

    const uint32_t bbase0 = smem_u32(bsm);
    const int lane = tid & 31;
    const int warp = tid >> 5;
    const int rowsel = warp / 3;          // 0..7
    const int x0 = (warp % 3) * 32;
    const int tg  = lane & 3;
    const int gid = lane >> 2;
    const int bg = lane >> 3;
    const int b_n  = ((bg >> 1) << 3) + (lane & 7);
    const int b_kh = bg & 1;

    for (int t = blockIdx.x; t < BATCH*96*12; t += gridDim.x) {
        const int b  = t / (96*12);
        const int rm = t % (96*12);
        const int z  = rm / 12;
        const int y  = (rm % 12)*8 + rowsel;

        float dacc[2][4][4];
        #pragma unroll
        for (int st = 0; st < 2; st++)
            #pragma unroll
            for (int nt = 0; nt < 4; nt++)
                #pragma unroll
                for (int j = 0; j < 4; j++) dacc[st][nt][j] = 0.f;

        #pragma unroll 1
        for (int r = 0; r < 9; r++) {
            const int dz = r / 3, dy = r % 3;
            const size_t rowb = (((size_t)(b*PZD + z + dz))*PYD + (y + dy))*PXD;
            const uint32_t bb_h = bbase0 + (uint32_t)(r*2 + 0)*(BTILE*2);
            const uint32_t bb_l = bbase0 + (uint32_t)(r*2 + 1)*(BTILE*2);

            #pragma unroll
            for (int kc = 0; kc < 6; kc++) {
                const int dx = kc >> 1;
                const int j0 = (kc & 1)*16;

                const uint32_t ko = (uint32_t)(kc*32 + b_kh*16);
                const uint32_t ro = (uint32_t)b_n * (BSTRIDE*2) + ko;
                uint32_t bh[8], bl[8];
                LDSM_X4(bh[0],bh[1],bh[2],bh[3], bb_h + ro);
                LDSM_X4(bh[4],bh[5],bh[6],bh[7], bb_h + ro + 16u*(BSTRIDE*2));
                LDSM_X4(bl[0],bl[1],bl[2],bl[3], bb_l + ro);
                LDSM_X4(bl[4],bl[5],bl[6],bl[7], bb_l + ro + 16u*(BSTRIDE*2));

                #pragma unroll
                for (int st = 0; st < 2; st++) {
                    const size_t ab = (rowb + (size_t)(x0 + st*16 + gid + dx))*32 + j0 + tg*2;
                    uint32_t ah0 = *(const uint32_t*)(padh + ab);
                    uint32_t ah1 = *(const uint32_t*)(padh + ab + 256);
                    uint32_t ah2 = *(const uint32_t*)(padh + ab + 8);
                    uint32_t ah3 = *(const uint32_t*)(padh + ab + 264);
                    uint32_t al0 = *(const uint32_t*)(padl + ab);
                    uint32_t al1 = *(const uint32_t*)(padl + ab + 256);
                    uint32_t al2 = *(const uint32_t*)(padl + ab + 8);
                    uint32_t al3 = *(const uint32_t*)(padl + ab + 264);
                    #pragma unroll
                    for (int nt = 0; nt < 4; nt++) {
                        MMA16816(dacc[st][nt], ah0,ah1,ah2,ah3, bh[nt*2], bh[nt*2+1]);
                        MMA16816(dacc[st][nt], al0,al1,al2,al3, bh[nt*2], bh[nt*2+1]);
                        MMA16816(dacc[st][nt], ah0,ah1,ah2,ah3, bl[nt*2], bl[nt*2+1]);
                    }
                }
            }
        }

        #pragma unroll
        for (int st = 0; st < 2; st++) {
            float* orow = raw + ((size_t)b*VOL + (size_t)z*9216 + (size_t)y*96 + x0 + st*16)*32;
            #pragma unroll
            for (int nt = 0; nt < 4; nt++) {
                const int col = nt*8 + tg*2;
                *(float2*)(orow + (size_t)gid*32 + col)      = make_float2(dacc[st][nt][0], dacc[st][nt][1]);
                *(float2*)(orow + (size_t)(gid+8)*32 + col)  = make_float2(dacc[st][nt][2], dacc[st][nt][3]);
            }
        }

        // fused stats over both subtiles
        float sv[8], qv[8];
        #pragma unroll
        for (int nt = 0; nt < 4; nt++) {
            sv[nt*2+0] = (dacc[0][nt][0] + dacc[0][nt][2]) + (dacc[1][nt][0] + dacc[1][nt][2]);
            sv[nt*2+1] = (dacc[0][nt][1] + dacc[0][nt][3]) + (dacc[1][nt][1] + dacc[1][nt][3]);
            float q0 = fmaf(dacc[0][nt][0], dacc[0][nt][0], dacc[0][nt][2]*dacc[0][nt][2]);
            float q1 = fmaf(dacc[0][nt][1], dacc[0][nt][1], dacc[0][nt][3]*dacc[0][nt][3]);
            qv[nt*2+0] = fmaf(dacc[1][nt][0], dacc[1][nt][0], fmaf(dacc[1][nt][2], dacc[1][nt][2], q0));
            qv[nt*2+1] = fmaf(dacc[1][nt][1], dacc[1][nt][1], fmaf(dacc[1][nt][3], dacc[1][nt][3], q1));
        }
        #pragma unroll
        for (int o = 4; o < 32; o <<= 1) {
            #pragma unroll
            for (int j = 0; j < 8; j++) {
                sv[j] += __shfl_xor_sync(0xffffffffu, sv[j], o);
                qv[j] += __shfl_xor_sync(0xffffffffu, qv[j], o);
            }
        }
        if (gid == 0) {
            #pragma unroll
            for (int nt = 0; nt < 4; nt++) {
                int c = b*32 + nt*8 + tg*2;
                atomicAdd(&s_sm[c],   sv[nt*2+0]);
                atomicAdd(&s_sm[c+1], sv[nt*2+1]);
                atomicAdd(&q_sm[c],   qv[nt*2+0]);
                atomicAdd(&q_sm[c+1], qv[nt*2+1]);
            }
        }
    }
    __syncthreads();
    if (tid < 64) {
        atomicAdd(&ss[tid*2 + 0], s_sm[tid]);
        atomicAdd(&ss[tid*2 + 1], q_sm[tid]);
    }
}

// ---------------- pool as warp-MMA GEMM (hi-only e; lo term averages out) ----------------
__global__ void __launch_bounds__(256, 2)
pool_kernel(const __nv_bfloat16* __restrict__ padh,
            const float* __restrict__ mask)
{
    __shared__ __nv_bfloat16 a_sm[128*40];
    __shared__ __nv_bfloat16 e_sm[2*32*40];

    const int tid  = threadIdx.x;
    const int lane = tid & 31;
    const int warp = tid >> 5;
    const int m0   = warp * 16;
    const int r0   = tid >> 3;
    const int vq   = tid & 7;

    for (int i = tid; i < 28*40; i += 256)
        a_sm[100*40 + i] = __float2bfloat16(0.f);

    float acc[8][4];
    #pragma unroll
    for (int j = 0; j < 8; j++)
        #pragma unroll
        for (int q = 0; q < 4; q++) acc[j][q] = 0.f;
    float msl[4] = {0.f, 0.f, 0.f, 0.f};

    const uint32_t abase = smem_u32(a_sm);
    const uint32_t ebase = smem_u32(e_sm);
    const int nch = VOL / 32;

    for (int chn = blockIdx.x; chn < nch; chn += gridDim.x) {
        const int v0 = chn * 32;
        const int z  = v0 / 9216;
        const int y  = (v0 / 96) % 96;
        const int x0 = v0 % 96;
        __syncthreads();

        #pragma unroll
        for (int j = 0; j < 4; j++) {
            if (j == 3 && tid >= 32) break;
            const int r = r0 + j*32;
            float4 f = *(const float4*)(mask + (size_t)r*VOL + v0 + vq*4);
            msl[j] += (f.x + f.y) + (f.z + f.w);
            uint32_t p0, p1;
            CVTBF2(p0, f.x, f.y);
            CVTBF2(p1, f.z, f.w);
            asm volatile("st.shared.v2.b32 [%0], {%1, %2};"
                :: "r"(abase + (uint32_t)(r*80 + vq*8)), "r"(p0), "r"(p1) : "memory");
        }

        // e hi tiles: 2 regions (b=0,1) x 128 uint4
        {
            const int i = tid;
            const int bb  = i >> 7;
            const int idx = i & 127;
            const int v   = idx >> 2;
            const int cq  = idx & 3;
            const __nv_bfloat16* src = padh
                + ((((size_t)(bb*PZD + z + 1))*PYD + (y + 1))*PXD + (x0 + 1) + v)*32;
            uint4 val = *(const uint4*)(src + cq*8);
            *(uint4*)((char*)e_sm + (size_t)(bb*32 + v)*80 + cq*16) = val;
        }
        __syncthreads();

        #pragma unroll
        for (int ks = 0; ks < 2; ks++) {
            uint32_t a0, a1, a2, a3;
            LDSM_X4(a0, a1, a2, a3,
                abase + (uint32_t)((m0 + (lane & 15))*80 + ks*32 + (lane >> 4)*16));
            #pragma unroll
            for (int bb = 0; bb < 2; bb++) {
                const uint32_t eb = ebase + (uint32_t)((bb*32 + ks*16)*80)
                                 + (uint32_t)((lane & 15)*80 + (lane >> 4)*16);
                uint32_t b0,b1,b2,b3, c0,c1,c2,c3;
                LDSM_X4_T(b0, b1, b2, b3, eb);
                LDSM_X4_T(c0, c1, c2, c3, eb + 32);
                const int j0 = bb*4;
                MMA16816(acc[j0+0], a0,a1,a2,a3, b0,b1);
                MMA16816(acc[j0+1], a0,a1,a2,a3, b2,b3);
                MMA16816(acc[j0+2], a0,a1,a2,a3, c0,c1);
                MMA16816(acc[j0+3], a0,a1,a2,a3, c2,c3);
            }
        }
    }

    const int rlo = m0 + (lane >> 2);
    const int cc  = (lane & 3) * 2;
    #pragma unroll
    for (int j = 0; j < 8; j++) {
        const int bb = j >> 2, q = j & 3;
        const int c = q*8 + cc;
        if (rlo < NRR) {
            atomicAdd(&g_roi[(bb*NRR + rlo)*CH + c    ], acc[j][0]);
            atomicAdd(&g_roi[(bb*NRR + rlo)*CH + c + 1], acc[j][1]);
        }
        if (rlo + 8 < NRR) {
            atomicAdd(&g_roi[(bb*NRR + rlo + 8)*CH + c    ], acc[j][2]);
            atomicAdd(&g_roi[(bb*NRR + rlo + 8)*CH + c + 1], acc[j][3]);
        }
    }
    atomicAdd(&g_msum[r0],      msl[0]);
    atomicAdd(&g_msum[r0 + 32], msl[1]);
    atomicAdd(&g_msum[r0 + 64], msl[2]);
    if (tid < 32) atomicAdd(&g_msum[96 + r0], msl[3]);
}

// ---------------- per-ROI MLPs ----------------
__global__ void mlp_kernel(const float* __restrict__ sw1, const float* __restrict__ sb1,
                           const float* __restrict__ sw2, const float* __restrict__ sb2,
                           const float* __restrict__ pw1, const float* __restrict__ pb1,
                           const float* __restrict__ pw2, const float* __restrict__ pb2,
                           float* __restrict__ out)
{
    const int b = blockIdx.x / NRR;
    const int r = blockIdx.x % NRR;
    const int tid = threadIdx.x;
    __shared__ float roi_s[32], h_s[64], sf_s[32], h2_s[256];

    if (tid < 32)
        roi_s[tid] = g_roi[(b*NRR + r)*CH + tid] / g_msum[r];
    __syncthreads();
    if (tid < 64) {
        float s = sb1[r*64 + tid];
        #pragma unroll
        for (int c = 0; c < 32; c++)
            s = fmaf(roi_s[c], sw1[(r*CH + c)*64 + tid], s);
        h_s[tid] = fmaxf(s, 0.f);
    }
    __syncthreads();
    if (tid < 32) {
        float s = sb2[r*CH + tid];
        #pragma unroll
        for (int j = 0; j < 64; j++)
            s = fmaf(h_s[j], sw2[(r*64 + j)*CH + tid], s);
        sf_s[tid] = roi_s[tid] / (1.f + expf(-s));
    }
    __syncthreads();
    {
        float s = pb1[r*RHN + tid];
        #pragma unroll
        for (int c = 0; c < 32; c++)
            s = fmaf(sf_s[c], pw1[(r*CH + c)*RHN + tid], s);
        h2_s[tid] = fmaxf(s, 0.f);
    }
    __syncthreads();
    if (tid < 128) {
        float s = pb2[r*REN + tid];
        for (int k = 0; k < 256; k++)
            s = fmaf(h2_s[k], pw2[(r*RHN + k)*REN + tid], s);
        out[(b*NRR + r)*REN + tid] = s;
    }
}

// ---------------- launch ----------------
extern "C" void kernel_launch(void* const* d_in, const int* in_sizes, int n_in,
                              void* d_out, int out_size)
{
    const float* data    = (const float*)d_in[0];
    const float* mask    = (const float*)d_in[1];
    const float* conv0_w = (const float*)d_in[2];
    const float* convk_w = (const float*)d_in[4];
    const float* sw1 = (const float*)d_in[6];
    const float* sb1 = (const float*)d_in[7];
    const float* sw2 = (const float*)d_in[8];
    const float* sb2 = (const float*)d_in[9];
    const float* pw1 = (const float*)d_in[10];
    const float* pb1 = (const float*)d_in[11];
    const float* pw2 = (const float*)d_in[12];
    const float* pb2 = (const float*)d_in[13];
    float* out = (float*)d_out;

    float* raw = nullptr;  cudaGetSymbolAddress((void**)&raw,  g_raw);
    __nv_bfloat16* padh = nullptr; cudaGetSymbolAddress((void**)&padh, g_padh);
    __nv_bfloat16* padl = nullptr; cudaGetSymbolAddress((void**)&padl, g_padl);
    __nv_bfloat16* wpre = nullptr; cudaGetSymbolAddress((void**)&wpre, g_wprep);
    float* ssum = nullptr; cudaGetSymbolAddress((void**)&ssum, g_ssum);
    float* ss0 = ssum + 0*BATCH*CH*2;
    float* ss1 = ssum + 1*BATCH*CH*2;
    float* ss2 = ssum + 2*BATCH*CH*2;
    float* ss3 = ssum + 3*BATCH*CH*2;

    const int SMEMB = 18*BTILE*2;
    cudaFuncSetAttribute(conv_mma_kernel, cudaFuncAttributeMaxDynamicSharedMemorySize, SMEMB);

    const int nnb = BATCH*VOL/256;
    const size_t LW = (size_t)9*2*BTILE;

    init_kernel<<<1, 256>>>();
    wprep_kernel<<<27, 256>>>(convk_w);

    conv0_kernel<<<nnb, 256>>>(data, conv0_w, raw);
    stats0_kernel<<<dim3(432, 2), 256>>>(raw, ss0);
    norm_split_kernel<<<nnb, 256>>>(raw, ss0, padh, padl);

    conv_mma_kernel<<<148, 768, SMEMB>>>(padh, padl, wpre + 0*LW, raw, ss1);
    norm_split_kernel<<<nnb, 256>>>(raw, ss1, padh, padl);

    conv_mma_kernel<<<148, 768, SMEMB>>>(padh, padl, wpre + 1*LW, raw, ss2);
    norm_split_kernel<<<nnb, 256>>>(raw, ss2, padh, padl);

    conv_mma_kernel<<<148, 768, SMEMB>>>(padh, padl, wpre + 2*LW, raw, ss3);
    norm_split_kernel<<<nnb, 256>>>(raw, ss3, padh, padl);

    pool_kernel<<<296, 256>>>(padh, mask);
    mlp_kernel<<<BATCH*NRR, 256>>>(sw1, sb1, sw2, sb2, pw1, pb1, pw2, pb2, out);
}

// round 11
// speedup vs baseline: 4.0175x; 1.3867x over previous
#include <cuda_runtime.h>
#include <cuda_fp16.h>
#include <math.h>
#include <stdint.h>

#define BATCH 2
#define CH    32
#define VOL   (96*96*96)
#define NRR   100
#define RHN   256
#define REN   128
#define INV_V (1.0f/884736.0f)
#define EPSN  1e-5f
#define PXD 132
#define PYD 98
#define PZD 98
#define PVOX (PZD*PYD*PXD)
#define BSTRIDE 104
#define BTILE   (32*BSTRIDE)

// ---------------- warp MMA helpers (fp16) ----------------
__device__ __forceinline__ uint32_t smem_u32(const void* p) {
    uint32_t a;
    asm("{ .reg .u64 t; cvta.to.shared.u64 t, %1; cvt.u32.u64 %0, t; }" : "=r"(a) : "l"(p));
    return a;
}
#define LDSM_X4(r0,r1,r2,r3,addr) \
    asm volatile("ldmatrix.sync.aligned.m8n8.x4.shared.b16 {%0,%1,%2,%3}, [%4];" \
        : "=r"(r0),"=r"(r1),"=r"(r2),"=r"(r3) : "r"(addr))
#define LDSM_X4_T(r0,r1,r2,r3,addr) \
    asm volatile("ldmatrix.sync.aligned.m8n8.x4.trans.shared.b16 {%0,%1,%2,%3}, [%4];" \
        : "=r"(r0),"=r"(r1),"=r"(r2),"=r"(r3) : "r"(addr))
#define MMA16816(d, a0,a1,a2,a3, b0,b1) \
    asm volatile("mma.sync.aligned.m16n8k16.row.col.f32.f16.f16.f32 " \
        "{%0,%1,%2,%3}, {%4,%5,%6,%7}, {%8,%9}, {%0,%1,%2,%3};" \
        : "+f"((d)[0]),"+f"((d)[1]),"+f"((d)[2]),"+f"((d)[3]) \
        : "r"(a0),"r"(a1),"r"(a2),"r"(a3), "r"(b0),"r"(b1))

// ---------------- scratch ----------------
__device__ float g_raw[(size_t)BATCH*VOL*CH];
__device__ __half g_pad[(size_t)BATCH*PVOX*CH];              // borders stay zero forever
__device__ __align__(16) __half g_wprep[3*9*2*BTILE];        // [L][dzdy][h/l]
__device__ float g_ssum[4][BATCH*CH][2];
__device__ float g_roi [BATCH*NRR*CH];
__device__ float g_msum[NRR];

__global__ void init_kernel() {
    int t = threadIdx.x;
    float* ss = &g_ssum[0][0][0];
    for (int i = t; i < 4*BATCH*CH*2; i += 256) ss[i] = 0.f;
    for (int i = t; i < BATCH*NRR*CH; i += 256) g_roi[i] = 0.f;
    for (int i = t; i < NRR; i += 256) g_msum[i] = 0.f;
}

// ---------------- weight prep: fp16 hi/lo tiles ----------------
__global__ void wprep_kernel(const float* __restrict__ convk_w) {
    const int L = blockIdx.x / 9;
    const int r = blockIdx.x % 9;
    const int dz = r / 3, dy = r % 3;
    __half* bh = g_wprep + ((size_t)(L*9 + r)*2 + 0)*BTILE;
    __half* bl = bh + BTILE;
    for (int i = threadIdx.x; i < 32*BSTRIDE; i += 256) {
        int co = i / BSTRIDE, k = i % BSTRIDE;
        float wv = 0.f;
        if (k < 96) {
            int dx = k >> 5, ci = k & 31;
            wv = convk_w[(size_t)((L*32 + co)*32 + ci)*27 + (dz*3 + dy)*3 + dx];
        }
        __half h = __float2half(wv);
        bh[i] = h;
        bl[i] = __float2half(wv - __half2float(h));
    }
}

// ---------------- conv0: 1->32 direct, channels-last ----------------
__global__ void conv0_kernel(const float* __restrict__ data,
                             const float* __restrict__ w0,
                             float* __restrict__ raw) {
    __shared__ float ws[27*32];
    for (int i = threadIdx.x; i < 864; i += 256) {
        int tap = i / 32, c = i % 32;
        ws[tap*32 + c] = w0[c*27 + tap];
    }
    __syncthreads();
    int v = blockIdx.x*256 + threadIdx.x;
    int b = v / VOL, s = v % VOL;
    int z = s / 9216, y = (s / 96) % 96, x = s % 96;
    const float* p = data + (size_t)b * VOL;
    float acc[32];
    #pragma unroll
    for (int q = 0; q < 32; q++) acc[q] = 0.f;
    #pragma unroll
    for (int dz = 0; dz < 3; dz++) {
        int zz = z + dz - 1; if ((unsigned)zz >= 96u) continue;
        #pragma unroll
        for (int dy = 0; dy < 3; dy++) {
            int yy = y + dy - 1; if ((unsigned)yy >= 96u) continue;
            #pragma unroll
            for (int dx = 0; dx < 3; dx++) {
                int xx = x + dx - 1; if ((unsigned)xx >= 96u) continue;
                float val = __ldg(p + ((size_t)zz*96 + yy)*96 + xx);
                const float4* wp = (const float4*)(ws + ((dz*3+dy)*3+dx)*32);
                #pragma unroll
                for (int q = 0; q < 8; q++) {
                    float4 ww = wp[q];
                    acc[q*4+0] = fmaf(val, ww.x, acc[q*4+0]);
                    acc[q*4+1] = fmaf(val, ww.y, acc[q*4+1]);
                    acc[q*4+2] = fmaf(val, ww.z, acc[q*4+2]);
                    acc[q*4+3] = fmaf(val, ww.w, acc[q*4+3]);
                }
            }
        }
    }
    float* o = raw + (size_t)v * 32;
    #pragma unroll
    for (int q = 0; q < 8; q++)
        ((float4*)o)[q] = make_float4(acc[q*4], acc[q*4+1], acc[q*4+2], acc[q*4+3]);
}

// ---------------- coalesced stats (conv0 output only) ----------------
__global__ void stats0_kernel(const float* __restrict__ raw, float* __restrict__ ss) {
    const int b = blockIdx.y;
    const int tid = threadIdx.x;
    const int lane = tid & 31;
    const float4* p = (const float4*)(raw + ((size_t)b*VOL + (size_t)blockIdx.x*2048)*32);
    float s[4] = {0,0,0,0}, q[4] = {0,0,0,0};
    for (int it = 0; it < 64; it++) {
        float4 f = p[it*256 + tid];
        s[0] += f.x; q[0] = fmaf(f.x, f.x, q[0]);
        s[1] += f.y; q[1] = fmaf(f.y, f.y, q[1]);
        s[2] += f.z; q[2] = fmaf(f.z, f.z, q[2]);
        s[3] += f.w; q[3] = fmaf(f.w, f.w, q[3]);
    }
    #pragma unroll
    for (int o = 8; o < 32; o <<= 1) {
        #pragma unroll
        for (int j = 0; j < 4; j++) {
            s[j] += __shfl_xor_sync(0xffffffffu, s[j], o);
            q[j] += __shfl_xor_sync(0xffffffffu, q[j], o);
        }
    }
    __shared__ float sa[32], qa[32];
    if (tid < 32) { sa[tid] = 0.f; qa[tid] = 0.f; }
    __syncthreads();
    if (lane < 8) {
        #pragma unroll
        for (int j = 0; j < 4; j++) {
            atomicAdd(&sa[lane*4 + j], s[j]);
            atomicAdd(&qa[lane*4 + j], q[j]);
        }
    }
    __syncthreads();
    if (tid < 32) {
        atomicAdd(&ss[(b*32 + tid)*2 + 0], sa[tid]);
        atomicAdd(&ss[(b*32 + tid)*2 + 1], qa[tid]);
    }
}

// ---------------- normalize + relu + single fp16 into padded layout ----------------
__global__ void norm_split_kernel(const float* __restrict__ raw, const float* __restrict__ ss,
                                  __half* __restrict__ pad) {
    __shared__ float na_s[64], nb_s[64];
    if (threadIdx.x < 64) {
        float s = ss[threadIdx.x*2], q = ss[threadIdx.x*2+1];
        float mm = s * INV_V;
        float var = fmaxf(q * INV_V - mm*mm, 0.f);
        float rstd = rsqrtf(var + EPSN);
        na_s[threadIdx.x] = rstd; nb_s[threadIdx.x] = -mm * rstd;
    }
    __syncthreads();
    int v = blockIdx.x*256 + threadIdx.x;
    int b = v / VOL, sidx = v % VOL;
    int z = sidx / 9216, y = (sidx / 96) % 96, x = sidx % 96;
    size_t pv = (((size_t)(b*PZD + z + 1))*PYD + (y + 1))*PXD + (x + 1);

    const float* rp = raw + (size_t)v * 32;
    const float* na = na_s + b*32;
    const float* nb = nb_s + b*32;
    uint32_t wh[16];
    #pragma unroll
    for (int j = 0; j < 16; j++) {
        float v0 = fmaxf(fmaf(rp[2*j],   na[2*j],   nb[2*j]),   0.f);
        float v1 = fmaxf(fmaf(rp[2*j+1], na[2*j+1], nb[2*j+1]), 0.f);
        __half2 h2 = __floats2half2_rn(v0, v1);
        wh[j] = *(uint32_t*)&h2;
    }
    uint4* oh = (uint4*)(pad + pv*32);
    #pragma unroll
    for (int q = 0; q < 4; q++)
        oh[q] = make_uint4(wh[q*4], wh[q*4+1], wh[q*4+2], wh[q*4+3]);
}

// ---------------- warp-MMA conv 32->32 + fused stats (fp16, 2 passes) ----------------
// 768 threads = 24 warps = 8 rows x 3 x-warps; warp = 32 voxels (2 m16 subtiles) x 32 co.
__global__ void __launch_bounds__(768, 1)
conv_mma_kernel(const __half* __restrict__ pad,
                const __half* __restrict__ wp,
                float* __restrict__ raw,
                float* __restrict__ ss)
{
    extern __shared__ __half bsm[];
    __shared__ float s_sm[64], q_sm[64];
    const int tid = threadIdx.x;
    {
        const uint4* s = (const uint4*)wp;
        uint4* d = (uint4*)bsm;
        for (int i = tid; i < 18*BTILE/8; i += 768) d[i] = s[i];
    }
    if (tid < 64) { s_sm[tid] = 0.f; q_sm[tid] = 0.f; }
    __syncthreads();

    const uint32_t bbase0 = smem_u32(bsm);
    const int lane = tid & 31;
    const int warp = tid >> 5;
    const int rowsel = warp / 3;          // 0..7
    const int x0 = (warp % 3) * 32;
    const int tg  = lane & 3;
    const int gid = lane >> 2;
    const int bg = lane >> 3;
    const int b_n  = ((bg >> 1) << 3) + (lane & 7);
    const int b_kh = bg & 1;

    for (int t = blockIdx.x; t < BATCH*96*12; t += gridDim.x) {
        const int b  = t / (96*12);
        const int rm = t % (96*12);
        const int z  = rm / 12;
        const int y  = (rm % 12)*8 + rowsel;

        float dacc[2][4][4];
        #pragma unroll
        for (int st = 0; st < 2; st++)
            #pragma unroll
            for (int nt = 0; nt < 4; nt++)
                #pragma unroll
                for (int j = 0; j < 4; j++) dacc[st][nt][j] = 0.f;

        #pragma unroll 1
        for (int r = 0; r < 9; r++) {
            const int dz = r / 3, dy = r % 3;
            const size_t rowb = (((size_t)(b*PZD + z + dz))*PYD + (y + dy))*PXD;
            const uint32_t bb_h = bbase0 + (uint32_t)(r*2 + 0)*(BTILE*2);
            const uint32_t bb_l = bbase0 + (uint32_t)(r*2 + 1)*(BTILE*2);

            #pragma unroll
            for (int kc = 0; kc < 6; kc++) {
                const int dx = kc >> 1;
                const int j0 = (kc & 1)*16;

                const uint32_t ko = (uint32_t)(kc*32 + b_kh*16);
                const uint32_t ro = (uint32_t)b_n * (BSTRIDE*2) + ko;
                uint32_t bh[8], bl[8];
                LDSM_X4(bh[0],bh[1],bh[2],bh[3], bb_h + ro);
                LDSM_X4(bh[4],bh[5],bh[6],bh[7], bb_h + ro + 16u*(BSTRIDE*2));
                LDSM_X4(bl[0],bl[1],bl[2],bl[3], bb_l + ro);
                LDSM_X4(bl[4],bl[5],bl[6],bl[7], bb_l + ro + 16u*(BSTRIDE*2));

                #pragma unroll
                for (int st = 0; st < 2; st++) {
                    const size_t ab = (rowb + (size_t)(x0 + st*16 + gid + dx))*32 + j0 + tg*2;
                    uint32_t ah0 = *(const uint32_t*)(pad + ab);
                    uint32_t ah1 = *(const uint32_t*)(pad + ab + 256);
                    uint32_t ah2 = *(const uint32_t*)(pad + ab + 8);
                    uint32_t ah3 = *(const uint32_t*)(pad + ab + 264);
                    #pragma unroll
                    for (int nt = 0; nt < 4; nt++) {
                        MMA16816(dacc[st][nt], ah0,ah1,ah2,ah3, bh[nt*2], bh[nt*2+1]);
                        MMA16816(dacc[st][nt], ah0,ah1,ah2,ah3, bl[nt*2], bl[nt*2+1]);
                    }
                }
            }
        }

        #pragma unroll
        for (int st = 0; st < 2; st++) {
            float* orow = raw + ((size_t)b*VOL + (size_t)z*9216 + (size_t)y*96 + x0 + st*16)*32;
            #pragma unroll
            for (int nt = 0; nt < 4; nt++) {
                const int col = nt*8 + tg*2;
                *(float2*)(orow + (size_t)gid*32 + col)      = make_float2(dacc[st][nt][0], dacc[st][nt][1]);
                *(float2*)(orow + (size_t)(gid+8)*32 + col)  = make_float2(dacc[st][nt][2], dacc[st][nt][3]);
            }
        }

        // fused stats over both subtiles
        float sv[8], qv[8];
        #pragma unroll
        for (int nt = 0; nt < 4; nt++) {
            sv[nt*2+0] = (dacc[0][nt][0] + dacc[0][nt][2]) + (dacc[1][nt][0] + dacc[1][nt][2]);
            sv[nt*2+1] = (dacc[0][nt][1] + dacc[0][nt][3]) + (dacc[1][nt][1] + dacc[1][nt][3]);
            float q0 = fmaf(dacc[0][nt][0], dacc[0][nt][0], dacc[0][nt][2]*dacc[0][nt][2]);
            float q1 = fmaf(dacc[0][nt][1], dacc[0][nt][1], dacc[0][nt][3]*dacc[0][nt][3]);
            qv[nt*2+0] = fmaf(dacc[1][nt][0], dacc[1][nt][0], fmaf(dacc[1][nt][2], dacc[1][nt][2], q0));
            qv[nt*2+1] = fmaf(dacc[1][nt][1], dacc[1][nt][1], fmaf(dacc[1][nt][3], dacc[1][nt][3], q1));
        }
        #pragma unroll
        for (int o = 4; o < 32; o <<= 1) {
            #pragma unroll
            for (int j = 0; j < 8; j++) {
                sv[j] += __shfl_xor_sync(0xffffffffu, sv[j], o);
                qv[j] += __shfl_xor_sync(0xffffffffu, qv[j], o);
            }
        }
        if (gid == 0) {
            #pragma unroll
            for (int nt = 0; nt < 4; nt++) {
                int c = b*32 + nt*8 + tg*2;
                atomicAdd(&s_sm[c],   sv[nt*2+0]);
                atomicAdd(&s_sm[c+1], sv[nt*2+1]);
                atomicAdd(&q_sm[c],   qv[nt*2+0]);
                atomicAdd(&q_sm[c+1], qv[nt*2+1]);
            }
        }
    }
    __syncthreads();
    if (tid < 64) {
        atomicAdd(&ss[tid*2 + 0], s_sm[tid]);
        atomicAdd(&ss[tid*2 + 1], q_sm[tid]);
    }
}

// ---------------- pool as warp-MMA GEMM (fp16) ----------------
__global__ void __launch_bounds__(256, 2)
pool_kernel(const __half* __restrict__ pad,
            const float* __restrict__ mask)
{
    __shared__ __half a_sm[128*40];
    __shared__ __half e_sm[2*32*40];

    const int tid  = threadIdx.x;
    const int lane = tid & 31;
    const int warp = tid >> 5;
    const int m0   = warp * 16;
    const int r0   = tid >> 3;
    const int vq   = tid & 7;

    for (int i = tid; i < 28*40; i += 256)
        a_sm[100*40 + i] = __float2half(0.f);

    float acc[8][4];
    #pragma unroll
    for (int j = 0; j < 8; j++)
        #pragma unroll
        for (int q = 0; q < 4; q++) acc[j][q] = 0.f;
    float msl[4] = {0.f, 0.f, 0.f, 0.f};

    const uint32_t abase = smem_u32(a_sm);
    const uint32_t ebase = smem_u32(e_sm);
    const int nch = VOL / 32;

    for (int chn = blockIdx.x; chn < nch; chn += gridDim.x) {
        const int v0 = chn * 32;
        const int z  = v0 / 9216;
        const int y  = (v0 / 96) % 96;
        const int x0 = v0 % 96;
        __syncthreads();

        #pragma unroll
        for (int j = 0; j < 4; j++) {
            if (j == 3 && tid >= 32) break;
            const int r = r0 + j*32;
            float4 f = *(const float4*)(mask + (size_t)r*VOL + v0 + vq*4);
            msl[j] += (f.x + f.y) + (f.z + f.w);
            __half2 h0 = __floats2half2_rn(f.x, f.y);
            __half2 h1 = __floats2half2_rn(f.z, f.w);
            uint32_t p0 = *(uint32_t*)&h0;
            uint32_t p1 = *(uint32_t*)&h1;
            asm volatile("st.shared.v2.b32 [%0], {%1, %2};"
                :: "r"(abase + (uint32_t)(r*80 + vq*8)), "r"(p0), "r"(p1) : "memory");
        }

        // e tiles: 2 regions (b=0,1) x 128 uint4
        {
            const int i = tid;
            const int bb  = i >> 7;
            const int idx = i & 127;
            const int v   = idx >> 2;
            const int cq  = idx & 3;
            const __half* src = pad
                + ((((size_t)(bb*PZD + z + 1))*PYD + (y + 1))*PXD + (x0 + 1) + v)*32;
            uint4 val = *(const uint4*)(src + cq*8);
            *(uint4*)((char*)e_sm + (size_t)(bb*32 + v)*80 + cq*16) = val;
        }
        __syncthreads();

        #pragma unroll
        for (int ks = 0; ks < 2; ks++) {
            uint32_t a0, a1, a2, a3;
            LDSM_X4(a0, a1, a2, a3,
                abase + (uint32_t)((m0 + (lane & 15))*80 + ks*32 + (lane >> 4)*16));
            #pragma unroll
            for (int bb = 0; bb < 2; bb++) {
                const uint32_t eb = ebase + (uint32_t)((bb*32 + ks*16)*80)
                                 + (uint32_t)((lane & 15)*80 + (lane >> 4)*16);
                uint32_t b0,b1,b2,b3, c0,c1,c2,c3;
                LDSM_X4_T(b0, b1, b2, b3, eb);
                LDSM_X4_T(c0, c1, c2, c3, eb + 32);
                const int j0 = bb*4;
                MMA16816(acc[j0+0], a0,a1,a2,a3, b0,b1);
                MMA16816(acc[j0+1], a0,a1,a2,a3, b2,b3);
                MMA16816(acc[j0+2], a0,a1,a2,a3, c0,c1);
                MMA16816(acc[j0+3], a0,a1,a2,a3, c2,c3);
            }
        }
    }

    const int rlo = m0 + (lane >> 2);
    const int cc  = (lane & 3) * 2;
    #pragma unroll
    for (int j = 0; j < 8; j++) {
        const int bb = j >> 2, q = j & 3;
        const int c = q*8 + cc;
        if (rlo < NRR) {
            atomicAdd(&g_roi[(bb*NRR + rlo)*CH + c    ], acc[j][0]);
            atomicAdd(&g_roi[(bb*NRR + rlo)*CH + c + 1], acc[j][1]);
        }
        if (rlo + 8 < NRR) {
            atomicAdd(&g_roi[(bb*NRR + rlo + 8)*CH + c    ], acc[j][2]);
            atomicAdd(&g_roi[(bb*NRR + rlo + 8)*CH + c + 1], acc[j][3]);
        }
    }
    atomicAdd(&g_msum[r0],      msl[0]);
    atomicAdd(&g_msum[r0 + 32], msl[1]);
    atomicAdd(&g_msum[r0 + 64], msl[2]);
    if (tid < 32) atomicAdd(&g_msum[96 + r0], msl[3]);
}

// ---------------- per-ROI MLPs ----------------
__global__ void mlp_kernel(const float* __restrict__ sw1, const float* __restrict__ sb1,
                           const float* __restrict__ sw2, const float* __restrict__ sb2,
                           const float* __restrict__ pw1, const float* __restrict__ pb1,
                           const float* __restrict__ pw2, const float* __restrict__ pb2,
                           float* __restrict__ out)
{
    const int b = blockIdx.x / NRR;
    const int r = blockIdx.x % NRR;
    const int tid = threadIdx.x;
    __shared__ float roi_s[32], h_s[64], sf_s[32], h2_s[256];

    if (tid < 32)
        roi_s[tid] = g_roi[(b*NRR + r)*CH + tid] / g_msum[r];
    __syncthreads();
    if (tid < 64) {
        float s = sb1[r*64 + tid];
        #pragma unroll
        for (int c = 0; c < 32; c++)
            s = fmaf(roi_s[c], sw1[(r*CH + c)*64 + tid], s);
        h_s[tid] = fmaxf(s, 0.f);
    }
    __syncthreads();
    if (tid < 32) {
        float s = sb2[r*CH + tid];
        #pragma unroll
        for (int j = 0; j < 64; j++)
            s = fmaf(h_s[j], sw2[(r*64 + j)*CH + tid], s);
        sf_s[tid] = roi_s[tid] / (1.f + expf(-s));
    }
    __syncthreads();
    {
        float s = pb1[r*RHN + tid];
        #pragma unroll
        for (int c = 0; c < 32; c++)
            s = fmaf(sf_s[c], pw1[(r*CH + c)*RHN + tid], s);
        h2_s[tid] = fmaxf(s, 0.f);
    }
    __syncthreads();
    if (tid < 128) {
        float s = pb2[r*REN + tid];
        for (int k = 0; k < 256; k++)
            s = fmaf(h2_s[k], pw2[(r*RHN + k)*REN + tid], s);
        out[(b*NRR + r)*REN + tid] = s;
    }
}

// ---------------- launch ----------------
extern "C" void kernel_launch(void* const* d_in, const int* in_sizes, int n_in,
                              void* d_out, int out_size)
{
    const float* data    = (const float*)d_in[0];
    const float* mask    = (const float*)d_in[1];
    const float* conv0_w = (const float*)d_in[2];
    const float* convk_w = (const float*)d_in[4];
    const float* sw1 = (const float*)d_in[6];
    const float* sb1 = (const float*)d_in[7];
    const float* sw2 = (const float*)d_in[8];
    const float* sb2 = (const float*)d_in[9];
    const float* pw1 = (const float*)d_in[10];
    const float* pb1 = (const float*)d_in[11];
    const float* pw2 = (const float*)d_in[12];
    const float* pb2 = (const float*)d_in[13];
    float* out = (float*)d_out;

    float* raw = nullptr;  cudaGetSymbolAddress((void**)&raw,  g_raw);
    __half* pad = nullptr; cudaGetSymbolAddress((void**)&pad, g_pad);
    __half* wpre = nullptr; cudaGetSymbolAddress((void**)&wpre, g_wprep);
    float* ssum = nullptr; cudaGetSymbolAddress((void**)&ssum, g_ssum);
    float* ss0 = ssum + 0*BATCH*CH*2;
    float* ss1 = ssum + 1*BATCH*CH*2;
    float* ss2 = ssum + 2*BATCH*CH*2;
    float* ss3 = ssum + 3*BATCH*CH*2;

    const int SMEMB = 18*BTILE*2;
    cudaFuncSetAttribute(conv_mma_kernel, cudaFuncAttributeMaxDynamicSharedMemorySize, SMEMB);

    const int nnb = BATCH*VOL/256;
    const size_t LW = (size_t)9*2*BTILE;

    init_kernel<<<1, 256>>>();
    wprep_kernel<<<27, 256>>>(convk_w);

    conv0_kernel<<<nnb, 256>>>(data, conv0_w, raw);
    stats0_kernel<<<dim3(432, 2), 256>>>(raw, ss0);
    norm_split_kernel<<<nnb, 256>>>(raw, ss0, pad);

    conv_mma_kernel<<<148, 768, SMEMB>>>(pad, wpre + 0*LW, raw, ss1);
    norm_split_kernel<<<nnb, 256>>>(raw, ss1, pad);

    conv_mma_kernel<<<148, 768, SMEMB>>>(pad, wpre + 1*LW, raw, ss2);
    norm_split_kernel<<<nnb, 256>>>(raw, ss2, pad);

    conv_mma_kernel<<<148, 768, SMEMB>>>(pad, wpre + 2*LW, raw, ss3);
    norm_split_kernel<<<nnb, 256>>>(raw, ss3, pad);

    pool_kernel<<<296, 256>>>(pad, mask);
    mlp_kernel<<<BATCH*NRR, 256>>>(sw1, sb1, sw2, sb2, pw1, pb1, pw2, pb2, out);
}

// round 12
// speedup vs baseline: 5.1275x; 1.2763x over previous
#include <cuda_runtime.h>
#include <cuda_fp16.h>
#include <math.h>
#include <stdint.h>

#define BATCH 2
#define CH    32
#define VOL   (96*96*96)
#define NRR   100
#define RHN   256
#define REN   128
#define INV_V (1.0f/884736.0f)
#define EPSN  1e-5f
#define PXD 132
#define PYD 98
#define PZD 98
#define PVOX (PZD*PYD*PXD)
#define BSTRIDE 104
#define BTILE   (32*BSTRIDE)

// ---------------- warp MMA helpers (fp16) ----------------
__device__ __forceinline__ uint32_t smem_u32(const void* p) {
    uint32_t a;
    asm("{ .reg .u64 t; cvta.to.shared.u64 t, %1; cvt.u32.u64 %0, t; }" : "=r"(a) : "l"(p));
    return a;
}
#define LDSM_X4(r0,r1,r2,r3,addr) \
    asm volatile("ldmatrix.sync.aligned.m8n8.x4.shared.b16 {%0,%1,%2,%3}, [%4];" \
        : "=r"(r0),"=r"(r1),"=r"(r2),"=r"(r3) : "r"(addr))
#define LDSM_X4_T(r0,r1,r2,r3,addr) \
    asm volatile("ldmatrix.sync.aligned.m8n8.x4.trans.shared.b16 {%0,%1,%2,%3}, [%4];" \
        : "=r"(r0),"=r"(r1),"=r"(r2),"=r"(r3) : "r"(addr))
#define MMA16816(d, a0,a1,a2,a3, b0,b1) \
    asm volatile("mma.sync.aligned.m16n8k16.row.col.f32.f16.f16.f32 " \
        "{%0,%1,%2,%3}, {%4,%5,%6,%7}, {%8,%9}, {%0,%1,%2,%3};" \
        : "+f"((d)[0]),"+f"((d)[1]),"+f"((d)[2]),"+f"((d)[3]) \
        : "r"(a0),"r"(a1),"r"(a2),"r"(a3), "r"(b0),"r"(b1))

__device__ __forceinline__ uint32_t packh2(float a, float b) {
    __half2 h = __floats2half2_rn(a, b);
    return *(uint32_t*)&h;
}
__device__ __forceinline__ float2 unph2(uint32_t u) {
    return __half22float2(*(__half2*)&u);
}

// ---------------- scratch ----------------
__device__ __half g_raw[(size_t)BATCH*VOL*CH];               // channels-last conv out (fp16)
__device__ __half g_pad[(size_t)BATCH*PVOX*CH];              // borders stay zero forever
__device__ __align__(16) __half g_wprep[3*9*2*BTILE];        // [L][dzdy][h/l]
__device__ float g_ssum[4][BATCH*CH][2];
__device__ float g_roi [BATCH*NRR*CH];
__device__ float g_msum[NRR];

__global__ void init_kernel() {
    int t = threadIdx.x;
    float* ss = &g_ssum[0][0][0];
    for (int i = t; i < 4*BATCH*CH*2; i += 256) ss[i] = 0.f;
    for (int i = t; i < BATCH*NRR*CH; i += 256) g_roi[i] = 0.f;
    for (int i = t; i < NRR; i += 256) g_msum[i] = 0.f;
}

// ---------------- weight prep: fp16 hi/lo tiles ----------------
__global__ void wprep_kernel(const float* __restrict__ convk_w) {
    const int L = blockIdx.x / 9;
    const int r = blockIdx.x % 9;
    const int dz = r / 3, dy = r % 3;
    __half* bh = g_wprep + ((size_t)(L*9 + r)*2 + 0)*BTILE;
    __half* bl = bh + BTILE;
    for (int i = threadIdx.x; i < 32*BSTRIDE; i += 256) {
        int co = i / BSTRIDE, k = i % BSTRIDE;
        float wv = 0.f;
        if (k < 96) {
            int dx = k >> 5, ci = k & 31;
            wv = convk_w[(size_t)((L*32 + co)*32 + ci)*27 + (dz*3 + dy)*3 + dx];
        }
        __half h = __float2half(wv);
        bh[i] = h;
        bl[i] = __float2half(wv - __half2float(h));
    }
}

// ---------------- conv0: 1->32 direct, channels-last fp16 out ----------------
__global__ void conv0_kernel(const float* __restrict__ data,
                             const float* __restrict__ w0,
                             __half* __restrict__ raw) {
    __shared__ float ws[27*32];
    for (int i = threadIdx.x; i < 864; i += 256) {
        int tap = i / 32, c = i % 32;
        ws[tap*32 + c] = w0[c*27 + tap];
    }
    __syncthreads();
    int v = blockIdx.x*256 + threadIdx.x;
    int b = v / VOL, s = v % VOL;
    int z = s / 9216, y = (s / 96) % 96, x = s % 96;
    const float* p = data + (size_t)b * VOL;
    float acc[32];
    #pragma unroll
    for (int q = 0; q < 32; q++) acc[q] = 0.f;
    #pragma unroll
    for (int dz = 0; dz < 3; dz++) {
        int zz = z + dz - 1; if ((unsigned)zz >= 96u) continue;
        #pragma unroll
        for (int dy = 0; dy < 3; dy++) {
            int yy = y + dy - 1; if ((unsigned)yy >= 96u) continue;
            #pragma unroll
            for (int dx = 0; dx < 3; dx++) {
                int xx = x + dx - 1; if ((unsigned)xx >= 96u) continue;
                float val = __ldg(p + ((size_t)zz*96 + yy)*96 + xx);
                const float4* wp = (const float4*)(ws + ((dz*3+dy)*3+dx)*32);
                #pragma unroll
                for (int q = 0; q < 8; q++) {
                    float4 ww = wp[q];
                    acc[q*4+0] = fmaf(val, ww.x, acc[q*4+0]);
                    acc[q*4+1] = fmaf(val, ww.y, acc[q*4+1]);
                    acc[q*4+2] = fmaf(val, ww.z, acc[q*4+2]);
                    acc[q*4+3] = fmaf(val, ww.w, acc[q*4+3]);
                }
            }
        }
    }
    uint4* o = (uint4*)(raw + (size_t)v * 32);
    #pragma unroll
    for (int q = 0; q < 4; q++)
        o[q] = make_uint4(packh2(acc[q*8+0], acc[q*8+1]), packh2(acc[q*8+2], acc[q*8+3]),
                          packh2(acc[q*8+4], acc[q*8+5]), packh2(acc[q*8+6], acc[q*8+7]));
}

// ---------------- coalesced stats over fp16 raw (conv0 output only) ----------------
__global__ void stats0_kernel(const __half* __restrict__ raw, float* __restrict__ ss) {
    const int b = blockIdx.y;
    const int tid = threadIdx.x;
    const int lane = tid & 31;
    const uint4* p = (const uint4*)(raw + ((size_t)b*VOL + (size_t)blockIdx.x*2048)*32);
    float s[8] = {0,0,0,0,0,0,0,0}, q[8] = {0,0,0,0,0,0,0,0};
    for (int it = 0; it < 32; it++) {
        uint4 f = p[it*256 + tid];
        float2 v0 = unph2(f.x), v1 = unph2(f.y), v2 = unph2(f.z), v3 = unph2(f.w);
        s[0] += v0.x; q[0] = fmaf(v0.x, v0.x, q[0]);
        s[1] += v0.y; q[1] = fmaf(v0.y, v0.y, q[1]);
        s[2] += v1.x; q[2] = fmaf(v1.x, v1.x, q[2]);
        s[3] += v1.y; q[3] = fmaf(v1.y, v1.y, q[3]);
        s[4] += v2.x; q[4] = fmaf(v2.x, v2.x, q[4]);
        s[5] += v2.y; q[5] = fmaf(v2.y, v2.y, q[5]);
        s[6] += v3.x; q[6] = fmaf(v3.x, v3.x, q[6]);
        s[7] += v3.y; q[7] = fmaf(v3.y, v3.y, q[7]);
    }
    // lanes sharing lane%4 hold channels (lane%4)*8..+8
    #pragma unroll
    for (int o = 4; o < 32; o <<= 1) {
        #pragma unroll
        for (int j = 0; j < 8; j++) {
            s[j] += __shfl_xor_sync(0xffffffffu, s[j], o);
            q[j] += __shfl_xor_sync(0xffffffffu, q[j], o);
        }
    }
    __shared__ float sa[32], qa[32];
    if (tid < 32) { sa[tid] = 0.f; qa[tid] = 0.f; }
    __syncthreads();
    if (lane < 4) {
        #pragma unroll
        for (int j = 0; j < 8; j++) {
            atomicAdd(&sa[lane*8 + j], s[j]);
            atomicAdd(&qa[lane*8 + j], q[j]);
        }
    }
    __syncthreads();
    if (tid < 32) {
        atomicAdd(&ss[(b*32 + tid)*2 + 0], sa[tid]);
        atomicAdd(&ss[(b*32 + tid)*2 + 1], qa[tid]);
    }
}

// ---------------- normalize + relu (fp16 raw -> fp16 padded) ----------------
__global__ void norm_split_kernel(const __half* __restrict__ raw, const float* __restrict__ ss,
                                  __half* __restrict__ pad) {
    __shared__ float na_s[64], nb_s[64];
    if (threadIdx.x < 64) {
        float s = ss[threadIdx.x*2], q = ss[threadIdx.x*2+1];
        float mm = s * INV_V;
        float var = fmaxf(q * INV_V - mm*mm, 0.f);
        float rstd = rsqrtf(var + EPSN);
        na_s[threadIdx.x] = rstd; nb_s[threadIdx.x] = -mm * rstd;
    }
    __syncthreads();
    int v = blockIdx.x*256 + threadIdx.x;
    int b = v / VOL, sidx = v % VOL;
    int z = sidx / 9216, y = (sidx / 96) % 96, x = sidx % 96;
    size_t pv = (((size_t)(b*PZD + z + 1))*PYD + (y + 1))*PXD + (x + 1);

    const uint4* rp = (const uint4*)(raw + (size_t)v * 32);
    const float* na = na_s + b*32;
    const float* nb = nb_s + b*32;
    uint4* oh = (uint4*)(pad + pv*32);
    #pragma unroll
    for (int q = 0; q < 4; q++) {
        uint4 f = rp[q];
        uint32_t w[4];
        uint32_t in[4] = { f.x, f.y, f.z, f.w };
        #pragma unroll
        for (int j = 0; j < 4; j++) {
            float2 vv = unph2(in[j]);
            int c = q*8 + j*2;
            float v0 = fmaxf(fmaf(vv.x, na[c],   nb[c]),   0.f);
            float v1 = fmaxf(fmaf(vv.y, na[c+1], nb[c+1]), 0.f);
            w[j] = packh2(v0, v1);
        }
        oh[q] = make_uint4(w[0], w[1], w[2], w[3]);
    }
}

// ---------------- warp-MMA conv 32->32 + fused stats (fp16, 2 passes) ----------------
__global__ void __launch_bounds__(768, 1)
conv_mma_kernel(const __half* __restrict__ pad,
                const __half* __restrict__ wp,
                __half* __restrict__ raw,
                float* __restrict__ ss)
{
    extern __shared__ __half bsm[];
    __shared__ float s_sm[64], q_sm[64];
    const int tid = threadIdx.x;
    {
        const uint4* s = (const uint4*)wp;
        uint4* d = (uint4*)bsm;
        for (int i = tid; i < 18*BTILE/8; i += 768) d[i] = s[i];
    }
    if (tid < 64) { s_sm[tid] = 0.f; q_sm[tid] = 0.f; }
    __syncthreads();

    const uint32_t bbase0 = smem_u32(bsm);
    const int lane = tid & 31;
    const int warp = tid >> 5;
    const int rowsel = warp / 3;          // 0..7
    const int x0 = (warp % 3) * 32;
    const int tg  = lane & 3;
    const int gid = lane >> 2;
    const int bg = lane >> 3;
    const int b_n  = ((bg >> 1) << 3) + (lane & 7);
    const int b_kh = bg & 1;

    for (int t = blockIdx.x; t < BATCH*96*12; t += gridDim.x) {
        const int b  = t / (96*12);
        const int rm = t % (96*12);
        const int z  = rm / 12;
        const int y  = (rm % 12)*8 + rowsel;

        float dacc[2][4][4];
        #pragma unroll
        for (int st = 0; st < 2; st++)
            #pragma unroll
            for (int nt = 0; nt < 4; nt++)
                #pragma unroll
                for (int j = 0; j < 4; j++) dacc[st][nt][j] = 0.f;

        #pragma unroll 1
        for (int r = 0; r < 9; r++) {
            const int dz = r / 3, dy = r % 3;
            const size_t rowb = (((size_t)(b*PZD + z + dz))*PYD + (y + dy))*PXD;
            const uint32_t bb_h = bbase0 + (uint32_t)(r*2 + 0)*(BTILE*2);
            const uint32_t bb_l = bbase0 + (uint32_t)(r*2 + 1)*(BTILE*2);

            #pragma unroll
            for (int kc = 0; kc < 6; kc++) {
                const int dx = kc >> 1;
                const int j0 = (kc & 1)*16;

                const uint32_t ko = (uint32_t)(kc*32 + b_kh*16);
                const uint32_t ro = (uint32_t)b_n * (BSTRIDE*2) + ko;
                uint32_t bh[8], bl[8];
                LDSM_X4(bh[0],bh[1],bh[2],bh[3], bb_h + ro);
                LDSM_X4(bh[4],bh[5],bh[6],bh[7], bb_h + ro + 16u*(BSTRIDE*2));
                LDSM_X4(bl[0],bl[1],bl[2],bl[3], bb_l + ro);
                LDSM_X4(bl[4],bl[5],bl[6],bl[7], bb_l + ro + 16u*(BSTRIDE*2));

                #pragma unroll
                for (int st = 0; st < 2; st++) {
                    const size_t ab = (rowb + (size_t)(x0 + st*16 + gid + dx))*32 + j0 + tg*2;
                    uint32_t ah0 = *(const uint32_t*)(pad + ab);
                    uint32_t ah1 = *(const uint32_t*)(pad + ab + 256);
                    uint32_t ah2 = *(const uint32_t*)(pad + ab + 8);
                    uint32_t ah3 = *(const uint32_t*)(pad + ab + 264);
                    #pragma unroll
                    for (int nt = 0; nt < 4; nt++) {
                        MMA16816(dacc[st][nt], ah0,ah1,ah2,ah3, bh[nt*2], bh[nt*2+1]);
                        MMA16816(dacc[st][nt], ah0,ah1,ah2,ah3, bl[nt*2], bl[nt*2+1]);
                    }
                }
            }
        }

        #pragma unroll
        for (int st = 0; st < 2; st++) {
            __half* orow = raw + ((size_t)b*VOL + (size_t)z*9216 + (size_t)y*96 + x0 + st*16)*32;
            #pragma unroll
            for (int nt = 0; nt < 4; nt++) {
                const int col = nt*8 + tg*2;
                *(uint32_t*)(orow + (size_t)gid*32 + col)     = packh2(dacc[st][nt][0], dacc[st][nt][1]);
                *(uint32_t*)(orow + (size_t)(gid+8)*32 + col) = packh2(dacc[st][nt][2], dacc[st][nt][3]);
            }
        }

        // fused stats over both subtiles
        float sv[8], qv[8];
        #pragma unroll
        for (int nt = 0; nt < 4; nt++) {
            sv[nt*2+0] = (dacc[0][nt][0] + dacc[0][nt][2]) + (dacc[1][nt][0] + dacc[1][nt][2]);
            sv[nt*2+1] = (dacc[0][nt][1] + dacc[0][nt][3]) + (dacc[1][nt][1] + dacc[1][nt][3]);
            float q0 = fmaf(dacc[0][nt][0], dacc[0][nt][0], dacc[0][nt][2]*dacc[0][nt][2]);
            float q1 = fmaf(dacc[0][nt][1], dacc[0][nt][1], dacc[0][nt][3]*dacc[0][nt][3]);
            qv[nt*2+0] = fmaf(dacc[1][nt][0], dacc[1][nt][0], fmaf(dacc[1][nt][2], dacc[1][nt][2], q0));
            qv[nt*2+1] = fmaf(dacc[1][nt][1], dacc[1][nt][1], fmaf(dacc[1][nt][3], dacc[1][nt][3], q1));
        }
        #pragma unroll
        for (int o = 4; o < 32; o <<= 1) {
            #pragma unroll
            for (int j = 0; j < 8; j++) {
                sv[j] += __shfl_xor_sync(0xffffffffu, sv[j], o);
                qv[j] += __shfl_xor_sync(0xffffffffu, qv[j], o);
            }
        }
        if (gid == 0) {
            #pragma unroll
            for (int nt = 0; nt < 4; nt++) {
                int c = b*32 + nt*8 + tg*2;
                atomicAdd(&s_sm[c],   sv[nt*2+0]);
                atomicAdd(&s_sm[c+1], sv[nt*2+1]);
                atomicAdd(&q_sm[c],   qv[nt*2+0]);
                atomicAdd(&q_sm[c+1], qv[nt*2+1]);
            }
        }
    }
    __syncthreads();
    if (tid < 64) {
        atomicAdd(&ss[tid*2 + 0], s_sm[tid]);
        atomicAdd(&ss[tid*2 + 1], q_sm[tid]);
    }
}

// ---------------- pool as warp-MMA GEMM, 96-voxel row chunks ----------------
#define ASTR 104                               // a_sm row stride (elems); 208B conflict-free
__global__ void __launch_bounds__(256, 2)
pool_kernel(const __half* __restrict__ pad,
            const float* __restrict__ mask)
{
    __shared__ __half a_sm[128*ASTR];          // mask rows [128][96used]
    __shared__ __half e_sm[2*96*40];           // [bb][v][c] stride 40

    const int tid  = threadIdx.x;
    const int lane = tid & 31;
    const int warp = tid >> 5;
    const int m0   = warp * 16;

    for (int i = tid; i < 28*ASTR; i += 256)
        a_sm[100*ASTR + i] = __float2half(0.f);

    float acc[8][4];
    #pragma unroll
    for (int j = 0; j < 8; j++)
        #pragma unroll
        for (int q = 0; q < 4; q++) acc[j][q] = 0.f;
    float msl[10];
    #pragma unroll
    for (int k = 0; k < 10; k++) msl[k] = 0.f;

    const uint32_t abase = smem_u32(a_sm);
    const uint32_t ebase = smem_u32(e_sm);
    const int nch = VOL / 96;                  // 9216 rows

    for (int chn = blockIdx.x; chn < nch; chn += gridDim.x) {
        const int v0 = chn * 96;
        const int z  = chn / 96;
        const int y  = chn % 96;
        __syncthreads();

        // mask rows -> fp16 smem (+ per-(thread,k) row-sum accumulators)
        {
            int k = 0;
            for (int u = tid; u < 2400; u += 256, k++) {
                const int r = u / 24, vq = u % 24;
                float4 f = *(const float4*)(mask + (size_t)r*VOL + v0 + vq*4);
                msl[k] += (f.x + f.y) + (f.z + f.w);
                uint32_t p0 = packh2(f.x, f.y);
                uint32_t p1 = packh2(f.z, f.w);
                asm volatile("st.shared.v2.b32 [%0], {%1, %2};"
                    :: "r"(abase + (uint32_t)(r*(ASTR*2) + vq*8)), "r"(p0), "r"(p1) : "memory");
            }
        }

        // e tiles: 2 bb x 96 v x 4 cq = 768 uint4
        #pragma unroll
        for (int ii = 0; ii < 3; ii++) {
            const int i = tid + ii*256;
            const int bb  = i / 384;
            const int rem = i % 384;
            const int v   = rem >> 2;
            const int cq  = rem & 3;
            const __half* src = pad
                + ((((size_t)(bb*PZD + z + 1))*PYD + (y + 1))*PXD + 1 + v)*32;
            uint4 val = *(const uint4*)(src + cq*8);
            *(uint4*)((char*)e_sm + (size_t)(bb*96 + v)*80 + cq*16) = val;
        }
        __syncthreads();

        #pragma unroll
        for (int ks = 0; ks < 6; ks++) {
            uint32_t a0, a1, a2, a3;
            LDSM_X4(a0, a1, a2, a3,
                abase + (uint32_t)((m0 + (lane & 15))*(ASTR*2) + ks*32 + (lane >> 4)*16));
            #pragma unroll
            for (int bb = 0; bb < 2; bb++) {
                const uint32_t eb = ebase + (uint32_t)((bb*96 + ks*16)*80)
                                 + (uint32_t)((lane & 15)*80 + (lane >> 4)*16);
                uint32_t b0,b1,b2,b3, c0,c1,c2,c3;
                LDSM_X4_T(b0, b1, b2, b3, eb);
                LDSM_X4_T(c0, c1, c2, c3, eb + 32);
                const int j0 = bb*4;
                MMA16816(acc[j0+0], a0,a1,a2,a3, b0,b1);
                MMA16816(acc[j0+1], a0,a1,a2,a3, b2,b3);
                MMA16816(acc[j0+2], a0,a1,a2,a3, c0,c1);
                MMA16816(acc[j0+3], a0,a1,a2,a3, c2,c3);
            }
        }
    }

    const int rlo = m0 + (lane >> 2);
    const int cc  = (lane & 3) * 2;
    #pragma unroll
    for (int j = 0; j < 8; j++) {
        const int bb = j >> 2, q = j & 3;
        const int c = q*8 + cc;
        if (rlo < NRR) {
            atomicAdd(&g_roi[(bb*NRR + rlo)*CH + c    ], acc[j][0]);
            atomicAdd(&g_roi[(bb*NRR + rlo)*CH + c + 1], acc[j][1]);
        }
        if (rlo + 8 < NRR) {
            atomicAdd(&g_roi[(bb*NRR + rlo + 8)*CH + c    ], acc[j][2]);
            atomicAdd(&g_roi[(bb*NRR + rlo + 8)*CH + c + 1], acc[j][3]);
        }
    }
    {
        int k = 0;
        for (int u = tid; u < 2400; u += 256, k++) {
            const int r = u / 24;
            atomicAdd(&g_msum[r], msl[k]);
        }
    }
}

// ---------------- per-ROI MLPs ----------------
__global__ void mlp_kernel(const float* __restrict__ sw1, const float* __restrict__ sb1,
                           const float* __restrict__ sw2, const float* __restrict__ sb2,
                           const float* __restrict__ pw1, const float* __restrict__ pb1,
                           const float* __restrict__ pw2, const float* __restrict__ pb2,
                           float* __restrict__ out)
{
    const int b = blockIdx.x / NRR;
    const int r = blockIdx.x % NRR;
    const int tid = threadIdx.x;
    __shared__ float roi_s[32], h_s[64], sf_s[32], h2_s[256];

    if (tid < 32)
        roi_s[tid] = g_roi[(b*NRR + r)*CH + tid] / g_msum[r];
    __syncthreads();
    if (tid < 64) {
        float s = sb1[r*64 + tid];
        #pragma unroll
        for (int c = 0; c < 32; c++)
            s = fmaf(roi_s[c], sw1[(r*CH + c)*64 + tid], s);
        h_s[tid] = fmaxf(s, 0.f);
    }
    __syncthreads();
    if (tid < 32) {
        float s = sb2[r*CH + tid];
        #pragma unroll
        for (int j = 0; j < 64; j++)
            s = fmaf(h_s[j], sw2[(r*64 + j)*CH + tid], s);
        sf_s[tid] = roi_s[tid] / (1.f + expf(-s));
    }
    __syncthreads();
    {
        float s = pb1[r*RHN + tid];
        #pragma unroll
        for (int c = 0; c < 32; c++)
            s = fmaf(sf_s[c], pw1[(r*CH + c)*RHN + tid], s);
        h2_s[tid] = fmaxf(s, 0.f);
    }
    __syncthreads();
    if (tid < 128) {
        float s = pb2[r*REN + tid];
        for (int k = 0; k < 256; k++)
            s = fmaf(h2_s[k], pw2[(r*RHN + k)*REN + tid], s);
        out[(b*NRR + r)*REN + tid] = s;
    }
}

// ---------------- launch ----------------
extern "C" void kernel_launch(void* const* d_in, const int* in_sizes, int n_in,
                              void* d_out, int out_size)
{
    const float* data    = (const float*)d_in[0];
    const float* mask    = (const float*)d_in[1];
    const float* conv0_w = (const float*)d_in[2];
    const float* convk_w = (const float*)d_in[4];
    const float* sw1 = (const float*)d_in[6];
    const float* sb1 = (const float*)d_in[7];
    const float* sw2 = (const float*)d_in[8];
    const float* sb2 = (const float*)d_in[9];
    const float* pw1 = (const float*)d_in[10];
    const float* pb1 = (const float*)d_in[11];
    const float* pw2 = (const float*)d_in[12];
    const float* pb2 = (const float*)d_in[13];
    float* out = (float*)d_out;

    __half* raw = nullptr; cudaGetSymbolAddress((void**)&raw, g_raw);
    __half* pad = nullptr; cudaGetSymbolAddress((void**)&pad, g_pad);
    __half* wpre = nullptr; cudaGetSymbolAddress((void**)&wpre, g_wprep);
    float* ssum = nullptr; cudaGetSymbolAddress((void**)&ssum, g_ssum);
    float* ss0 = ssum + 0*BATCH*CH*2;
    float* ss1 = ssum + 1*BATCH*CH*2;
    float* ss2 = ssum + 2*BATCH*CH*2;
    float* ss3 = ssum + 3*BATCH*CH*2;

    const int SMEMB = 18*BTILE*2;
    cudaFuncSetAttribute(conv_mma_kernel, cudaFuncAttributeMaxDynamicSharedMemorySize, SMEMB);

    const int nnb = BATCH*VOL/256;
    const size_t LW = (size_t)9*2*BTILE;

    init_kernel<<<1, 256>>>();
    wprep_kernel<<<27, 256>>>(convk_w);

    conv0_kernel<<<nnb, 256>>>(data, conv0_w, raw);
    stats0_kernel<<<dim3(432, 2), 256>>>(raw, ss0);
    norm_split_kernel<<<nnb, 256>>>(raw, ss0, pad);

    conv_mma_kernel<<<148, 768, SMEMB>>>(pad, wpre + 0*LW, raw, ss1);
    norm_split_kernel<<<nnb, 256>>>(raw, ss1, pad);

    conv_mma_kernel<<<148, 768, SMEMB>>>(pad, wpre + 1*LW, raw, ss2);
    norm_split_kernel<<<nnb, 256>>>(raw, ss2, pad);

    conv_mma_kernel<<<148, 768, SMEMB>>>(pad, wpre + 2*LW, raw, ss3);
    norm_split_kernel<<<nnb, 256>>>(raw, ss3, pad);

    pool_kernel<<<296, 256>>>(pad, mask);
    mlp_kernel<<<BATCH*NRR, 256>>>(sw1, sb1, sw2, sb2, pw1, pb1, pw2, pb2, out);
}